// round 1
// baseline (speedup 1.0000x reference)
#include <cuda_runtime.h>
#include <math.h>

#define BATCH 4
#define SEQ   1024
#define DM    1024
#define NH    16
#define HD    64
#define BH    (BATCH*NH)   // 64
#define NREL  33
#define NEGV  (-1e6f)

// ---------------- scratch (device globals: allocation is forbidden) ----------
__device__ float g_Q[BH*SEQ*HD];                 // 16 MB  [bh][s][d]
__device__ float g_K[BH*SEQ*HD];                 // 16 MB
__device__ float g_V[BH*SEQ*HD];                 // 16 MB
__device__ float g_qek[BH*SEQ*NREL];             // 8.6 MB [bh][s][r]
__device__ float g_pe [BH*SEQ*NREL];             // 8.6 MB [bh][s][r]
__device__ float g_ctx[BATCH*SEQ*DM];            // 16 MB  merged-head context
__device__ float g_scores[(size_t)BH*SEQ*SEQ];   // 256 MB [bh][q][k] (scores, then attn)

// ---------------- generic NT GEMM: C = A * B^T, A[M,K] rm, B[N,K] rm ---------
// BM=BN=128, BK=16, 256 threads, 8x8 per thread.
template<bool SPLIT_HEADS>
__global__ void __launch_bounds__(256) gemm_nt_kernel(
    const float* __restrict__ A, const float* __restrict__ B, float* __restrict__ C,
    int M, int N, int K, long sA, long sB, long sC)
{
    const int BM = 128, BN = 128, BK = 16;
    __shared__ float As[BK][BM];
    __shared__ float Bs[BK][BN];

    int z = blockIdx.z;
    A += (long)z * sA;  B += (long)z * sB;  C += (long)z * sC;

    int m0 = blockIdx.y * BM, n0 = blockIdx.x * BN;
    int tid = threadIdx.x;
    int tx = tid & 15, ty = tid >> 4;

    float acc[8][8];
    #pragma unroll
    for (int i = 0; i < 8; i++)
        #pragma unroll
        for (int j = 0; j < 8; j++) acc[i][j] = 0.f;

    for (int k0 = 0; k0 < K; k0 += BK) {
        #pragma unroll
        for (int it = 0; it < 2; it++) {            // A tile: 512 float4
            int lin = tid + it * 256;
            int row = lin >> 2;
            int kq  = (lin & 3) << 2;
            float4 v = *reinterpret_cast<const float4*>(&A[(size_t)(m0 + row) * K + k0 + kq]);
            As[kq + 0][row] = v.x; As[kq + 1][row] = v.y;
            As[kq + 2][row] = v.z; As[kq + 3][row] = v.w;
        }
        #pragma unroll
        for (int it = 0; it < 2; it++) {            // B tile
            int lin = tid + it * 256;
            int row = lin >> 2;
            int kq  = (lin & 3) << 2;
            float4 v = *reinterpret_cast<const float4*>(&B[(size_t)(n0 + row) * K + k0 + kq]);
            Bs[kq + 0][row] = v.x; Bs[kq + 1][row] = v.y;
            Bs[kq + 2][row] = v.z; Bs[kq + 3][row] = v.w;
        }
        __syncthreads();
        #pragma unroll
        for (int kk = 0; kk < BK; kk++) {
            float a[8], b[8];
            *reinterpret_cast<float4*>(a)     = *reinterpret_cast<float4*>(&As[kk][ty * 8]);
            *reinterpret_cast<float4*>(a + 4) = *reinterpret_cast<float4*>(&As[kk][ty * 8 + 4]);
            *reinterpret_cast<float4*>(b)     = *reinterpret_cast<float4*>(&Bs[kk][tx * 8]);
            *reinterpret_cast<float4*>(b + 4) = *reinterpret_cast<float4*>(&Bs[kk][tx * 8 + 4]);
            #pragma unroll
            for (int i = 0; i < 8; i++)
                #pragma unroll
                for (int j = 0; j < 8; j++) acc[i][j] += a[i] * b[j];
        }
        __syncthreads();
    }

    #pragma unroll
    for (int i = 0; i < 8; i++) {
        int m = m0 + ty * 8 + i;
        #pragma unroll
        for (int j = 0; j < 8; j++) {
            int n = n0 + tx * 8 + j;
            if (SPLIT_HEADS) {
                // m = b*SEQ+s over flattened [B,S]; n = h*HD+d → [bh][s][d]
                int b = m >> 10, s = m & 1023, h = n >> 6, d = n & 63;
                C[(size_t)((b * NH + h) * SEQ + s) * HD + d] = acc[i][j];
            } else {
                C[(size_t)m * N + n] = acc[i][j];
            }
        }
    }
}

// ---------------- O = P(attn) * V, NN GEMM, per-head, merged-head epilogue ---
// BM=128, BN=64, BK=16, 256 threads, 8x4 per thread.
__global__ void __launch_bounds__(256) attn_v_kernel(
    const float* __restrict__ P, const float* __restrict__ V, float* __restrict__ C)
{
    const int BM = 128, BK = 16;
    __shared__ float As[BK][BM];
    __shared__ float Bs[BK][HD];

    int bh = blockIdx.z;
    const float* A  = P + (size_t)bh * SEQ * SEQ;
    const float* Bp = V + (size_t)bh * SEQ * HD;

    int m0 = blockIdx.y * BM;
    int tid = threadIdx.x;
    int tx = tid & 15, ty = tid >> 4;

    float acc[8][4];
    #pragma unroll
    for (int i = 0; i < 8; i++)
        #pragma unroll
        for (int j = 0; j < 4; j++) acc[i][j] = 0.f;

    for (int k0 = 0; k0 < SEQ; k0 += BK) {
        #pragma unroll
        for (int it = 0; it < 2; it++) {
            int lin = tid + it * 256;
            int row = lin >> 2;
            int kq  = (lin & 3) << 2;
            float4 v = *reinterpret_cast<const float4*>(&A[(size_t)(m0 + row) * SEQ + k0 + kq]);
            As[kq + 0][row] = v.x; As[kq + 1][row] = v.y;
            As[kq + 2][row] = v.z; As[kq + 3][row] = v.w;
        }
        {   // B tile: 16x64 = 256 float4, one per thread, no transpose needed
            int row = tid >> 4;
            int c4  = (tid & 15) << 2;
            float4 v = *reinterpret_cast<const float4*>(&Bp[(size_t)(k0 + row) * HD + c4]);
            *reinterpret_cast<float4*>(&Bs[row][c4]) = v;
        }
        __syncthreads();
        #pragma unroll
        for (int kk = 0; kk < BK; kk++) {
            float a[8], b[4];
            *reinterpret_cast<float4*>(a)     = *reinterpret_cast<float4*>(&As[kk][ty * 8]);
            *reinterpret_cast<float4*>(a + 4) = *reinterpret_cast<float4*>(&As[kk][ty * 8 + 4]);
            *reinterpret_cast<float4*>(b)     = *reinterpret_cast<float4*>(&Bs[kk][tx * 4]);
            #pragma unroll
            for (int i = 0; i < 8; i++)
                #pragma unroll
                for (int j = 0; j < 4; j++) acc[i][j] += a[i] * b[j];
        }
        __syncthreads();
    }

    int b = bh >> 4, h = bh & 15;
    #pragma unroll
    for (int i = 0; i < 8; i++) {
        int s = m0 + ty * 8 + i;
        #pragma unroll
        for (int j = 0; j < 4; j++) {
            int d = tx * 4 + j;
            C[(size_t)(b * SEQ + s) * DM + h * HD + d] = acc[i][j];
        }
    }
}

// ---------------- qek[bh,s,r] = sum_d Q[bh,s,d]*Ek[r,d] ----------------------
__global__ void qek_kernel(const float* __restrict__ Ek)
{
    int idx = blockIdx.x * blockDim.x + threadIdx.x;
    if (idx >= BH * SEQ * NREL) return;
    int r   = idx % NREL;
    int row = idx / NREL;
    const float4* q = reinterpret_cast<const float4*>(g_Q + (size_t)row * HD);
    const float4* e = reinterpret_cast<const float4*>(Ek + r * HD);
    float acc = 0.f;
    #pragma unroll
    for (int d4 = 0; d4 < HD / 4; d4++) {
        float4 a = q[d4], b = e[d4];
        acc += a.x * b.x + a.y * b.y + a.z * b.z + a.w * b.w;
    }
    g_qek[idx] = acc;
}

// ---------------- softmax row kernel: mask + rel-k add + softmax + pe --------
// One block (256 thr) per (bh, q). pe: middles are single elements,
// ends are masked row-sums -> no atomics needed.
__global__ void __launch_bounds__(256) softmax_kernel(const int* __restrict__ valid_lens)
{
    int q  = blockIdx.x;
    int bh = blockIdx.y;
    int vl = valid_lens[bh >> 4];

    float* row = g_scores + ((size_t)bh * SEQ + q) * SEQ;
    const float* qek = g_qek + ((size_t)bh * SEQ + q) * NREL;
    size_t peb = ((size_t)bh * SEQ + q) * NREL;

    __shared__ float sqek[NREL];
    __shared__ float red[256];

    int tid = threadIdx.x;
    if (tid < NREL) sqek[tid] = qek[tid];
    __syncthreads();

    float v[4];
    float mx = -3.4e38f;
    #pragma unroll
    for (int i = 0; i < 4; i++) {
        int k = tid + i * 256;
        int dist = k - q;
        dist = min(16, max(-16, dist));
        float s = (row[k] + sqek[dist + 16]) * 0.125f;  // 1/sqrt(64)
        if (k >= vl) s = NEGV;
        v[i] = s;
        mx = fmaxf(mx, s);
    }
    red[tid] = mx; __syncthreads();
    for (int off = 128; off > 0; off >>= 1) {
        if (tid < off) red[tid] = fmaxf(red[tid], red[tid + off]);
        __syncthreads();
    }
    mx = red[0]; __syncthreads();

    float sum = 0.f;
    #pragma unroll
    for (int i = 0; i < 4; i++) { v[i] = __expf(v[i] - mx); sum += v[i]; }
    red[tid] = sum; __syncthreads();
    for (int off = 128; off > 0; off >>= 1) {
        if (tid < off) red[tid] += red[tid + off];
        __syncthreads();
    }
    float inv = 1.f / red[0]; __syncthreads();

    float sLow = 0.f, sHigh = 0.f;
    #pragma unroll
    for (int i = 0; i < 4; i++) {
        int k = tid + i * 256;
        float p = v[i] * inv;
        row[k] = p;
        if (k <= q - 16) sLow  += p;   // bucket 0
        if (k >= q + 16) sHigh += p;   // bucket 32
    }
    __syncthreads();                    // row[] fully written

    red[tid] = sLow; __syncthreads();
    for (int off = 128; off > 0; off >>= 1) {
        if (tid < off) red[tid] += red[tid + off];
        __syncthreads();
    }
    if (tid == 0) g_pe[peb + 0] = red[0];
    __syncthreads();
    red[tid] = sHigh; __syncthreads();
    for (int off = 128; off > 0; off >>= 1) {
        if (tid < off) red[tid] += red[tid + off];
        __syncthreads();
    }
    if (tid == 0) g_pe[peb + 32] = red[0];

    if (tid >= 1 && tid < 32) {         // middle buckets: single attn element
        int k2 = q + tid - 16;
        g_pe[peb + tid] = (k2 >= 0 && k2 < SEQ) ? row[k2] : 0.f;
    }
}

// ---------------- ctx += pe @ Ev (relative-position value term) --------------
__global__ void relv_kernel(const float* __restrict__ Ev)
{
    int idx = blockIdx.x * blockDim.x + threadIdx.x;
    if (idx >= BH * SEQ * HD) return;
    int d     = idx & 63;
    int rowid = idx >> 6;               // bh*SEQ + s
    int bh    = rowid >> 10;
    int s     = rowid & 1023;
    const float* pe = g_pe + (size_t)rowid * NREL;
    float acc = 0.f;
    #pragma unroll
    for (int r = 0; r < NREL; r++) acc += pe[r] * Ev[r * HD + d];
    int b = bh >> 4, h = bh & 15;
    g_ctx[(size_t)(b * SEQ + s) * DM + h * HD + d] += acc;
}

// ---------------- launch ------------------------------------------------------
extern "C" void kernel_launch(void* const* d_in, const int* in_sizes, int n_in,
                              void* d_out, int out_size)
{
    const float* queries = (const float*)d_in[0];
    const float* keys    = (const float*)d_in[1];
    const float* values  = (const float*)d_in[2];
    const int*   valid   = (const int*)  d_in[3];
    const float* Wq      = (const float*)d_in[4];
    const float* Wk      = (const float*)d_in[5];
    const float* Wv      = (const float*)d_in[6];
    const float* Wo      = (const float*)d_in[7];
    const float* Ek      = (const float*)d_in[8];
    const float* Ev      = (const float*)d_in[9];
    float* out = (float*)d_out;

    float *Qp, *Kp, *Vp, *Sp, *Cp;
    cudaGetSymbolAddress((void**)&Qp, g_Q);
    cudaGetSymbolAddress((void**)&Kp, g_K);
    cudaGetSymbolAddress((void**)&Vp, g_V);
    cudaGetSymbolAddress((void**)&Sp, g_scores);
    cudaGetSymbolAddress((void**)&Cp, g_ctx);

    const int M = BATCH * SEQ;  // 4096

    // 1) projections, head-split output
    dim3 gproj(DM / 128, M / 128, 1);
    gemm_nt_kernel<true><<<gproj, 256>>>(queries, Wq, Qp, M, DM, DM, 0, 0, 0);
    gemm_nt_kernel<true><<<gproj, 256>>>(keys,    Wk, Kp, M, DM, DM, 0, 0, 0);
    gemm_nt_kernel<true><<<gproj, 256>>>(values,  Wv, Vp, M, DM, DM, 0, 0, 0);

    // 2) qek table
    qek_kernel<<<(BH * SEQ * NREL + 255) / 256, 256>>>(Ek);

    // 3) raw scores = Q K^T per head
    dim3 gsc(SEQ / 128, SEQ / 128, BH);
    gemm_nt_kernel<false><<<gsc, 256>>>(Qp, Kp, Sp, SEQ, SEQ, HD,
                                        (long)SEQ * HD, (long)SEQ * HD, (long)SEQ * SEQ);

    // 4) mask + rel-k + softmax + pe buckets (in-place on scores)
    softmax_kernel<<<dim3(SEQ, BH), 256>>>(valid);

    // 5) ctx = attn @ V (merged-head layout)
    attn_v_kernel<<<dim3(1, SEQ / 128, BH), 256>>>(Sp, Vp, Cp);

    // 6) ctx += pe @ Ev
    relv_kernel<<<(BH * SEQ * HD + 255) / 256, 256>>>(Ev);

    // 7) out = ctx @ Wo^T
    gemm_nt_kernel<false><<<dim3(DM / 128, M / 128, 1), 256>>>(Cp, Wo, out, M, DM, DM, 0, 0, 0);
}

// round 2
// speedup vs baseline: 2.5831x; 2.5831x over previous
#include <cuda_runtime.h>
#include <math.h>
#include <stdint.h>

#define BATCH 4
#define SEQ   1024
#define DM    1024
#define NH    16
#define HD    64
#define BH    (BATCH*NH)   // 64
#define NREL  33
#define NEGV  (-1e6f)

// ---------------- scratch (device globals: allocation is forbidden) ----------
__device__ float g_Q[BH*SEQ*HD];                 // [bh][s][d]
__device__ float g_K[BH*SEQ*HD];
__device__ float g_V[BH*SEQ*HD];
__device__ float g_qek[BH*SEQ*NREL];             // [bh][s][r]
__device__ float g_pe [BH*SEQ*NREL];
__device__ float g_ctx[BATCH*SEQ*DM];            // merged-head context
__device__ float g_scores[(size_t)BH*SEQ*SEQ];   // [bh][q][k]

// ---------------- tf32 helpers ----------------------------------------------
__device__ __forceinline__ uint32_t f2tf(float f) {
    uint32_t u;
    asm("cvt.rna.tf32.f32 %0, %1;" : "=r"(u) : "f"(f));
    return u;
}

__device__ __forceinline__ void mma8(float* c,
    uint32_t a0, uint32_t a1, uint32_t a2, uint32_t a3,
    uint32_t b0, uint32_t b1)
{
    asm volatile(
        "mma.sync.aligned.m16n8k8.row.col.f32.tf32.tf32.f32 "
        "{%0,%1,%2,%3}, {%4,%5,%6,%7}, {%8,%9}, {%0,%1,%2,%3};"
        : "+f"(c[0]), "+f"(c[1]), "+f"(c[2]), "+f"(c[3])
        : "r"(a0), "r"(a1), "r"(a2), "r"(a3), "r"(b0), "r"(b1));
}

// ---------------- tensor-core GEMM -------------------------------------------
// C = A * B^T (B_NT=true, B is [N,K] row-major) or C = A * B (B_NT=false,
// B is [K,N] row-major). A is [M,K] row-major. tf32 inputs, fp32 accumulate.
// Block tile BM x BN, BK=32. Warp tile 64x32 (4x4 m16n8k8 mmas per k-chunk).
// OUT: 0 = plain C[m*N+n]; 1 = split-heads projection epilogue;
//      2 = merged-head attention-output epilogue (z = bh).
template<int BM, int BN, bool B_NT, int OUT>
__global__ void __launch_bounds__((BM/64)*(BN/32)*32)
gemm_mma(const float* __restrict__ A, const float* __restrict__ B,
         float* __restrict__ C, int M, int N, int K,
         long sA, long sB, long sC)
{
    constexpr int BK  = 32;
    constexpr int NWM = BM / 64;      // warps along M
    constexpr int NWN = BN / 32;      // warps along N
    constexpr int T   = NWM * NWN * 32;

    // A tile: [m][k] untransposed, stride 36 (bank offset 4/row) ->
    // conflict-free uint4 stores AND conflict-free fragment reads.
    __shared__ uint32_t As[BM][BK + 4];
    constexpr int BR = B_NT ? BN : BK;
    constexpr int BC = B_NT ? (BK + 4) : (BN + 4);
    __shared__ uint32_t Bs[BR][BC];

    int z = blockIdx.z;
    A += (long)z * sA;  B += (long)z * sB;  C += (long)z * sC;

    int m0  = blockIdx.y * BM, n0 = blockIdx.x * BN;
    int tid = threadIdx.x;
    int lane = tid & 31, warp = tid >> 5;
    int gid = lane >> 2, tig = lane & 3;
    int wm0 = (warp / NWN) * 64;
    int wn0 = (warp % NWN) * 32;

    float acc[4][4][4];
    #pragma unroll
    for (int i = 0; i < 4; i++)
        #pragma unroll
        for (int j = 0; j < 4; j++)
            #pragma unroll
            for (int l = 0; l < 4; l++) acc[i][j][l] = 0.f;

    for (int k0 = 0; k0 < K; k0 += BK) {
        // --- A tile: BM x 32, coalesced float4 rows, stored [m][k]
        #pragma unroll
        for (int it = 0; it < BM * BK / 4 / T; it++) {
            int idx = tid + it * T;
            int row = idx >> 3, kq = (idx & 7) << 2;
            float4 v = *reinterpret_cast<const float4*>(
                &A[(size_t)(m0 + row) * K + k0 + kq]);
            uint4 u = make_uint4(f2tf(v.x), f2tf(v.y), f2tf(v.z), f2tf(v.w));
            *reinterpret_cast<uint4*>(&As[row][kq]) = u;
        }
        // --- B tile
        if (B_NT) {
            #pragma unroll
            for (int it = 0; it < BN * BK / 4 / T; it++) {
                int idx = tid + it * T;
                int row = idx >> 3, kq = (idx & 7) << 2;
                float4 v = *reinterpret_cast<const float4*>(
                    &B[(size_t)(n0 + row) * K + k0 + kq]);
                uint4 u = make_uint4(f2tf(v.x), f2tf(v.y), f2tf(v.z), f2tf(v.w));
                *reinterpret_cast<uint4*>(&Bs[row][kq]) = u;
            }
        } else {
            #pragma unroll
            for (int it = 0; it < BK * BN / 4 / T; it++) {
                int idx = tid + it * T;
                int row = idx / (BN / 4), nq = (idx % (BN / 4)) << 2;
                float4 v = *reinterpret_cast<const float4*>(
                    &B[(size_t)(k0 + row) * N + n0 + nq]);
                uint4 u = make_uint4(f2tf(v.x), f2tf(v.y), f2tf(v.z), f2tf(v.w));
                *reinterpret_cast<uint4*>(&Bs[row][nq]) = u;
            }
        }
        __syncthreads();

        #pragma unroll
        for (int kc = 0; kc < BK / 8; kc++) {
            int kb = kc * 8;
            uint32_t af[4][4];
            #pragma unroll
            for (int mt = 0; mt < 4; mt++) {
                int r = wm0 + mt * 16 + gid;
                af[mt][0] = As[r    ][kb + tig];
                af[mt][1] = As[r + 8][kb + tig];
                af[mt][2] = As[r    ][kb + tig + 4];
                af[mt][3] = As[r + 8][kb + tig + 4];
            }
            uint32_t bf[4][2];
            #pragma unroll
            for (int nt = 0; nt < 4; nt++) {
                int cn = wn0 + nt * 8 + gid;
                if (B_NT) {
                    bf[nt][0] = Bs[cn][kb + tig];
                    bf[nt][1] = Bs[cn][kb + tig + 4];
                } else {
                    bf[nt][0] = Bs[kb + tig    ][cn];
                    bf[nt][1] = Bs[kb + tig + 4][cn];
                }
            }
            #pragma unroll
            for (int mt = 0; mt < 4; mt++)
                #pragma unroll
                for (int nt = 0; nt < 4; nt++)
                    mma8(acc[mt][nt], af[mt][0], af[mt][1], af[mt][2], af[mt][3],
                         bf[nt][0], bf[nt][1]);
        }
        __syncthreads();
    }

    // --- epilogue: per-mma frag c0,c1 at (row, 2tig..2tig+1), c2,c3 at row+8
    #pragma unroll
    for (int mt = 0; mt < 4; mt++) {
        #pragma unroll
        for (int nt = 0; nt < 4; nt++) {
            int r0 = m0 + wm0 + mt * 16 + gid;
            int c0 = n0 + wn0 + nt * 8 + 2 * tig;
            float2 t0 = make_float2(acc[mt][nt][0], acc[mt][nt][1]);
            float2 t1 = make_float2(acc[mt][nt][2], acc[mt][nt][3]);
            if (OUT == 0) {
                *reinterpret_cast<float2*>(&C[(size_t)r0 * N + c0]) = t0;
                *reinterpret_cast<float2*>(&C[(size_t)(r0 + 8) * N + c0]) = t1;
            } else if (OUT == 1) {
                int b = r0 >> 10, s = r0 & 1023, h = c0 >> 6, d = c0 & 63;
                *reinterpret_cast<float2*>(
                    &C[(size_t)((b * NH + h) * SEQ + s) * HD + d]) = t0;
                int b2 = (r0 + 8) >> 10, s2 = (r0 + 8) & 1023;
                *reinterpret_cast<float2*>(
                    &C[(size_t)((b2 * NH + h) * SEQ + s2) * HD + d]) = t1;
            } else {  // OUT == 2: z = bh, m = s, n = d
                int b = z >> 4, h = z & 15;
                *reinterpret_cast<float2*>(
                    &C[(size_t)(b * SEQ + r0) * DM + h * HD + c0]) = t0;
                *reinterpret_cast<float2*>(
                    &C[(size_t)(b * SEQ + r0 + 8) * DM + h * HD + c0]) = t1;
            }
        }
    }
}

// ---------------- qek[bh,s,r] = sum_d Q[bh,s,d]*Ek[r,d] ----------------------
// One thread per row s; Ek resident in smem; 33 accumulators in registers.
__global__ void __launch_bounds__(256) qek_kernel(const float* __restrict__ Ek)
{
    __shared__ float4 sEk[NREL][HD / 4];
    int tid = threadIdx.x;
    for (int i = tid; i < NREL * HD / 4; i += 256)
        sEk[i / (HD / 4)][i % (HD / 4)] =
            reinterpret_cast<const float4*>(Ek)[i];
    __syncthreads();

    int row = blockIdx.x * 256 + tid;   // bh*SEQ + s
    const float4* q = reinterpret_cast<const float4*>(g_Q + (size_t)row * HD);
    float acc[NREL];
    #pragma unroll
    for (int r = 0; r < NREL; r++) acc[r] = 0.f;
    #pragma unroll 4
    for (int d4 = 0; d4 < HD / 4; d4++) {
        float4 a = q[d4];
        #pragma unroll
        for (int r = 0; r < NREL; r++) {
            float4 e = sEk[r][d4];   // broadcast
            acc[r] += a.x * e.x + a.y * e.y + a.z * e.z + a.w * e.w;
        }
    }
    float* o = g_qek + (size_t)row * NREL;
    #pragma unroll
    for (int r = 0; r < NREL; r++) o[r] = acc[r];
}

// ---------------- softmax row kernel: mask + rel-k add + softmax + pe --------
__global__ void __launch_bounds__(256) softmax_kernel(const int* __restrict__ valid_lens)
{
    int q  = blockIdx.x;
    int bh = blockIdx.y;
    int vl = valid_lens[bh >> 4];

    float* row = g_scores + ((size_t)bh * SEQ + q) * SEQ;
    const float* qek = g_qek + ((size_t)bh * SEQ + q) * NREL;
    size_t peb = ((size_t)bh * SEQ + q) * NREL;

    __shared__ float sqek[NREL];
    __shared__ float red[256];

    int tid = threadIdx.x;
    if (tid < NREL) sqek[tid] = qek[tid];
    __syncthreads();

    float v[4];
    float mx = -3.4e38f;
    #pragma unroll
    for (int i = 0; i < 4; i++) {
        int k = tid + i * 256;
        int dist = k - q;
        dist = min(16, max(-16, dist));
        float s = (row[k] + sqek[dist + 16]) * 0.125f;  // 1/sqrt(64)
        if (k >= vl) s = NEGV;
        v[i] = s;
        mx = fmaxf(mx, s);
    }
    red[tid] = mx; __syncthreads();
    for (int off = 128; off > 0; off >>= 1) {
        if (tid < off) red[tid] = fmaxf(red[tid], red[tid + off]);
        __syncthreads();
    }
    mx = red[0]; __syncthreads();

    float sum = 0.f;
    #pragma unroll
    for (int i = 0; i < 4; i++) { v[i] = __expf(v[i] - mx); sum += v[i]; }
    red[tid] = sum; __syncthreads();
    for (int off = 128; off > 0; off >>= 1) {
        if (tid < off) red[tid] += red[tid + off];
        __syncthreads();
    }
    float inv = 1.f / red[0]; __syncthreads();

    float sLow = 0.f, sHigh = 0.f;
    #pragma unroll
    for (int i = 0; i < 4; i++) {
        int k = tid + i * 256;
        float p = v[i] * inv;
        row[k] = p;
        if (k <= q - 16) sLow  += p;   // bucket 0
        if (k >= q + 16) sHigh += p;   // bucket 32
    }
    __syncthreads();

    red[tid] = sLow; __syncthreads();
    for (int off = 128; off > 0; off >>= 1) {
        if (tid < off) red[tid] += red[tid + off];
        __syncthreads();
    }
    if (tid == 0) g_pe[peb + 0] = red[0];
    __syncthreads();
    red[tid] = sHigh; __syncthreads();
    for (int off = 128; off > 0; off >>= 1) {
        if (tid < off) red[tid] += red[tid + off];
        __syncthreads();
    }
    if (tid == 0) g_pe[peb + 32] = red[0];

    if (tid >= 1 && tid < 32) {
        int k2 = q + tid - 16;
        g_pe[peb + tid] = (k2 >= 0 && k2 < SEQ) ? row[k2] : 0.f;
    }
}

// ---------------- ctx += pe @ Ev ---------------------------------------------
__global__ void relv_kernel(const float* __restrict__ Ev)
{
    int idx = blockIdx.x * blockDim.x + threadIdx.x;
    if (idx >= BH * SEQ * HD) return;
    int d     = idx & 63;
    int rowid = idx >> 6;
    int bh    = rowid >> 10;
    int s     = rowid & 1023;
    const float* pe = g_pe + (size_t)rowid * NREL;
    float acc = 0.f;
    #pragma unroll
    for (int r = 0; r < NREL; r++) acc += pe[r] * Ev[r * HD + d];
    int b = bh >> 4, h = bh & 15;
    g_ctx[(size_t)(b * SEQ + s) * DM + h * HD + d] += acc;
}

// ---------------- launch ------------------------------------------------------
extern "C" void kernel_launch(void* const* d_in, const int* in_sizes, int n_in,
                              void* d_out, int out_size)
{
    const float* queries = (const float*)d_in[0];
    const float* keys    = (const float*)d_in[1];
    const float* values  = (const float*)d_in[2];
    const int*   valid   = (const int*)  d_in[3];
    const float* Wq      = (const float*)d_in[4];
    const float* Wk      = (const float*)d_in[5];
    const float* Wv      = (const float*)d_in[6];
    const float* Wo      = (const float*)d_in[7];
    const float* Ek      = (const float*)d_in[8];
    const float* Ev      = (const float*)d_in[9];
    float* out = (float*)d_out;

    float *Qp, *Kp, *Vp, *Sp, *Cp;
    cudaGetSymbolAddress((void**)&Qp, g_Q);
    cudaGetSymbolAddress((void**)&Kp, g_K);
    cudaGetSymbolAddress((void**)&Vp, g_V);
    cudaGetSymbolAddress((void**)&Sp, g_scores);
    cudaGetSymbolAddress((void**)&Cp, g_ctx);

    const int M = BATCH * SEQ;  // 4096

    // 1) projections (tf32 mma), head-split epilogue
    dim3 gproj(DM / 128, M / 128, 1);
    gemm_mma<128, 128, true, 1><<<gproj, 256>>>(queries, Wq, Qp, M, DM, DM, 0, 0, 0);
    gemm_mma<128, 128, true, 1><<<gproj, 256>>>(keys,    Wk, Kp, M, DM, DM, 0, 0, 0);
    gemm_mma<128, 128, true, 1><<<gproj, 256>>>(values,  Wv, Vp, M, DM, DM, 0, 0, 0);

    // 2) qek table (register-blocked, Ek in smem)
    qek_kernel<<<BH * SEQ / 256, 256>>>(Ek);

    // 3) raw scores = Q K^T per head (tf32 mma)
    gemm_mma<128, 128, true, 0><<<dim3(8, 8, BH), 256>>>(
        Qp, Kp, Sp, SEQ, SEQ, HD,
        (long)SEQ * HD, (long)SEQ * HD, (long)SEQ * SEQ);

    // 4) mask + rel-k + softmax + pe buckets
    softmax_kernel<<<dim3(SEQ, BH), 256>>>(valid);

    // 5) ctx = attn @ V (NN tf32 mma, merged-head epilogue)
    gemm_mma<128, 64, false, 2><<<dim3(1, 8, BH), 128>>>(
        Sp, Vp, Cp, SEQ, HD, SEQ,
        (long)SEQ * SEQ, (long)SEQ * HD, 0);

    // 6) ctx += pe @ Ev
    relv_kernel<<<(BH * SEQ * HD + 255) / 256, 256>>>(Ev);

    // 7) out = ctx @ Wo^T
    gemm_mma<128, 128, true, 0><<<dim3(DM / 128, M / 128, 1), 256>>>(
        Cp, Wo, out, M, DM, DM, 0, 0, 0);
}

// round 3
// speedup vs baseline: 2.6568x; 1.0286x over previous
#include <cuda_runtime.h>
#include <math.h>
#include <stdint.h>

#define BATCH 4
#define SEQ   1024
#define DM    1024
#define NH    16
#define HD    64
#define BH    (BATCH*NH)   // 64
#define NREL  33
#define NEGV  (-1e6f)

// ---------------- scratch (device globals: allocation is forbidden) ----------
__device__ float g_Q[BH*SEQ*HD];                 // [bh][s][d]
__device__ float g_K[BH*SEQ*HD];
__device__ float g_V[BH*SEQ*HD];
__device__ float g_qek[BH*SEQ*NREL];             // [bh][s][r]
__device__ float g_pe [BH*SEQ*NREL];
__device__ float g_ctx[BATCH*SEQ*DM];            // merged-head context
__device__ float g_scores[(size_t)BH*SEQ*SEQ];   // [bh][q][k]

// ---------------- helpers ----------------------------------------------------
__device__ __forceinline__ uint32_t f2tf(float f) {
    uint32_t u;
    asm("cvt.rna.tf32.f32 %0, %1;" : "=r"(u) : "f"(f));
    return u;
}

__device__ __forceinline__ void mma8(float* c,
    uint32_t a0, uint32_t a1, uint32_t a2, uint32_t a3,
    uint32_t b0, uint32_t b1)
{
    asm volatile(
        "mma.sync.aligned.m16n8k8.row.col.f32.tf32.tf32.f32 "
        "{%0,%1,%2,%3}, {%4,%5,%6,%7}, {%8,%9}, {%0,%1,%2,%3};"
        : "+f"(c[0]), "+f"(c[1]), "+f"(c[2]), "+f"(c[3])
        : "r"(a0), "r"(a1), "r"(a2), "r"(a3), "r"(b0), "r"(b1));
}

__device__ __forceinline__ void cp16(void* smem_dst, const void* gmem_src) {
    uint32_t s = (uint32_t)__cvta_generic_to_shared(smem_dst);
    asm volatile("cp.async.cg.shared.global [%0], [%1], 16;\n"
                 :: "r"(s), "l"(gmem_src));
}
__device__ __forceinline__ void cp_commit() {
    asm volatile("cp.async.commit_group;\n");
}
template<int N>
__device__ __forceinline__ void cp_wait() {
    asm volatile("cp.async.wait_group %0;\n" :: "n"(N));
}

// ---------------- pipelined tensor-core GEMM ---------------------------------
// C = A * B^T (B_NT) or A * B. A[M,K] rm. tf32 mma, fp32 accum.
// 2-stage cp.async double buffering. Warp tile 64x32 (4x4 m16n8k8).
// OUT: 0 plain, 1 split-heads projection epilogue, 2 merged-head (z=bh).
template<int BM, int BN, int NWM, int NWN, bool B_NT, int OUT>
__global__ void __launch_bounds__(NWM*NWN*32)
gemm_mma(const float* __restrict__ A, const float* __restrict__ B,
         float* __restrict__ C, int M, int N, int K,
         long sA, long sB, long sC)
{
    constexpr int BK = 32;
    constexpr int T  = NWM * NWN * 32;
    constexpr int BR = B_NT ? BN : BK;
    constexpr int BC = B_NT ? (BK + 4) : (BN + 4);
    constexpr int ASZ = BM * (BK + 4);
    constexpr int BSZ = BR * BC;

    extern __shared__ float dynsmem[];
    float (*As)[BM][BK + 4] = reinterpret_cast<float(*)[BM][BK + 4]>(dynsmem);
    float (*Bs)[BR][BC]     = reinterpret_cast<float(*)[BR][BC]>(dynsmem + 2 * ASZ);

    int z = blockIdx.z;
    A += (long)z * sA;  B += (long)z * sB;  C += (long)z * sC;

    int m0  = blockIdx.y * BM, n0 = blockIdx.x * BN;
    int tid = threadIdx.x;
    int lane = tid & 31, warp = tid >> 5;
    int gid = lane >> 2, tig = lane & 3;
    int wm0 = (warp / NWN) * 64;
    int wn0 = (warp % NWN) * 32;

    auto load_tiles = [&](int buf, int k0) {
        #pragma unroll
        for (int it = 0; it < BM * BK / 4 / T; it++) {
            int idx = tid + it * T;
            int row = idx >> 3, kq = (idx & 7) << 2;
            cp16(&As[buf][row][kq], &A[(size_t)(m0 + row) * K + k0 + kq]);
        }
        if (B_NT) {
            #pragma unroll
            for (int it = 0; it < BN * BK / 4 / T; it++) {
                int idx = tid + it * T;
                int row = idx >> 3, kq = (idx & 7) << 2;
                cp16(&Bs[buf][row][kq], &B[(size_t)(n0 + row) * K + k0 + kq]);
            }
        } else {
            #pragma unroll
            for (int it = 0; it < BK * BN / 4 / T; it++) {
                int idx = tid + it * T;
                int row = idx / (BN / 4), nq = (idx % (BN / 4)) << 2;
                cp16(&Bs[buf][row][nq], &B[(size_t)(k0 + row) * N + n0 + nq]);
            }
        }
        cp_commit();
    };

    float acc[4][4][4];
    #pragma unroll
    for (int i = 0; i < 4; i++)
        #pragma unroll
        for (int j = 0; j < 4; j++)
            #pragma unroll
            for (int l = 0; l < 4; l++) acc[i][j][l] = 0.f;

    const int KT = K / BK;
    load_tiles(0, 0);

    for (int kt = 0; kt < KT; kt++) {
        int buf = kt & 1;
        if (kt + 1 < KT) { load_tiles(buf ^ 1, (kt + 1) * BK); cp_wait<1>(); }
        else             { cp_wait<0>(); }
        __syncthreads();

        #pragma unroll
        for (int kc = 0; kc < BK / 8; kc++) {
            int kb = kc * 8;
            uint32_t af[4][4];
            #pragma unroll
            for (int mt = 0; mt < 4; mt++) {
                int r = wm0 + mt * 16 + gid;
                af[mt][0] = f2tf(As[buf][r    ][kb + tig]);
                af[mt][1] = f2tf(As[buf][r + 8][kb + tig]);
                af[mt][2] = f2tf(As[buf][r    ][kb + tig + 4]);
                af[mt][3] = f2tf(As[buf][r + 8][kb + tig + 4]);
            }
            uint32_t bf[4][2];
            #pragma unroll
            for (int nt = 0; nt < 4; nt++) {
                int cn = wn0 + nt * 8 + gid;
                if (B_NT) {
                    bf[nt][0] = f2tf(Bs[buf][cn][kb + tig]);
                    bf[nt][1] = f2tf(Bs[buf][cn][kb + tig + 4]);
                } else {
                    bf[nt][0] = f2tf(Bs[buf][kb + tig    ][cn]);
                    bf[nt][1] = f2tf(Bs[buf][kb + tig + 4][cn]);
                }
            }
            #pragma unroll
            for (int mt = 0; mt < 4; mt++)
                #pragma unroll
                for (int nt = 0; nt < 4; nt++)
                    mma8(acc[mt][nt], af[mt][0], af[mt][1], af[mt][2], af[mt][3],
                         bf[nt][0], bf[nt][1]);
        }
        __syncthreads();
    }

    #pragma unroll
    for (int mt = 0; mt < 4; mt++) {
        #pragma unroll
        for (int nt = 0; nt < 4; nt++) {
            int r0 = m0 + wm0 + mt * 16 + gid;
            int c0 = n0 + wn0 + nt * 8 + 2 * tig;
            float2 t0 = make_float2(acc[mt][nt][0], acc[mt][nt][1]);
            float2 t1 = make_float2(acc[mt][nt][2], acc[mt][nt][3]);
            if (OUT == 0) {
                *reinterpret_cast<float2*>(&C[(size_t)r0 * N + c0]) = t0;
                *reinterpret_cast<float2*>(&C[(size_t)(r0 + 8) * N + c0]) = t1;
            } else if (OUT == 1) {
                int b = r0 >> 10, s = r0 & 1023, h = c0 >> 6, d = c0 & 63;
                *reinterpret_cast<float2*>(
                    &C[(size_t)((b * NH + h) * SEQ + s) * HD + d]) = t0;
                int b2 = (r0 + 8) >> 10, s2 = (r0 + 8) & 1023;
                *reinterpret_cast<float2*>(
                    &C[(size_t)((b2 * NH + h) * SEQ + s2) * HD + d]) = t1;
            } else {  // OUT == 2: z = bh, m = s, n = d
                int b = z >> 4, h = z & 15;
                *reinterpret_cast<float2*>(
                    &C[(size_t)(b * SEQ + r0) * DM + h * HD + c0]) = t0;
                *reinterpret_cast<float2*>(
                    &C[(size_t)(b * SEQ + r0 + 8) * DM + h * HD + c0]) = t1;
            }
        }
    }
}

// ---------------- qek[bh,s,r] = sum_d Q[bh,s,d]*Ek[r,d] ----------------------
__global__ void __launch_bounds__(64) qek_kernel(const float* __restrict__ Ek)
{
    __shared__ float4 sEk[NREL][HD / 4];
    int tid = threadIdx.x;
    for (int i = tid; i < NREL * HD / 4; i += 64)
        sEk[i / (HD / 4)][i % (HD / 4)] =
            reinterpret_cast<const float4*>(Ek)[i];
    __syncthreads();

    int row = blockIdx.x * 64 + tid;   // bh*SEQ + s
    const float4* q = reinterpret_cast<const float4*>(g_Q + (size_t)row * HD);
    float acc[NREL];
    #pragma unroll
    for (int r = 0; r < NREL; r++) acc[r] = 0.f;
    #pragma unroll 4
    for (int d4 = 0; d4 < HD / 4; d4++) {
        float4 a = q[d4];
        #pragma unroll
        for (int r = 0; r < NREL; r++) {
            float4 e = sEk[r][d4];
            acc[r] += a.x * e.x + a.y * e.y + a.z * e.z + a.w * e.w;
        }
    }
    float* o = g_qek + (size_t)row * NREL;
    #pragma unroll
    for (int r = 0; r < NREL; r++) o[r] = acc[r];
}

// ---------------- softmax row kernel: mask + rel-k add + softmax + pe --------
__global__ void __launch_bounds__(256) softmax_kernel(const int* __restrict__ valid_lens)
{
    int q  = blockIdx.x;
    int bh = blockIdx.y;
    int vl = valid_lens[bh >> 4];

    float* row = g_scores + ((size_t)bh * SEQ + q) * SEQ;
    const float* qek = g_qek + ((size_t)bh * SEQ + q) * NREL;
    size_t peb = ((size_t)bh * SEQ + q) * NREL;

    __shared__ float sqek[NREL];
    __shared__ float red[256];

    int tid = threadIdx.x;
    if (tid < NREL) sqek[tid] = qek[tid];
    __syncthreads();

    float v[4];
    float mx = -3.4e38f;
    #pragma unroll
    for (int i = 0; i < 4; i++) {
        int k = tid + i * 256;
        int dist = k - q;
        dist = min(16, max(-16, dist));
        float s = (row[k] + sqek[dist + 16]) * 0.125f;
        if (k >= vl) s = NEGV;
        v[i] = s;
        mx = fmaxf(mx, s);
    }
    red[tid] = mx; __syncthreads();
    for (int off = 128; off > 0; off >>= 1) {
        if (tid < off) red[tid] = fmaxf(red[tid], red[tid + off]);
        __syncthreads();
    }
    mx = red[0]; __syncthreads();

    float sum = 0.f;
    #pragma unroll
    for (int i = 0; i < 4; i++) { v[i] = __expf(v[i] - mx); sum += v[i]; }
    red[tid] = sum; __syncthreads();
    for (int off = 128; off > 0; off >>= 1) {
        if (tid < off) red[tid] += red[tid + off];
        __syncthreads();
    }
    float inv = 1.f / red[0]; __syncthreads();

    float sLow = 0.f, sHigh = 0.f;
    #pragma unroll
    for (int i = 0; i < 4; i++) {
        int k = tid + i * 256;
        float p = v[i] * inv;
        row[k] = p;
        if (k <= q - 16) sLow  += p;
        if (k >= q + 16) sHigh += p;
    }
    __syncthreads();

    red[tid] = sLow; __syncthreads();
    for (int off = 128; off > 0; off >>= 1) {
        if (tid < off) red[tid] += red[tid + off];
        __syncthreads();
    }
    if (tid == 0) g_pe[peb + 0] = red[0];
    __syncthreads();
    red[tid] = sHigh; __syncthreads();
    for (int off = 128; off > 0; off >>= 1) {
        if (tid < off) red[tid] += red[tid + off];
        __syncthreads();
    }
    if (tid == 0) g_pe[peb + 32] = red[0];

    if (tid >= 1 && tid < 32) {
        int k2 = q + tid - 16;
        g_pe[peb + tid] = (k2 >= 0 && k2 < SEQ) ? row[k2] : 0.f;
    }
}

// ---------------- ctx += pe @ Ev ---------------------------------------------
__global__ void relv_kernel(const float* __restrict__ Ev)
{
    int idx = blockIdx.x * blockDim.x + threadIdx.x;
    if (idx >= BH * SEQ * HD) return;
    int d     = idx & 63;
    int rowid = idx >> 6;
    int bh    = rowid >> 10;
    int s     = rowid & 1023;
    const float* pe = g_pe + (size_t)rowid * NREL;
    float acc = 0.f;
    #pragma unroll
    for (int r = 0; r < NREL; r++) acc += pe[r] * Ev[r * HD + d];
    int b = bh >> 4, h = bh & 15;
    g_ctx[(size_t)(b * SEQ + s) * DM + h * HD + d] += acc;
}

// ---------------- launch ------------------------------------------------------
extern "C" void kernel_launch(void* const* d_in, const int* in_sizes, int n_in,
                              void* d_out, int out_size)
{
    const float* queries = (const float*)d_in[0];
    const float* keys    = (const float*)d_in[1];
    const float* values  = (const float*)d_in[2];
    const int*   valid   = (const int*)  d_in[3];
    const float* Wq      = (const float*)d_in[4];
    const float* Wk      = (const float*)d_in[5];
    const float* Wv      = (const float*)d_in[6];
    const float* Wo      = (const float*)d_in[7];
    const float* Ek      = (const float*)d_in[8];
    const float* Ev      = (const float*)d_in[9];
    float* out = (float*)d_out;

    float *Qp, *Kp, *Vp, *Sp, *Cp;
    cudaGetSymbolAddress((void**)&Qp, g_Q);
    cudaGetSymbolAddress((void**)&Kp, g_K);
    cudaGetSymbolAddress((void**)&Vp, g_V);
    cudaGetSymbolAddress((void**)&Sp, g_scores);
    cudaGetSymbolAddress((void**)&Cp, g_ctx);

    const int M = BATCH * SEQ;  // 4096

    // dynamic smem sizes (double-buffered)
    const int smBig = 2 * (128 * 36 + 128 * 36) * sizeof(float);   // 73728
    const int smPV  = 2 * (128 * 36 + 32 * 68) * sizeof(float);    // 54272

    cudaFuncSetAttribute(gemm_mma<128,128,2,4,true,1>,
        cudaFuncAttributeMaxDynamicSharedMemorySize, smBig);
    cudaFuncSetAttribute(gemm_mma<128,128,2,4,true,0>,
        cudaFuncAttributeMaxDynamicSharedMemorySize, smBig);
    cudaFuncSetAttribute(gemm_mma<128,64,2,2,false,2>,
        cudaFuncAttributeMaxDynamicSharedMemorySize, smPV);

    // 1) projections (tf32 mma), head-split epilogue
    dim3 gproj(DM / 128, M / 128, 1);
    gemm_mma<128,128,2,4,true,1><<<gproj, 256, smBig>>>(queries, Wq, Qp, M, DM, DM, 0, 0, 0);
    gemm_mma<128,128,2,4,true,1><<<gproj, 256, smBig>>>(keys,    Wk, Kp, M, DM, DM, 0, 0, 0);
    gemm_mma<128,128,2,4,true,1><<<gproj, 256, smBig>>>(values,  Wv, Vp, M, DM, DM, 0, 0, 0);

    // 2) qek table
    qek_kernel<<<BH * SEQ / 64, 64>>>(Ek);

    // 3) raw scores = Q K^T per head
    gemm_mma<128,128,2,4,true,0><<<dim3(8, 8, BH), 256, smBig>>>(
        Qp, Kp, Sp, SEQ, SEQ, HD,
        (long)SEQ * HD, (long)SEQ * HD, (long)SEQ * SEQ);

    // 4) mask + rel-k + softmax + pe buckets
    softmax_kernel<<<dim3(SEQ, BH), 256>>>(valid);

    // 5) ctx = attn @ V (NN, merged-head epilogue)
    gemm_mma<128,64,2,2,false,2><<<dim3(1, 8, BH), 128, smPV>>>(
        Sp, Vp, Cp, SEQ, HD, SEQ,
        (long)SEQ * SEQ, (long)SEQ * HD, 0);

    // 6) ctx += pe @ Ev
    relv_kernel<<<(BH * SEQ * HD + 255) / 256, 256>>>(Ev);

    // 7) out = ctx @ Wo^T
    gemm_mma<128,128,2,4,true,0><<<dim3(DM / 128, M / 128, 1), 256, smBig>>>(
        Cp, Wo, out, M, DM, DM, 0, 0, 0);
}

// round 4
// speedup vs baseline: 3.2457x; 1.2216x over previous
#include <cuda_runtime.h>
#include <math.h>
#include <stdint.h>

#define BATCH 4
#define SEQ   1024
#define DM    1024
#define NH    16
#define HD    64
#define BH    (BATCH*NH)   // 64
#define NREL  33
#define NEGV  (-1e6f)

// ---------------- scratch (device globals: allocation is forbidden) ----------
__device__ float g_Q[BH*SEQ*HD];                 // [bh][s][d]
__device__ float g_K[BH*SEQ*HD];
__device__ float g_V[BH*SEQ*HD];
__device__ float g_qek[BH*SEQ*NREL];             // [bh][s][r]
__device__ float g_pe [BH*SEQ*NREL];
__device__ float g_ctx[BATCH*SEQ*DM];            // merged-head context
__device__ float g_scores[(size_t)BH*SEQ*SEQ];   // [bh][q][k]

// ---------------- helpers ----------------------------------------------------
__device__ __forceinline__ uint32_t f2tf(float f) {
    uint32_t u;
    asm("cvt.rna.tf32.f32 %0, %1;" : "=r"(u) : "f"(f));
    return u;
}

__device__ __forceinline__ void mma8(float* c,
    uint32_t a0, uint32_t a1, uint32_t a2, uint32_t a3,
    uint32_t b0, uint32_t b1)
{
    asm volatile(
        "mma.sync.aligned.m16n8k8.row.col.f32.tf32.tf32.f32 "
        "{%0,%1,%2,%3}, {%4,%5,%6,%7}, {%8,%9}, {%0,%1,%2,%3};"
        : "+f"(c[0]), "+f"(c[1]), "+f"(c[2]), "+f"(c[3])
        : "r"(a0), "r"(a1), "r"(a2), "r"(a3), "r"(b0), "r"(b1));
}

__device__ __forceinline__ void cp16(void* smem_dst, const void* gmem_src) {
    uint32_t s = (uint32_t)__cvta_generic_to_shared(smem_dst);
    asm volatile("cp.async.cg.shared.global [%0], [%1], 16;\n"
                 :: "r"(s), "l"(gmem_src));
}
__device__ __forceinline__ void cp_commit() {
    asm volatile("cp.async.commit_group;\n");
}
template<int N>
__device__ __forceinline__ void cp_wait() {
    asm volatile("cp.async.wait_group %0;\n" :: "n"(N));
}

// =============================================================================
// Big NT GEMM: C = A * B^T. A[M,K] rm, B[N,K] rm. 128x128 tile, 128 threads,
// warp tile 64x64 (4x8 m16n8k8). 2-stage cp.async.
// OUT: 0 plain, 1 split-heads projection. VLSKIP: skip col tiles >= ceil64(vl).
// =============================================================================
template<int OUT, bool VLSKIP>
__global__ void __launch_bounds__(128)
gemm_big(const float* __restrict__ A, const float* __restrict__ B,
         float* __restrict__ C, int M, int N, int K,
         long sA, long sB, long sC, const int* __restrict__ vlp)
{
    constexpr int BM = 128, BN = 128, BK = 32, T = 128;
    constexpr int ASZ = BM * (BK + 4);

    int z = blockIdx.z;
    int n0 = blockIdx.x * BN;
    if (VLSKIP) {
        int vl = vlp[z >> 4];
        int vlc = (vl + 63) & ~63;
        if (n0 >= vlc) return;
    }

    extern __shared__ float dynsmem[];
    float (*As)[BM][BK + 4] = reinterpret_cast<float(*)[BM][BK + 4]>(dynsmem);
    float (*Bs)[BN][BK + 4] = reinterpret_cast<float(*)[BN][BK + 4]>(dynsmem + 2 * ASZ);

    A += (long)z * sA;  B += (long)z * sB;  C += (long)z * sC;

    int m0  = blockIdx.y * BM;
    int tid = threadIdx.x;
    int lane = tid & 31, warp = tid >> 5;
    int gid = lane >> 2, tig = lane & 3;
    int wm0 = (warp >> 1) * 64;
    int wn0 = (warp & 1) * 64;

    auto load_tiles = [&](int buf, int k0) {
        #pragma unroll
        for (int it = 0; it < 8; it++) {
            int idx = tid + it * T;
            int row = idx >> 3, kq = (idx & 7) << 2;
            cp16(&As[buf][row][kq], &A[(size_t)(m0 + row) * K + k0 + kq]);
        }
        #pragma unroll
        for (int it = 0; it < 8; it++) {
            int idx = tid + it * T;
            int row = idx >> 3, kq = (idx & 7) << 2;
            cp16(&Bs[buf][row][kq], &B[(size_t)(n0 + row) * K + k0 + kq]);
        }
        cp_commit();
    };

    float acc[4][8][4];
    #pragma unroll
    for (int i = 0; i < 4; i++)
        #pragma unroll
        for (int j = 0; j < 8; j++)
            #pragma unroll
            for (int l = 0; l < 4; l++) acc[i][j][l] = 0.f;

    const int KT = K / BK;
    load_tiles(0, 0);

    for (int kt = 0; kt < KT; kt++) {
        int buf = kt & 1;
        if (kt + 1 < KT) { load_tiles(buf ^ 1, (kt + 1) * BK); cp_wait<1>(); }
        else             { cp_wait<0>(); }
        __syncthreads();

        #pragma unroll
        for (int kc = 0; kc < BK / 8; kc++) {
            int kb = kc * 8;
            uint32_t af[4][4];
            #pragma unroll
            for (int mt = 0; mt < 4; mt++) {
                int r = wm0 + mt * 16 + gid;
                af[mt][0] = f2tf(As[buf][r    ][kb + tig]);
                af[mt][1] = f2tf(As[buf][r + 8][kb + tig]);
                af[mt][2] = f2tf(As[buf][r    ][kb + tig + 4]);
                af[mt][3] = f2tf(As[buf][r + 8][kb + tig + 4]);
            }
            uint32_t bf[8][2];
            #pragma unroll
            for (int nt = 0; nt < 8; nt++) {
                int cn = wn0 + nt * 8 + gid;
                bf[nt][0] = f2tf(Bs[buf][cn][kb + tig]);
                bf[nt][1] = f2tf(Bs[buf][cn][kb + tig + 4]);
            }
            #pragma unroll
            for (int mt = 0; mt < 4; mt++)
                #pragma unroll
                for (int nt = 0; nt < 8; nt++)
                    mma8(acc[mt][nt], af[mt][0], af[mt][1], af[mt][2], af[mt][3],
                         bf[nt][0], bf[nt][1]);
        }
        __syncthreads();
    }

    #pragma unroll
    for (int mt = 0; mt < 4; mt++) {
        #pragma unroll
        for (int nt = 0; nt < 8; nt++) {
            int r0 = m0 + wm0 + mt * 16 + gid;
            int c0 = n0 + wn0 + nt * 8 + 2 * tig;
            float2 t0 = make_float2(acc[mt][nt][0], acc[mt][nt][1]);
            float2 t1 = make_float2(acc[mt][nt][2], acc[mt][nt][3]);
            if (OUT == 0) {
                *reinterpret_cast<float2*>(&C[(size_t)r0 * N + c0]) = t0;
                *reinterpret_cast<float2*>(&C[(size_t)(r0 + 8) * N + c0]) = t1;
            } else {
                int b = r0 >> 10, s = r0 & 1023, h = c0 >> 6, d = c0 & 63;
                *reinterpret_cast<float2*>(
                    &C[(size_t)((b * NH + h) * SEQ + s) * HD + d]) = t0;
                int b2 = (r0 + 8) >> 10, s2 = (r0 + 8) & 1023;
                *reinterpret_cast<float2*>(
                    &C[(size_t)((b2 * NH + h) * SEQ + s2) * HD + d]) = t1;
            }
        }
    }
}

// =============================================================================
// PV GEMM: ctx = P * V (NN), per head, k-loop limited to ceil64(vl).
// 128x64 tile, 128 threads, warp 64x32.
// =============================================================================
__global__ void __launch_bounds__(128)
gemm_pv(const float* __restrict__ P, const float* __restrict__ V,
        float* __restrict__ C, const int* __restrict__ vlp)
{
    constexpr int BM = 128, BN = 64, BK = 32, T = 128;
    constexpr int ASZ = BM * (BK + 4);

    int z = blockIdx.z;                       // bh
    int vl  = vlp[z >> 4];
    int vlc = (vl + 63) & ~63;

    extern __shared__ float dynsmem[];
    float (*As)[BM][BK + 4] = reinterpret_cast<float(*)[BM][BK + 4]>(dynsmem);
    float (*Bs)[BK][BN + 4] = reinterpret_cast<float(*)[BK][BN + 4]>(dynsmem + 2 * ASZ);

    const float* A  = P + (size_t)z * SEQ * SEQ;
    const float* Bp = V + (size_t)z * SEQ * HD;

    int m0  = blockIdx.y * BM;
    int tid = threadIdx.x;
    int lane = tid & 31, warp = tid >> 5;
    int gid = lane >> 2, tig = lane & 3;
    int wm0 = (warp >> 1) * 64;
    int wn0 = (warp & 1) * 32;

    auto load_tiles = [&](int buf, int k0) {
        #pragma unroll
        for (int it = 0; it < 8; it++) {
            int idx = tid + it * T;
            int row = idx >> 3, kq = (idx & 7) << 2;
            cp16(&As[buf][row][kq], &A[(size_t)(m0 + row) * SEQ + k0 + kq]);
        }
        #pragma unroll
        for (int it = 0; it < 4; it++) {
            int idx = tid + it * T;
            int row = idx >> 4, nq = (idx & 15) << 2;
            cp16(&Bs[buf][row][nq], &Bp[(size_t)(k0 + row) * HD + nq]);
        }
        cp_commit();
    };

    float acc[4][4][4];
    #pragma unroll
    for (int i = 0; i < 4; i++)
        #pragma unroll
        for (int j = 0; j < 4; j++)
            #pragma unroll
            for (int l = 0; l < 4; l++) acc[i][j][l] = 0.f;

    const int KT = vlc / BK;
    load_tiles(0, 0);

    for (int kt = 0; kt < KT; kt++) {
        int buf = kt & 1;
        if (kt + 1 < KT) { load_tiles(buf ^ 1, (kt + 1) * BK); cp_wait<1>(); }
        else             { cp_wait<0>(); }
        __syncthreads();

        #pragma unroll
        for (int kc = 0; kc < BK / 8; kc++) {
            int kb = kc * 8;
            uint32_t af[4][4];
            #pragma unroll
            for (int mt = 0; mt < 4; mt++) {
                int r = wm0 + mt * 16 + gid;
                af[mt][0] = f2tf(As[buf][r    ][kb + tig]);
                af[mt][1] = f2tf(As[buf][r + 8][kb + tig]);
                af[mt][2] = f2tf(As[buf][r    ][kb + tig + 4]);
                af[mt][3] = f2tf(As[buf][r + 8][kb + tig + 4]);
            }
            uint32_t bf[4][2];
            #pragma unroll
            for (int nt = 0; nt < 4; nt++) {
                int cn = wn0 + nt * 8 + gid;
                bf[nt][0] = f2tf(Bs[buf][kb + tig    ][cn]);
                bf[nt][1] = f2tf(Bs[buf][kb + tig + 4][cn]);
            }
            #pragma unroll
            for (int mt = 0; mt < 4; mt++)
                #pragma unroll
                for (int nt = 0; nt < 4; nt++)
                    mma8(acc[mt][nt], af[mt][0], af[mt][1], af[mt][2], af[mt][3],
                         bf[nt][0], bf[nt][1]);
        }
        __syncthreads();
    }

    int b = z >> 4, h = z & 15;
    #pragma unroll
    for (int mt = 0; mt < 4; mt++) {
        #pragma unroll
        for (int nt = 0; nt < 4; nt++) {
            int r0 = m0 + wm0 + mt * 16 + gid;
            int c0 = wn0 + nt * 8 + 2 * tig;
            float2 t0 = make_float2(acc[mt][nt][0], acc[mt][nt][1]);
            float2 t1 = make_float2(acc[mt][nt][2], acc[mt][nt][3]);
            *reinterpret_cast<float2*>(
                &C[(size_t)(b * SEQ + r0) * DM + h * HD + c0]) = t0;
            *reinterpret_cast<float2*>(
                &C[(size_t)(b * SEQ + r0 + 8) * DM + h * HD + c0]) = t1;
        }
    }
}

// ---------------- qek[bh,s,r] = sum_d Q[bh,s,d]*Ek[r,d] ----------------------
__global__ void __launch_bounds__(64) qek_kernel(const float* __restrict__ Ek)
{
    __shared__ float4 sEk[NREL][HD / 4];
    int tid = threadIdx.x;
    for (int i = tid; i < NREL * HD / 4; i += 64)
        sEk[i / (HD / 4)][i % (HD / 4)] =
            reinterpret_cast<const float4*>(Ek)[i];
    __syncthreads();

    int row = blockIdx.x * 64 + tid;   // bh*SEQ + s
    const float4* q = reinterpret_cast<const float4*>(g_Q + (size_t)row * HD);
    float acc[NREL];
    #pragma unroll
    for (int r = 0; r < NREL; r++) acc[r] = 0.f;
    #pragma unroll 4
    for (int d4 = 0; d4 < HD / 4; d4++) {
        float4 a = q[d4];
        #pragma unroll
        for (int r = 0; r < NREL; r++) {
            float4 e = sEk[r][d4];
            acc[r] += a.x * e.x + a.y * e.y + a.z * e.z + a.w * e.w;
        }
    }
    float* o = g_qek + (size_t)row * NREL;
    #pragma unroll
    for (int r = 0; r < NREL; r++) o[r] = acc[r];
}

// ---------------- softmax: mask + rel-k add + softmax + pe, vl-trimmed -------
__global__ void __launch_bounds__(256) softmax_kernel(const int* __restrict__ valid_lens)
{
    int q  = blockIdx.x;
    int bh = blockIdx.y;
    int vl  = valid_lens[bh >> 4];
    int vlc = (vl + 63) & ~63;

    float* row = g_scores + ((size_t)bh * SEQ + q) * SEQ;
    const float* qek = g_qek + ((size_t)bh * SEQ + q) * NREL;
    size_t peb = ((size_t)bh * SEQ + q) * NREL;

    __shared__ float sqek[NREL];
    __shared__ float red[256];

    int tid = threadIdx.x;
    if (tid < NREL) sqek[tid] = qek[tid];
    __syncthreads();

    float v[4];
    float mx = -3.4e38f;
    #pragma unroll
    for (int i = 0; i < 4; i++) {
        int k = tid + i * 256;
        float s = NEGV;
        if (k < vl) {
            int dist = min(16, max(-16, k - q));
            s = (row[k] + sqek[dist + 16]) * 0.125f;   // 1/sqrt(64)
        }
        v[i] = s;
        mx = fmaxf(mx, s);
    }
    red[tid] = mx; __syncthreads();
    for (int off = 128; off > 0; off >>= 1) {
        if (tid < off) red[tid] = fmaxf(red[tid], red[tid + off]);
        __syncthreads();
    }
    mx = red[0]; __syncthreads();

    float sum = 0.f;
    #pragma unroll
    for (int i = 0; i < 4; i++) { v[i] = __expf(v[i] - mx); sum += v[i]; }
    red[tid] = sum; __syncthreads();
    for (int off = 128; off > 0; off >>= 1) {
        if (tid < off) red[tid] += red[tid + off];
        __syncthreads();
    }
    float inv = 1.f / red[0]; __syncthreads();

    float sLow = 0.f, sHigh = 0.f;
    #pragma unroll
    for (int i = 0; i < 4; i++) {
        int k = tid + i * 256;
        float p = v[i] * inv;
        if (k < vlc) row[k] = p;          // PV reads only k < vlc
        if (k <= q - 16) sLow  += p;
        if (k >= q + 16) sHigh += p;
    }
    __syncthreads();

    red[tid] = sLow; __syncthreads();
    for (int off = 128; off > 0; off >>= 1) {
        if (tid < off) red[tid] += red[tid + off];
        __syncthreads();
    }
    if (tid == 0) g_pe[peb + 0] = red[0];
    __syncthreads();
    red[tid] = sHigh; __syncthreads();
    for (int off = 128; off > 0; off >>= 1) {
        if (tid < off) red[tid] += red[tid + off];
        __syncthreads();
    }
    if (tid == 0) g_pe[peb + 32] = red[0];

    if (tid >= 1 && tid < 32) {
        int k2 = q + tid - 16;
        g_pe[peb + tid] = (k2 >= 0 && k2 < vl) ? row[k2] : 0.f;
    }
}

// ---------------- ctx += pe @ Ev ---------------------------------------------
__global__ void relv_kernel(const float* __restrict__ Ev)
{
    int idx = blockIdx.x * blockDim.x + threadIdx.x;
    if (idx >= BH * SEQ * HD) return;
    int d     = idx & 63;
    int rowid = idx >> 6;
    int bh    = rowid >> 10;
    int s     = rowid & 1023;
    const float* pe = g_pe + (size_t)rowid * NREL;
    float acc = 0.f;
    #pragma unroll
    for (int r = 0; r < NREL; r++) acc += pe[r] * Ev[r * HD + d];
    int b = bh >> 4, h = bh & 15;
    g_ctx[(size_t)(b * SEQ + s) * DM + h * HD + d] += acc;
}

// ---------------- launch ------------------------------------------------------
extern "C" void kernel_launch(void* const* d_in, const int* in_sizes, int n_in,
                              void* d_out, int out_size)
{
    const float* queries = (const float*)d_in[0];
    const float* keys    = (const float*)d_in[1];
    const float* values  = (const float*)d_in[2];
    const int*   valid   = (const int*)  d_in[3];
    const float* Wq      = (const float*)d_in[4];
    const float* Wk      = (const float*)d_in[5];
    const float* Wv      = (const float*)d_in[6];
    const float* Wo      = (const float*)d_in[7];
    const float* Ek      = (const float*)d_in[8];
    const float* Ev      = (const float*)d_in[9];
    float* out = (float*)d_out;

    float *Qp, *Kp, *Vp, *Sp, *Cp;
    cudaGetSymbolAddress((void**)&Qp, g_Q);
    cudaGetSymbolAddress((void**)&Kp, g_K);
    cudaGetSymbolAddress((void**)&Vp, g_V);
    cudaGetSymbolAddress((void**)&Sp, g_scores);
    cudaGetSymbolAddress((void**)&Cp, g_ctx);

    const int M = BATCH * SEQ;  // 4096

    const int smBig = 2 * (128 * 36 + 128 * 36) * sizeof(float);   // 73728
    const int smPV  = 2 * (128 * 36 + 32 * 68) * sizeof(float);    // 54272

    cudaFuncSetAttribute(gemm_big<1,false>,
        cudaFuncAttributeMaxDynamicSharedMemorySize, smBig);
    cudaFuncSetAttribute(gemm_big<0,false>,
        cudaFuncAttributeMaxDynamicSharedMemorySize, smBig);
    cudaFuncSetAttribute(gemm_big<0,true>,
        cudaFuncAttributeMaxDynamicSharedMemorySize, smBig);
    cudaFuncSetAttribute(gemm_pv,
        cudaFuncAttributeMaxDynamicSharedMemorySize, smPV);

    // 1) projections (tf32 mma), head-split epilogue
    dim3 gproj(DM / 128, M / 128, 1);
    gemm_big<1,false><<<gproj, 128, smBig>>>(queries, Wq, Qp, M, DM, DM, 0, 0, 0, nullptr);
    gemm_big<1,false><<<gproj, 128, smBig>>>(keys,    Wk, Kp, M, DM, DM, 0, 0, 0, nullptr);
    gemm_big<1,false><<<gproj, 128, smBig>>>(values,  Wv, Vp, M, DM, DM, 0, 0, 0, nullptr);

    // 2) qek table
    qek_kernel<<<BH * SEQ / 64, 64>>>(Ek);

    // 3) raw scores = Q K^T per head, col-tiles beyond ceil64(vl) skipped
    gemm_big<0,true><<<dim3(8, 8, BH), 128, smBig>>>(
        Qp, Kp, Sp, SEQ, SEQ, HD,
        (long)SEQ * HD, (long)SEQ * HD, (long)SEQ * SEQ, valid);

    // 4) mask + rel-k + softmax + pe buckets (vl-trimmed)
    softmax_kernel<<<dim3(SEQ, BH), 256>>>(valid);

    // 5) ctx = attn @ V (k-loop limited to ceil64(vl))
    gemm_pv<<<dim3(1, 8, BH), 128, smPV>>>(Sp, Vp, Cp, valid);

    // 6) ctx += pe @ Ev
    relv_kernel<<<(BH * SEQ * HD + 255) / 256, 256>>>(Ev);

    // 7) out = ctx @ Wo^T
    gemm_big<0,false><<<dim3(DM / 128, M / 128, 1), 128, smBig>>>(
        Cp, Wo, out, M, DM, DM, 0, 0, 0, nullptr);
}

// round 5
// speedup vs baseline: 4.5579x; 1.4043x over previous
#include <cuda_runtime.h>
#include <math.h>
#include <stdint.h>

#define BATCH 4
#define SEQ   1024
#define DM    1024
#define NH    16
#define HD    64
#define BH    (BATCH*NH)   // 64
#define NREL  33
#define NEGV  (-1e6f)
// (1/sqrt(64)) * log2(e) : softmax done in log2 domain (bare EX2 on MUFU)
#define SCALE 0.1803368801111243f

// ---------------- scratch (device globals: allocation is forbidden) ----------
__device__ float g_Q[BH*SEQ*HD];                 // [bh][s][d]
__device__ float g_K[BH*SEQ*HD];
__device__ float g_V[BH*SEQ*HD];
__device__ float g_qek[BH*SEQ*NREL];             // [bh][s][r]
__device__ float g_pe [BH*SEQ*NREL];
__device__ float g_ctx[BATCH*SEQ*DM];            // merged-head context

// ---------------- helpers ----------------------------------------------------
__device__ __forceinline__ uint32_t f2tf(float f) {
    uint32_t u;
    asm("cvt.rna.tf32.f32 %0, %1;" : "=r"(u) : "f"(f));
    return u;
}

__device__ __forceinline__ void mma8(float* c,
    uint32_t a0, uint32_t a1, uint32_t a2, uint32_t a3,
    uint32_t b0, uint32_t b1)
{
    asm volatile(
        "mma.sync.aligned.m16n8k8.row.col.f32.tf32.tf32.f32 "
        "{%0,%1,%2,%3}, {%4,%5,%6,%7}, {%8,%9}, {%0,%1,%2,%3};"
        : "+f"(c[0]), "+f"(c[1]), "+f"(c[2]), "+f"(c[3])
        : "r"(a0), "r"(a1), "r"(a2), "r"(a3), "r"(b0), "r"(b1));
}

__device__ __forceinline__ void cp16(void* smem_dst, const void* gmem_src) {
    uint32_t s = (uint32_t)__cvta_generic_to_shared(smem_dst);
    asm volatile("cp.async.cg.shared.global [%0], [%1], 16;\n"
                 :: "r"(s), "l"(gmem_src));
}
__device__ __forceinline__ void cp_commit() {
    asm volatile("cp.async.commit_group;\n");
}
template<int N>
__device__ __forceinline__ void cp_wait() {
    asm volatile("cp.async.wait_group %0;\n" :: "n"(N));
}

// =============================================================================
// Big NT GEMM: C = A * B^T. 128x128 tile, 128 threads, warp tile 64x64.
// OUT: 0 plain, 1 split-heads projection.
// =============================================================================
template<int OUT>
__global__ void __launch_bounds__(128)
gemm_big(const float* __restrict__ A, const float* __restrict__ B,
         float* __restrict__ C, int M, int N, int K)
{
    constexpr int BM = 128, BN = 128, BK = 32, T = 128;
    constexpr int ASZ = BM * (BK + 4);

    extern __shared__ float dynsmem[];
    float (*As)[BM][BK + 4] = reinterpret_cast<float(*)[BM][BK + 4]>(dynsmem);
    float (*Bs)[BN][BK + 4] = reinterpret_cast<float(*)[BN][BK + 4]>(dynsmem + 2 * ASZ);

    int m0  = blockIdx.y * BM, n0 = blockIdx.x * BN;
    int tid = threadIdx.x;
    int lane = tid & 31, warp = tid >> 5;
    int gid = lane >> 2, tig = lane & 3;
    int wm0 = (warp >> 1) * 64;
    int wn0 = (warp & 1) * 64;

    auto load_tiles = [&](int buf, int k0) {
        #pragma unroll
        for (int it = 0; it < 8; it++) {
            int idx = tid + it * T;
            int row = idx >> 3, kq = (idx & 7) << 2;
            cp16(&As[buf][row][kq], &A[(size_t)(m0 + row) * K + k0 + kq]);
        }
        #pragma unroll
        for (int it = 0; it < 8; it++) {
            int idx = tid + it * T;
            int row = idx >> 3, kq = (idx & 7) << 2;
            cp16(&Bs[buf][row][kq], &B[(size_t)(n0 + row) * K + k0 + kq]);
        }
        cp_commit();
    };

    float acc[4][8][4];
    #pragma unroll
    for (int i = 0; i < 4; i++)
        #pragma unroll
        for (int j = 0; j < 8; j++)
            #pragma unroll
            for (int l = 0; l < 4; l++) acc[i][j][l] = 0.f;

    const int KT = K / BK;
    load_tiles(0, 0);

    for (int kt = 0; kt < KT; kt++) {
        int buf = kt & 1;
        if (kt + 1 < KT) { load_tiles(buf ^ 1, (kt + 1) * BK); cp_wait<1>(); }
        else             { cp_wait<0>(); }
        __syncthreads();

        #pragma unroll
        for (int kc = 0; kc < BK / 8; kc++) {
            int kb = kc * 8;
            uint32_t af[4][4];
            #pragma unroll
            for (int mt = 0; mt < 4; mt++) {
                int r = wm0 + mt * 16 + gid;
                af[mt][0] = f2tf(As[buf][r    ][kb + tig]);
                af[mt][1] = f2tf(As[buf][r + 8][kb + tig]);
                af[mt][2] = f2tf(As[buf][r    ][kb + tig + 4]);
                af[mt][3] = f2tf(As[buf][r + 8][kb + tig + 4]);
            }
            uint32_t bf[8][2];
            #pragma unroll
            for (int nt = 0; nt < 8; nt++) {
                int cn = wn0 + nt * 8 + gid;
                bf[nt][0] = f2tf(Bs[buf][cn][kb + tig]);
                bf[nt][1] = f2tf(Bs[buf][cn][kb + tig + 4]);
            }
            #pragma unroll
            for (int mt = 0; mt < 4; mt++)
                #pragma unroll
                for (int nt = 0; nt < 8; nt++)
                    mma8(acc[mt][nt], af[mt][0], af[mt][1], af[mt][2], af[mt][3],
                         bf[nt][0], bf[nt][1]);
        }
        __syncthreads();
    }

    #pragma unroll
    for (int mt = 0; mt < 4; mt++) {
        #pragma unroll
        for (int nt = 0; nt < 8; nt++) {
            int r0 = m0 + wm0 + mt * 16 + gid;
            int c0 = n0 + wn0 + nt * 8 + 2 * tig;
            float2 t0 = make_float2(acc[mt][nt][0], acc[mt][nt][1]);
            float2 t1 = make_float2(acc[mt][nt][2], acc[mt][nt][3]);
            if (OUT == 0) {
                *reinterpret_cast<float2*>(&C[(size_t)r0 * N + c0]) = t0;
                *reinterpret_cast<float2*>(&C[(size_t)(r0 + 8) * N + c0]) = t1;
            } else {
                int b = r0 >> 10, s = r0 & 1023, h = c0 >> 6, d = c0 & 63;
                *reinterpret_cast<float2*>(
                    &C[(size_t)((b * NH + h) * SEQ + s) * HD + d]) = t0;
                int b2 = (r0 + 8) >> 10, s2 = (r0 + 8) & 1023;
                *reinterpret_cast<float2*>(
                    &C[(size_t)((b2 * NH + h) * SEQ + s2) * HD + d]) = t1;
            }
        }
    }
}

// =============================================================================
// Fused flash attention with relative-position bias + pe extraction.
// Block = (bh, 64-row q tile), 128 threads (4 warps x 16 rows).
// Streams K/V tiles (64 keys) to ceil64(vl), online softmax in log2 domain.
// Outputs: g_ctx (merged heads) and g_pe (33 buckets/row).
// =============================================================================
__global__ void __launch_bounds__(128)
flash_kernel(const int* __restrict__ valid_lens)
{
    constexpr int KS = 68;              // padded row stride
    constexpr int TILE = 64 * KS;       // 4352 floats per K/V buffer

    extern __shared__ float sm[];
    float* Ks = sm;                     // [2][64][68]
    float* Vs = Ks + 2 * TILE;          // [2][64][68]
    float* Ps = Vs + 2 * TILE;          // [64][68]  per-warp private 16-row bands
    float* SQ = Ps + 64 * KS;           // [64][33]  qek for this q-tile
    float* SMID = SQ + 64 * NREL;       // [64][33]  raw scores at |dist|<16
    float* MR = SMID + 64 * NREL;       // [64] final row max (log2)
    float* IL = MR + 64;                // [64] final 1/l

    const int q0 = blockIdx.x * 64;
    const int bh = blockIdx.y;
    const int vl  = valid_lens[bh >> 4];
    const int vlc = (vl + 63) & ~63;

    const int tid = threadIdx.x;
    const int lane = tid & 31, warp = tid >> 5;
    const int gid = lane >> 2, tig = lane & 3;
    const int wq = warp * 16;           // warp's first row within the q tile

    auto loadKV = [&](int buf, int k0) {
        const float* Kg = g_K + ((size_t)bh * SEQ + k0) * HD;
        const float* Vg = g_V + ((size_t)bh * SEQ + k0) * HD;
        #pragma unroll
        for (int it = 0; it < 8; it++) {
            int idx = tid + it * 128;
            int row = idx >> 4, c4 = (idx & 15) << 2;
            cp16(&Ks[buf * TILE + row * KS + c4], Kg + row * HD + c4);
        }
        #pragma unroll
        for (int it = 0; it < 8; it++) {
            int idx = tid + it * 128;
            int row = idx >> 4, c4 = (idx & 15) << 2;
            cp16(&Vs[buf * TILE + row * KS + c4], Vg + row * HD + c4);
        }
        cp_commit();
    };

    loadKV(0, 0);

    // Q fragments: resident in registers for the whole kernel
    uint32_t qa[8][4];
    {
        const float* Qg = g_Q + ((size_t)bh * SEQ + q0 + wq) * HD;
        #pragma unroll
        for (int kc = 0; kc < 8; kc++) {
            qa[kc][0] = f2tf(Qg[(size_t)gid       * HD + kc * 8 + tig]);
            qa[kc][1] = f2tf(Qg[(size_t)(gid + 8) * HD + kc * 8 + tig]);
            qa[kc][2] = f2tf(Qg[(size_t)gid       * HD + kc * 8 + tig + 4]);
            qa[kc][3] = f2tf(Qg[(size_t)(gid + 8) * HD + kc * 8 + tig + 4]);
        }
    }

    // qek table + smid init
    for (int i = tid; i < 64 * NREL; i += 128) {
        int row = i / NREL, r = i % NREL;
        SQ[i] = g_qek[((size_t)bh * SEQ + q0 + row) * NREL + r];
        SMID[i] = NEGV;
    }

    const int qrow0 = q0 + wq + gid;
    const int qrow1 = qrow0 + 8;

    float oa[8][4];
    #pragma unroll
    for (int nt = 0; nt < 8; nt++)
        #pragma unroll
        for (int j = 0; j < 4; j++) oa[nt][j] = 0.f;

    float m0 = -1e30f, m1 = -1e30f;
    float l0 = 0.f, l1 = 0.f;
    float eL0 = 0.f, eL1 = 0.f, eH0 = 0.f, eH1 = 0.f;

    const int KT = vlc / 64;
    for (int t = 0; t < KT; t++) {
        int buf = t & 1;
        int k0 = t * 64;
        if (t + 1 < KT) { loadKV(buf ^ 1, k0 + 64); cp_wait<1>(); }
        else            { cp_wait<0>(); }
        __syncthreads();

        // ---- S = Q K^T (16 x 64 per warp)
        float sa[8][4];
        #pragma unroll
        for (int nt = 0; nt < 8; nt++)
            #pragma unroll
            for (int j = 0; j < 4; j++) sa[nt][j] = 0.f;

        const float* Kb = Ks + buf * TILE;
        #pragma unroll
        for (int kc = 0; kc < 8; kc++) {
            #pragma unroll
            for (int nt = 0; nt < 8; nt++) {
                uint32_t b0 = f2tf(Kb[(nt * 8 + gid) * KS + kc * 8 + tig]);
                uint32_t b1 = f2tf(Kb[(nt * 8 + gid) * KS + kc * 8 + tig + 4]);
                mma8(sa[nt], qa[kc][0], qa[kc][1], qa[kc][2], qa[kc][3], b0, b1);
            }
        }

        // ---- rel-pos add, scale->log2 domain, mask; stash mid-band raw scores
        float tm0 = -1e30f, tm1 = -1e30f;
        #pragma unroll
        for (int nt = 0; nt < 8; nt++) {
            int kc0 = k0 + nt * 8 + 2 * tig;
            #pragma unroll
            for (int e = 0; e < 4; e++) {
                int kcol = kc0 + (e & 1);
                int qrow = (e < 2) ? qrow0 : qrow1;
                int rloc = wq + gid + ((e < 2) ? 0 : 8);
                int d = kcol - qrow;
                int bidx = min(16, max(-16, d)) + 16;
                float s = (sa[nt][e] + SQ[rloc * NREL + bidx]) * SCALE;
                if (kcol >= vl) s = NEGV;
                sa[nt][e] = s;
                if (d > -16 && d < 16) SMID[rloc * NREL + bidx] = s;
                if (e < 2) tm0 = fmaxf(tm0, s); else tm1 = fmaxf(tm1, s);
            }
        }
        tm0 = fmaxf(tm0, __shfl_xor_sync(0xffffffffu, tm0, 1));
        tm0 = fmaxf(tm0, __shfl_xor_sync(0xffffffffu, tm0, 2));
        tm1 = fmaxf(tm1, __shfl_xor_sync(0xffffffffu, tm1, 1));
        tm1 = fmaxf(tm1, __shfl_xor_sync(0xffffffffu, tm1, 2));

        float mn0 = fmaxf(m0, tm0), mn1 = fmaxf(m1, tm1);
        float a0 = exp2f(m0 - mn0), a1 = exp2f(m1 - mn1);
        m0 = mn0; m1 = mn1;

        // ---- p = exp2(s - m), partial sums + end buckets
        float ps0 = 0.f, ps1 = 0.f, tl0 = 0.f, tl1 = 0.f, th0 = 0.f, th1 = 0.f;
        #pragma unroll
        for (int nt = 0; nt < 8; nt++) {
            int kc0 = k0 + nt * 8 + 2 * tig;
            #pragma unroll
            for (int e = 0; e < 4; e++) {
                int kcol = kc0 + (e & 1);
                float p = exp2f(sa[nt][e] - ((e < 2) ? mn0 : mn1));
                sa[nt][e] = p;
                int d = kcol - ((e < 2) ? qrow0 : qrow1);
                if (e < 2) {
                    ps0 += p;
                    if (d <= -16) tl0 += p; else if (d >= 16) th0 += p;
                } else {
                    ps1 += p;
                    if (d <= -16) tl1 += p; else if (d >= 16) th1 += p;
                }
            }
        }
        ps0 += __shfl_xor_sync(0xffffffffu, ps0, 1); ps0 += __shfl_xor_sync(0xffffffffu, ps0, 2);
        ps1 += __shfl_xor_sync(0xffffffffu, ps1, 1); ps1 += __shfl_xor_sync(0xffffffffu, ps1, 2);
        tl0 += __shfl_xor_sync(0xffffffffu, tl0, 1); tl0 += __shfl_xor_sync(0xffffffffu, tl0, 2);
        tl1 += __shfl_xor_sync(0xffffffffu, tl1, 1); tl1 += __shfl_xor_sync(0xffffffffu, tl1, 2);
        th0 += __shfl_xor_sync(0xffffffffu, th0, 1); th0 += __shfl_xor_sync(0xffffffffu, th0, 2);
        th1 += __shfl_xor_sync(0xffffffffu, th1, 1); th1 += __shfl_xor_sync(0xffffffffu, th1, 2);

        l0 = l0 * a0 + ps0;  l1 = l1 * a1 + ps1;
        eL0 = eL0 * a0 + tl0; eL1 = eL1 * a1 + tl1;
        eH0 = eH0 * a0 + th0; eH1 = eH1 * a1 + th1;

        // ---- rescale O, stage P (per-warp private band), accumulate P V
        #pragma unroll
        for (int nt = 0; nt < 8; nt++) {
            oa[nt][0] *= a0; oa[nt][1] *= a0;
            oa[nt][2] *= a1; oa[nt][3] *= a1;
            *reinterpret_cast<float2*>(&Ps[(wq + gid) * KS + nt * 8 + 2 * tig]) =
                make_float2(sa[nt][0], sa[nt][1]);
            *reinterpret_cast<float2*>(&Ps[(wq + gid + 8) * KS + nt * 8 + 2 * tig]) =
                make_float2(sa[nt][2], sa[nt][3]);
        }
        __syncwarp();

        const float* Vb = Vs + buf * TILE;
        #pragma unroll
        for (int kc = 0; kc < 8; kc++) {
            uint32_t p0 = f2tf(Ps[(wq + gid)     * KS + kc * 8 + tig]);
            uint32_t p1 = f2tf(Ps[(wq + gid + 8) * KS + kc * 8 + tig]);
            uint32_t p2 = f2tf(Ps[(wq + gid)     * KS + kc * 8 + tig + 4]);
            uint32_t p3 = f2tf(Ps[(wq + gid + 8) * KS + kc * 8 + tig + 4]);
            #pragma unroll
            for (int nt = 0; nt < 8; nt++) {
                uint32_t b0 = f2tf(Vb[(kc * 8 + tig)     * KS + nt * 8 + gid]);
                uint32_t b1 = f2tf(Vb[(kc * 8 + tig + 4) * KS + nt * 8 + gid]);
                mma8(oa[nt], p0, p1, p2, p3, b0, b1);
            }
        }
        __syncthreads();   // everyone done reading this K/V buffer
    }

    // ---- epilogue: normalize O, write ctx; pe ends + mids
    const int b = bh >> 4, h = bh & 15;
    float il0 = 1.f / l0, il1 = 1.f / l1;
    #pragma unroll
    for (int nt = 0; nt < 8; nt++) {
        int col = h * HD + nt * 8 + 2 * tig;
        *reinterpret_cast<float2*>(&g_ctx[(size_t)(b * SEQ + qrow0) * DM + col]) =
            make_float2(oa[nt][0] * il0, oa[nt][1] * il0);
        *reinterpret_cast<float2*>(&g_ctx[(size_t)(b * SEQ + qrow1) * DM + col]) =
            make_float2(oa[nt][2] * il1, oa[nt][3] * il1);
    }
    if (tig == 0) {
        MR[wq + gid] = m0;     IL[wq + gid] = il0;
        MR[wq + gid + 8] = m1; IL[wq + gid + 8] = il1;
        size_t pb0 = ((size_t)bh * SEQ + qrow0) * NREL;
        size_t pb1 = ((size_t)bh * SEQ + qrow1) * NREL;
        g_pe[pb0 + 0]  = eL0 * il0;  g_pe[pb0 + 32] = eH0 * il0;
        g_pe[pb1 + 0]  = eL1 * il1;  g_pe[pb1 + 32] = eH1 * il1;
    }
    __syncthreads();
    for (int i = tid; i < 64 * 31; i += 128) {
        int row = i / 31, r = i % 31 + 1;
        float p = exp2f(SMID[row * NREL + r] - MR[row]) * IL[row];
        g_pe[((size_t)bh * SEQ + q0 + row) * NREL + r] = p;
    }
}

// ---------------- qek[bh,s,r] = sum_d Q[bh,s,d]*Ek[r,d] ----------------------
__global__ void __launch_bounds__(64) qek_kernel(const float* __restrict__ Ek)
{
    __shared__ float4 sEk[NREL][HD / 4];
    int tid = threadIdx.x;
    for (int i = tid; i < NREL * HD / 4; i += 64)
        sEk[i / (HD / 4)][i % (HD / 4)] =
            reinterpret_cast<const float4*>(Ek)[i];
    __syncthreads();

    int row = blockIdx.x * 64 + tid;   // bh*SEQ + s
    const float4* q = reinterpret_cast<const float4*>(g_Q + (size_t)row * HD);
    float acc[NREL];
    #pragma unroll
    for (int r = 0; r < NREL; r++) acc[r] = 0.f;
    #pragma unroll 4
    for (int d4 = 0; d4 < HD / 4; d4++) {
        float4 a = q[d4];
        #pragma unroll
        for (int r = 0; r < NREL; r++) {
            float4 e = sEk[r][d4];
            acc[r] += a.x * e.x + a.y * e.y + a.z * e.z + a.w * e.w;
        }
    }
    float* o = g_qek + (size_t)row * NREL;
    #pragma unroll
    for (int r = 0; r < NREL; r++) o[r] = acc[r];
}

// ---------------- ctx += pe @ Ev ---------------------------------------------
__global__ void relv_kernel(const float* __restrict__ Ev)
{
    int idx = blockIdx.x * blockDim.x + threadIdx.x;
    if (idx >= BH * SEQ * HD) return;
    int d     = idx & 63;
    int rowid = idx >> 6;
    int bh    = rowid >> 10;
    int s     = rowid & 1023;
    const float* pe = g_pe + (size_t)rowid * NREL;
    float acc = 0.f;
    #pragma unroll
    for (int r = 0; r < NREL; r++) acc += pe[r] * Ev[r * HD + d];
    int b = bh >> 4, h = bh & 15;
    g_ctx[(size_t)(b * SEQ + s) * DM + h * HD + d] += acc;
}

// ---------------- launch ------------------------------------------------------
extern "C" void kernel_launch(void* const* d_in, const int* in_sizes, int n_in,
                              void* d_out, int out_size)
{
    const float* queries = (const float*)d_in[0];
    const float* keys    = (const float*)d_in[1];
    const float* values  = (const float*)d_in[2];
    const int*   valid   = (const int*)  d_in[3];
    const float* Wq      = (const float*)d_in[4];
    const float* Wk      = (const float*)d_in[5];
    const float* Wv      = (const float*)d_in[6];
    const float* Wo      = (const float*)d_in[7];
    const float* Ek      = (const float*)d_in[8];
    const float* Ev      = (const float*)d_in[9];
    float* out = (float*)d_out;

    float *Qp, *Kp, *Vp, *Cp;
    cudaGetSymbolAddress((void**)&Qp, g_Q);
    cudaGetSymbolAddress((void**)&Kp, g_K);
    cudaGetSymbolAddress((void**)&Vp, g_V);
    cudaGetSymbolAddress((void**)&Cp, g_ctx);

    const int M = BATCH * SEQ;  // 4096

    const int smBig   = 2 * (128 * 36 + 128 * 36) * sizeof(float);   // 73728
    const int smFlash = (2 * 64 * 68 + 2 * 64 * 68 + 64 * 68
                         + 64 * NREL + 64 * NREL + 128) * sizeof(float); // 104448

    cudaFuncSetAttribute(gemm_big<1>,
        cudaFuncAttributeMaxDynamicSharedMemorySize, smBig);
    cudaFuncSetAttribute(gemm_big<0>,
        cudaFuncAttributeMaxDynamicSharedMemorySize, smBig);
    cudaFuncSetAttribute(flash_kernel,
        cudaFuncAttributeMaxDynamicSharedMemorySize, smFlash);

    // 1) projections (tf32 mma), head-split epilogue
    dim3 gproj(DM / 128, M / 128, 1);
    gemm_big<1><<<gproj, 128, smBig>>>(queries, Wq, Qp, M, DM, DM);
    gemm_big<1><<<gproj, 128, smBig>>>(keys,    Wk, Kp, M, DM, DM);
    gemm_big<1><<<gproj, 128, smBig>>>(values,  Wv, Vp, M, DM, DM);

    // 2) qek table
    qek_kernel<<<BH * SEQ / 64, 64>>>(Ek);

    // 3) fused: scores + rel-k + mask + softmax + PV + pe extraction
    flash_kernel<<<dim3(SEQ / 64, BH), 128, smFlash>>>(valid);

    // 4) ctx += pe @ Ev
    relv_kernel<<<(BH * SEQ * HD + 255) / 256, 256>>>(Ev);

    // 5) out = ctx @ Wo^T
    gemm_big<0><<<dim3(DM / 128, M / 128, 1), 128, smBig>>>(
        Cp, Wo, out, M, DM, DM);
}

// round 6
// speedup vs baseline: 5.4612x; 1.1982x over previous
#include <cuda_runtime.h>
#include <math.h>
#include <stdint.h>

#define BATCH 4
#define SEQ   1024
#define DM    1024
#define NH    16
#define HD    64
#define BH    (BATCH*NH)   // 64
#define NREL  33
#define NEGV  (-1e6f)
// (1/sqrt(64)) * log2(e) : softmax in log2 domain
#define SCALE 0.1803368801111243f

// ---------------- scratch (device globals: allocation is forbidden) ----------
__device__ float g_Q[BH*SEQ*HD];                 // [bh][s][d]
__device__ float g_K[BH*SEQ*HD];
__device__ float g_V[BH*SEQ*HD];
__device__ float g_ctx[BATCH*SEQ*DM];            // merged-head context

// ---------------- helpers ----------------------------------------------------
__device__ __forceinline__ uint32_t f2tf(float f) {
    uint32_t u;
    asm("cvt.rna.tf32.f32 %0, %1;" : "=r"(u) : "f"(f));
    return u;
}

__device__ __forceinline__ void mma8(float* c,
    uint32_t a0, uint32_t a1, uint32_t a2, uint32_t a3,
    uint32_t b0, uint32_t b1)
{
    asm volatile(
        "mma.sync.aligned.m16n8k8.row.col.f32.tf32.tf32.f32 "
        "{%0,%1,%2,%3}, {%4,%5,%6,%7}, {%8,%9}, {%0,%1,%2,%3};"
        : "+f"(c[0]), "+f"(c[1]), "+f"(c[2]), "+f"(c[3])
        : "r"(a0), "r"(a1), "r"(a2), "r"(a3), "r"(b0), "r"(b1));
}

__device__ __forceinline__ void cp16(void* smem_dst, const void* gmem_src) {
    uint32_t s = (uint32_t)__cvta_generic_to_shared(smem_dst);
    asm volatile("cp.async.cg.shared.global [%0], [%1], 16;\n"
                 :: "r"(s), "l"(gmem_src));
}
__device__ __forceinline__ void cp_commit() {
    asm volatile("cp.async.commit_group;\n");
}
template<int N>
__device__ __forceinline__ void cp_wait() {
    asm volatile("cp.async.wait_group %0;\n" :: "n"(N));
}

struct Proj3Args {
    const float* A[3];
    const float* B[3];
    float*       C[3];
};

// =============================================================================
// Big NT GEMM: C = A * B^T. 128x128 tile, 128 threads, warp tile 64x64.
// PROJ3: blockIdx.z selects (A,B,C) triple, split-heads epilogue.
// else: single matrices, plain epilogue.
// =============================================================================
template<bool PROJ3>
__global__ void __launch_bounds__(128)
gemm_big(Proj3Args args, int M, int N, int K)
{
    constexpr int BM = 128, BN = 128, BK = 32, T = 128;
    constexpr int ASZ = BM * (BK + 4);

    extern __shared__ float dynsmem[];
    float (*As)[BM][BK + 4] = reinterpret_cast<float(*)[BM][BK + 4]>(dynsmem);
    float (*Bs)[BN][BK + 4] = reinterpret_cast<float(*)[BN][BK + 4]>(dynsmem + 2 * ASZ);

    int z = PROJ3 ? blockIdx.z : 0;
    const float* A = args.A[z];
    const float* B = args.B[z];
    float*       C = args.C[z];

    int m0  = blockIdx.y * BM, n0 = blockIdx.x * BN;
    int tid = threadIdx.x;
    int lane = tid & 31, warp = tid >> 5;
    int gid = lane >> 2, tig = lane & 3;
    int wm0 = (warp >> 1) * 64;
    int wn0 = (warp & 1) * 64;

    auto load_tiles = [&](int buf, int k0) {
        #pragma unroll
        for (int it = 0; it < 8; it++) {
            int idx = tid + it * T;
            int row = idx >> 3, kq = (idx & 7) << 2;
            cp16(&As[buf][row][kq], &A[(size_t)(m0 + row) * K + k0 + kq]);
        }
        #pragma unroll
        for (int it = 0; it < 8; it++) {
            int idx = tid + it * T;
            int row = idx >> 3, kq = (idx & 7) << 2;
            cp16(&Bs[buf][row][kq], &B[(size_t)(n0 + row) * K + k0 + kq]);
        }
        cp_commit();
    };

    float acc[4][8][4];
    #pragma unroll
    for (int i = 0; i < 4; i++)
        #pragma unroll
        for (int j = 0; j < 8; j++)
            #pragma unroll
            for (int l = 0; l < 4; l++) acc[i][j][l] = 0.f;

    const int KT = K / BK;
    load_tiles(0, 0);

    for (int kt = 0; kt < KT; kt++) {
        int buf = kt & 1;
        if (kt + 1 < KT) { load_tiles(buf ^ 1, (kt + 1) * BK); cp_wait<1>(); }
        else             { cp_wait<0>(); }
        __syncthreads();

        #pragma unroll
        for (int kc = 0; kc < BK / 8; kc++) {
            int kb = kc * 8;
            uint32_t af[4][4];
            #pragma unroll
            for (int mt = 0; mt < 4; mt++) {
                int r = wm0 + mt * 16 + gid;
                af[mt][0] = f2tf(As[buf][r    ][kb + tig]);
                af[mt][1] = f2tf(As[buf][r + 8][kb + tig]);
                af[mt][2] = f2tf(As[buf][r    ][kb + tig + 4]);
                af[mt][3] = f2tf(As[buf][r + 8][kb + tig + 4]);
            }
            uint32_t bf[8][2];
            #pragma unroll
            for (int nt = 0; nt < 8; nt++) {
                int cn = wn0 + nt * 8 + gid;
                bf[nt][0] = f2tf(Bs[buf][cn][kb + tig]);
                bf[nt][1] = f2tf(Bs[buf][cn][kb + tig + 4]);
            }
            #pragma unroll
            for (int mt = 0; mt < 4; mt++)
                #pragma unroll
                for (int nt = 0; nt < 8; nt++)
                    mma8(acc[mt][nt], af[mt][0], af[mt][1], af[mt][2], af[mt][3],
                         bf[nt][0], bf[nt][1]);
        }
        __syncthreads();
    }

    #pragma unroll
    for (int mt = 0; mt < 4; mt++) {
        #pragma unroll
        for (int nt = 0; nt < 8; nt++) {
            int r0 = m0 + wm0 + mt * 16 + gid;
            int c0 = n0 + wn0 + nt * 8 + 2 * tig;
            float2 t0 = make_float2(acc[mt][nt][0], acc[mt][nt][1]);
            float2 t1 = make_float2(acc[mt][nt][2], acc[mt][nt][3]);
            if (PROJ3) {   // split heads: [B,S,D] -> [bh][s][d]
                int b = r0 >> 10, s = r0 & 1023, h = c0 >> 6, d = c0 & 63;
                *reinterpret_cast<float2*>(
                    &C[(size_t)((b * NH + h) * SEQ + s) * HD + d]) = t0;
                int b2 = (r0 + 8) >> 10, s2 = (r0 + 8) & 1023;
                *reinterpret_cast<float2*>(
                    &C[(size_t)((b2 * NH + h) * SEQ + s2) * HD + d]) = t1;
            } else {
                *reinterpret_cast<float2*>(&C[(size_t)r0 * N + c0]) = t0;
                *reinterpret_cast<float2*>(&C[(size_t)(r0 + 8) * N + c0]) = t1;
            }
        }
    }
}

// =============================================================================
// Fully fused flash attention: qek (via resident Q fragments) + scores +
// rel-k bias + mask + online softmax + PV + pe extraction + pe@Ev epilogue.
// Block = (64-row q tile, bh), 128 threads (4 warps x 16 rows).
// =============================================================================
__global__ void __launch_bounds__(128)
flash_kernel(const int* __restrict__ valid_lens,
             const float* __restrict__ Ek, const float* __restrict__ Ev)
{
    constexpr int KS = 68;              // padded row stride
    constexpr int TILE = 64 * KS;

    extern __shared__ float sm[];
    float* Ks = sm;                     // [2][64][68]
    float* Vs = Ks + 2 * TILE;          // [2][64][68]
    float* Ps = Vs + 2 * TILE;          // [64][68]: Ek -> P staging -> Ev
    float* SQ = Ps + 64 * KS;           // [64][33]: qek, then normalized pe
    float* SMID = SQ + 64 * NREL;       // [64][33]: raw scores at |dist|<16
    float* MR = SMID + 64 * NREL;       // [64] final row max (log2 domain)
    float* IL = MR + 64;                // [64] final 1/l

    const int q0 = blockIdx.x * 64;
    const int bh = blockIdx.y;
    const int vl  = valid_lens[bh >> 4];
    const int vlc = (vl + 63) & ~63;

    const int tid = threadIdx.x;
    const int lane = tid & 31, warp = tid >> 5;
    const int gid = lane >> 2, tig = lane & 3;
    const int wq = warp * 16;

    auto loadKV = [&](int buf, int k0) {
        const float* Kg = g_K + ((size_t)bh * SEQ + k0) * HD;
        const float* Vg = g_V + ((size_t)bh * SEQ + k0) * HD;
        #pragma unroll
        for (int it = 0; it < 8; it++) {
            int idx = tid + it * 128;
            int row = idx >> 4, c4 = (idx & 15) << 2;
            cp16(&Ks[buf * TILE + row * KS + c4], Kg + row * HD + c4);
        }
        #pragma unroll
        for (int it = 0; it < 8; it++) {
            int idx = tid + it * 128;
            int row = idx >> 4, c4 = (idx & 15) << 2;
            cp16(&Vs[buf * TILE + row * KS + c4], Vg + row * HD + c4);
        }
        cp_commit();
    };

    loadKV(0, 0);

    // Ek -> Ps  (rows r=0..32, cols d=0..63)
    for (int i = tid; i < NREL * 16; i += 128) {
        int row = i >> 4, c = i & 15;
        *reinterpret_cast<float4*>(&Ps[row * KS + 4 * c]) =
            reinterpret_cast<const float4*>(Ek)[i];
    }

    // Q fragments: resident in registers for the whole kernel
    uint32_t qa[8][4];
    {
        const float* Qg = g_Q + ((size_t)bh * SEQ + q0 + wq) * HD;
        #pragma unroll
        for (int kc = 0; kc < 8; kc++) {
            qa[kc][0] = f2tf(Qg[(size_t)gid       * HD + kc * 8 + tig]);
            qa[kc][1] = f2tf(Qg[(size_t)(gid + 8) * HD + kc * 8 + tig]);
            qa[kc][2] = f2tf(Qg[(size_t)gid       * HD + kc * 8 + tig + 4]);
            qa[kc][3] = f2tf(Qg[(size_t)(gid + 8) * HD + kc * 8 + tig + 4]);
        }
    }
    __syncthreads();    // Ek visible

    // qek: SQ[row][r] = Q[row] . Ek[r]  (tf32 mma, 5 n-tiles of 8, pad->40)
    {
        float sq[5][4];
        #pragma unroll
        for (int nt = 0; nt < 5; nt++)
            #pragma unroll
            for (int e = 0; e < 4; e++) sq[nt][e] = 0.f;
        #pragma unroll
        for (int kc = 0; kc < 8; kc++) {
            #pragma unroll
            for (int nt = 0; nt < 5; nt++) {
                uint32_t b0 = f2tf(Ps[(nt * 8 + gid) * KS + kc * 8 + tig]);
                uint32_t b1 = f2tf(Ps[(nt * 8 + gid) * KS + kc * 8 + tig + 4]);
                mma8(sq[nt], qa[kc][0], qa[kc][1], qa[kc][2], qa[kc][3], b0, b1);
            }
        }
        #pragma unroll
        for (int nt = 0; nt < 5; nt++) {
            #pragma unroll
            for (int e = 0; e < 4; e++) {
                int col = nt * 8 + 2 * tig + (e & 1);
                int row = wq + gid + ((e < 2) ? 0 : 8);
                if (col < NREL) SQ[row * NREL + col] = sq[nt][e];
            }
        }
    }
    for (int i = tid; i < 64 * NREL; i += 128) SMID[i] = NEGV;
    __syncthreads();    // SQ/SMID ready; Ps free for P staging

    const int qrow0 = q0 + wq + gid;
    const int qrow1 = qrow0 + 8;

    float oa[8][4];
    #pragma unroll
    for (int nt = 0; nt < 8; nt++)
        #pragma unroll
        for (int j = 0; j < 4; j++) oa[nt][j] = 0.f;

    float m0 = -1e30f, m1 = -1e30f;
    float l0 = 0.f, l1 = 0.f;
    float eL0 = 0.f, eL1 = 0.f, eH0 = 0.f, eH1 = 0.f;

    const int KT = vlc / 64;
    for (int t = 0; t < KT; t++) {
        int buf = t & 1;
        int k0 = t * 64;
        if (t + 1 < KT) { loadKV(buf ^ 1, k0 + 64); cp_wait<1>(); }
        else            { cp_wait<0>(); }
        __syncthreads();

        // ---- S = Q K^T
        float sa[8][4];
        #pragma unroll
        for (int nt = 0; nt < 8; nt++)
            #pragma unroll
            for (int j = 0; j < 4; j++) sa[nt][j] = 0.f;

        const float* Kb = Ks + buf * TILE;
        #pragma unroll
        for (int kc = 0; kc < 8; kc++) {
            #pragma unroll
            for (int nt = 0; nt < 8; nt++) {
                uint32_t b0 = f2tf(Kb[(nt * 8 + gid) * KS + kc * 8 + tig]);
                uint32_t b1 = f2tf(Kb[(nt * 8 + gid) * KS + kc * 8 + tig + 4]);
                mma8(sa[nt], qa[kc][0], qa[kc][1], qa[kc][2], qa[kc][3], b0, b1);
            }
        }

        // ---- rel-pos add, scale into log2 domain, mask; stash mid-band
        float tm0 = -1e30f, tm1 = -1e30f;
        #pragma unroll
        for (int nt = 0; nt < 8; nt++) {
            int kc0 = k0 + nt * 8 + 2 * tig;
            #pragma unroll
            for (int e = 0; e < 4; e++) {
                int kcol = kc0 + (e & 1);
                int qrow = (e < 2) ? qrow0 : qrow1;
                int rloc = wq + gid + ((e < 2) ? 0 : 8);
                int d = kcol - qrow;
                int bidx = min(16, max(-16, d)) + 16;
                float s = (sa[nt][e] + SQ[rloc * NREL + bidx]) * SCALE;
                if (kcol >= vl) s = NEGV;
                sa[nt][e] = s;
                if (d > -16 && d < 16) SMID[rloc * NREL + bidx] = s;
                if (e < 2) tm0 = fmaxf(tm0, s); else tm1 = fmaxf(tm1, s);
            }
        }
        tm0 = fmaxf(tm0, __shfl_xor_sync(0xffffffffu, tm0, 1));
        tm0 = fmaxf(tm0, __shfl_xor_sync(0xffffffffu, tm0, 2));
        tm1 = fmaxf(tm1, __shfl_xor_sync(0xffffffffu, tm1, 1));
        tm1 = fmaxf(tm1, __shfl_xor_sync(0xffffffffu, tm1, 2));

        float mn0 = fmaxf(m0, tm0), mn1 = fmaxf(m1, tm1);
        float a0 = exp2f(m0 - mn0), a1 = exp2f(m1 - mn1);
        m0 = mn0; m1 = mn1;

        // ---- p = exp2(s - m), partial sums + end buckets
        float ps0 = 0.f, ps1 = 0.f, tl0 = 0.f, tl1 = 0.f, th0 = 0.f, th1 = 0.f;
        #pragma unroll
        for (int nt = 0; nt < 8; nt++) {
            int kc0 = k0 + nt * 8 + 2 * tig;
            #pragma unroll
            for (int e = 0; e < 4; e++) {
                int kcol = kc0 + (e & 1);
                float p = exp2f(sa[nt][e] - ((e < 2) ? mn0 : mn1));
                sa[nt][e] = p;
                int d = kcol - ((e < 2) ? qrow0 : qrow1);
                if (e < 2) {
                    ps0 += p;
                    if (d <= -16) tl0 += p; else if (d >= 16) th0 += p;
                } else {
                    ps1 += p;
                    if (d <= -16) tl1 += p; else if (d >= 16) th1 += p;
                }
            }
        }
        ps0 += __shfl_xor_sync(0xffffffffu, ps0, 1); ps0 += __shfl_xor_sync(0xffffffffu, ps0, 2);
        ps1 += __shfl_xor_sync(0xffffffffu, ps1, 1); ps1 += __shfl_xor_sync(0xffffffffu, ps1, 2);
        tl0 += __shfl_xor_sync(0xffffffffu, tl0, 1); tl0 += __shfl_xor_sync(0xffffffffu, tl0, 2);
        tl1 += __shfl_xor_sync(0xffffffffu, tl1, 1); tl1 += __shfl_xor_sync(0xffffffffu, tl1, 2);
        th0 += __shfl_xor_sync(0xffffffffu, th0, 1); th0 += __shfl_xor_sync(0xffffffffu, th0, 2);
        th1 += __shfl_xor_sync(0xffffffffu, th1, 1); th1 += __shfl_xor_sync(0xffffffffu, th1, 2);

        l0 = l0 * a0 + ps0;  l1 = l1 * a1 + ps1;
        eL0 = eL0 * a0 + tl0; eL1 = eL1 * a1 + tl1;
        eH0 = eH0 * a0 + th0; eH1 = eH1 * a1 + th1;

        // ---- rescale O, stage P (per-warp private band), accumulate P V
        #pragma unroll
        for (int nt = 0; nt < 8; nt++) {
            oa[nt][0] *= a0; oa[nt][1] *= a0;
            oa[nt][2] *= a1; oa[nt][3] *= a1;
            *reinterpret_cast<float2*>(&Ps[(wq + gid) * KS + nt * 8 + 2 * tig]) =
                make_float2(sa[nt][0], sa[nt][1]);
            *reinterpret_cast<float2*>(&Ps[(wq + gid + 8) * KS + nt * 8 + 2 * tig]) =
                make_float2(sa[nt][2], sa[nt][3]);
        }
        __syncwarp();

        const float* Vb = Vs + buf * TILE;
        #pragma unroll
        for (int kc = 0; kc < 8; kc++) {
            uint32_t p0 = f2tf(Ps[(wq + gid)     * KS + kc * 8 + tig]);
            uint32_t p1 = f2tf(Ps[(wq + gid + 8) * KS + kc * 8 + tig]);
            uint32_t p2 = f2tf(Ps[(wq + gid)     * KS + kc * 8 + tig + 4]);
            uint32_t p3 = f2tf(Ps[(wq + gid + 8) * KS + kc * 8 + tig + 4]);
            #pragma unroll
            for (int nt = 0; nt < 8; nt++) {
                uint32_t b0 = f2tf(Vb[(kc * 8 + tig)     * KS + nt * 8 + gid]);
                uint32_t b1 = f2tf(Vb[(kc * 8 + tig + 4) * KS + nt * 8 + gid]);
                mma8(oa[nt], p0, p1, p2, p3, b0, b1);
            }
        }
        __syncthreads();
    }

    // ---- epilogue ----
    const int b = bh >> 4, h = bh & 15;
    float il0 = 1.f / l0, il1 = 1.f / l1;

    if (tig == 0) {
        MR[wq + gid] = m0;     IL[wq + gid] = il0;
        MR[wq + gid + 8] = m1; IL[wq + gid + 8] = il1;
        SQ[(wq + gid) * NREL + 0]      = eL0 * il0;
        SQ[(wq + gid) * NREL + 32]     = eH0 * il0;
        SQ[(wq + gid + 8) * NREL + 0]  = eL1 * il1;
        SQ[(wq + gid + 8) * NREL + 32] = eH1 * il1;
    }
    // Ev -> Ps (main loop's final __syncthreads freed Ps)
    for (int i = tid; i < NREL * 16; i += 128) {
        int row = i >> 4, c = i & 15;
        *reinterpret_cast<float4*>(&Ps[row * KS + 4 * c]) =
            reinterpret_cast<const float4*>(Ev)[i];
    }
    __syncthreads();    // MR/IL/ends + Ev visible

    // mid buckets -> normalized pe in SQ
    for (int i = tid; i < 64 * 31; i += 128) {
        int row = i / 31, r = i % 31 + 1;
        SQ[row * NREL + r] = exp2f(SMID[row * NREL + r] - MR[row]) * IL[row];
    }
    __syncthreads();    // pe fully in SQ

    // normalize O, add pe @ Ev, store ctx (merged heads)
    #pragma unroll
    for (int nt = 0; nt < 8; nt++) {
        oa[nt][0] *= il0; oa[nt][1] *= il0;
        oa[nt][2] *= il1; oa[nt][3] *= il1;
    }
    for (int r = 0; r < NREL; r++) {
        float pr0 = SQ[(wq + gid) * NREL + r];
        float pr1 = SQ[(wq + gid + 8) * NREL + r];
        #pragma unroll
        for (int nt = 0; nt < 8; nt++) {
            float2 ev = *reinterpret_cast<const float2*>(&Ps[r * KS + nt * 8 + 2 * tig]);
            oa[nt][0] += pr0 * ev.x; oa[nt][1] += pr0 * ev.y;
            oa[nt][2] += pr1 * ev.x; oa[nt][3] += pr1 * ev.y;
        }
    }
    #pragma unroll
    for (int nt = 0; nt < 8; nt++) {
        int col = h * HD + nt * 8 + 2 * tig;
        *reinterpret_cast<float2*>(&g_ctx[(size_t)(b * SEQ + qrow0) * DM + col]) =
            make_float2(oa[nt][0], oa[nt][1]);
        *reinterpret_cast<float2*>(&g_ctx[(size_t)(b * SEQ + qrow1) * DM + col]) =
            make_float2(oa[nt][2], oa[nt][3]);
    }
}

// ---------------- launch ------------------------------------------------------
extern "C" void kernel_launch(void* const* d_in, const int* in_sizes, int n_in,
                              void* d_out, int out_size)
{
    const float* queries = (const float*)d_in[0];
    const float* keys    = (const float*)d_in[1];
    const float* values  = (const float*)d_in[2];
    const int*   valid   = (const int*)  d_in[3];
    const float* Wq      = (const float*)d_in[4];
    const float* Wk      = (const float*)d_in[5];
    const float* Wv      = (const float*)d_in[6];
    const float* Wo      = (const float*)d_in[7];
    const float* Ek      = (const float*)d_in[8];
    const float* Ev      = (const float*)d_in[9];
    float* out = (float*)d_out;

    float *Qp, *Kp, *Vp, *Cp;
    cudaGetSymbolAddress((void**)&Qp, g_Q);
    cudaGetSymbolAddress((void**)&Kp, g_K);
    cudaGetSymbolAddress((void**)&Vp, g_V);
    cudaGetSymbolAddress((void**)&Cp, g_ctx);

    const int M = BATCH * SEQ;  // 4096

    const int smBig   = 2 * (128 * 36 + 128 * 36) * sizeof(float);   // 73728
    const int smFlash = (2 * 64 * 68 + 2 * 64 * 68 + 64 * 68
                         + 64 * NREL + 64 * NREL + 128) * sizeof(float); // 104448

    cudaFuncSetAttribute(gemm_big<true>,
        cudaFuncAttributeMaxDynamicSharedMemorySize, smBig);
    cudaFuncSetAttribute(gemm_big<false>,
        cudaFuncAttributeMaxDynamicSharedMemorySize, smBig);
    cudaFuncSetAttribute(flash_kernel,
        cudaFuncAttributeMaxDynamicSharedMemorySize, smFlash);

    // 1) Q/K/V projections in one launch (grid.z selects), head-split epilogue
    Proj3Args pa;
    pa.A[0] = queries; pa.A[1] = keys; pa.A[2] = values;
    pa.B[0] = Wq;      pa.B[1] = Wk;   pa.B[2] = Wv;
    pa.C[0] = Qp;      pa.C[1] = Kp;   pa.C[2] = Vp;
    gemm_big<true><<<dim3(DM / 128, M / 128, 3), 128, smBig>>>(pa, M, DM, DM);

    // 2) fully fused attention (qek + scores + softmax + PV + pe@Ev)
    flash_kernel<<<dim3(SEQ / 64, BH), 128, smFlash>>>(valid, Ek, Ev);

    // 3) out = ctx @ Wo^T
    Proj3Args po;
    po.A[0] = Cp; po.B[0] = Wo; po.C[0] = out;
    gemm_big<false><<<dim3(DM / 128, M / 128, 1), 128, smBig>>>(po, M, DM, DM);
}

// round 8
// speedup vs baseline: 5.8633x; 1.0736x over previous
#include <cuda_runtime.h>
#include <math.h>
#include <stdint.h>

#define BATCH 4
#define SEQ   1024
#define DM    1024
#define NH    16
#define HD    64
#define BH    (BATCH*NH)   // 64
#define NREL  33
#define NEGV  (-1e6f)
#define SCALE 0.1803368801111243f   // (1/sqrt(64)) * log2(e)

// ---------------- scratch (device globals: allocation is forbidden) ----------
__device__ float g_Q[BH*SEQ*HD];                 // [bh][s][d]  (tf32-rounded)
__device__ float g_K[BH*SEQ*HD];
__device__ float g_V[BH*SEQ*HD];
__device__ float g_ctx[BATCH*SEQ*DM];            // merged-head ctx (tf32-rounded)
__device__ float g_rin[3u*4096*1024];            // pre-rounded q,k,v inputs
__device__ float g_rw [4u*1024*1024];            // pre-rounded Wq,Wk,Wv,Wo

// ---------------- helpers ----------------------------------------------------
__device__ __forceinline__ uint32_t f2tf(float f) {
    uint32_t u;
    asm("cvt.rna.tf32.f32 %0, %1;" : "=r"(u) : "f"(f));
    return u;
}
__device__ __forceinline__ float f2tf_f(float f) {
    return __uint_as_float(f2tf(f));
}
__device__ __forceinline__ void mma8(float* c,
    uint32_t a0, uint32_t a1, uint32_t a2, uint32_t a3,
    uint32_t b0, uint32_t b1)
{
    asm volatile(
        "mma.sync.aligned.m16n8k8.row.col.f32.tf32.tf32.f32 "
        "{%0,%1,%2,%3}, {%4,%5,%6,%7}, {%8,%9}, {%0,%1,%2,%3};"
        : "+f"(c[0]), "+f"(c[1]), "+f"(c[2]), "+f"(c[3])
        : "r"(a0), "r"(a1), "r"(a2), "r"(a3), "r"(b0), "r"(b1));
}
__device__ __forceinline__ void cp16(void* smem_dst, const void* gmem_src) {
    uint32_t s = (uint32_t)__cvta_generic_to_shared(smem_dst);
    asm volatile("cp.async.cg.shared.global [%0], [%1], 16;\n"
                 :: "r"(s), "l"(gmem_src));
}
__device__ __forceinline__ void cp_commit() {
    asm volatile("cp.async.commit_group;\n");
}
template<int N>
__device__ __forceinline__ void cp_wait() {
    asm volatile("cp.async.wait_group %0;\n" :: "n"(N));
}
__device__ __forceinline__ uint32_t ldu(const float* p) {   // raw bits
    return __float_as_uint(*p);
}

// =============================================================================
// fp32 -> tf32-rounded fp32 copies (7 regions, one launch)
// =============================================================================
struct ConvArgs {
    const float* src[7];
    float* dst[7];
    int n4[7];
};
__global__ void __launch_bounds__(256) conv_kernel(ConvArgs a)
{
    int rg = blockIdx.y;
    const float4* s = reinterpret_cast<const float4*>(a.src[rg]);
    float4* d = reinterpret_cast<float4*>(a.dst[rg]);
    int n4 = a.n4[rg];
    for (int i = blockIdx.x * 256 + threadIdx.x; i < n4; i += gridDim.x * 256) {
        float4 v = s[i];
        v.x = f2tf_f(v.x); v.y = f2tf_f(v.y);
        v.z = f2tf_f(v.z); v.w = f2tf_f(v.w);
        d[i] = v;
    }
}

struct Proj3Args {
    const float* A[3];
    const float* B[3];
    float*       C[3];
};

// =============================================================================
// Big NT GEMM: C = A * B^T. Operands pre-rounded to tf32 -> NO cvt in hot loop.
// 128x128 tile, 128 threads, warp tile 64x64.
// PROJ3: z selects triple, split-heads epilogue with tf32-rounded store.
// =============================================================================
template<bool PROJ3>
__global__ void __launch_bounds__(128)
gemm_big(Proj3Args args, int M, int N, int K)
{
    constexpr int BM = 128, BN = 128, BK = 32, T = 128;
    constexpr int ASZ = BM * (BK + 4);

    extern __shared__ float dynsmem[];
    float (*As)[BM][BK + 4] = reinterpret_cast<float(*)[BM][BK + 4]>(dynsmem);
    float (*Bs)[BN][BK + 4] = reinterpret_cast<float(*)[BN][BK + 4]>(dynsmem + 2 * ASZ);

    int z = PROJ3 ? blockIdx.z : 0;
    const float* A = args.A[z];
    const float* B = args.B[z];
    float*       C = args.C[z];

    int m0  = blockIdx.y * BM, n0 = blockIdx.x * BN;
    int tid = threadIdx.x;
    int lane = tid & 31, warp = tid >> 5;
    int gid = lane >> 2, tig = lane & 3;
    int wm0 = (warp >> 1) * 64;
    int wn0 = (warp & 1) * 64;

    auto load_tiles = [&](int buf, int k0) {
        #pragma unroll
        for (int it = 0; it < 8; it++) {
            int idx = tid + it * T;
            int row = idx >> 3, kq = (idx & 7) << 2;
            cp16(&As[buf][row][kq], &A[(size_t)(m0 + row) * K + k0 + kq]);
        }
        #pragma unroll
        for (int it = 0; it < 8; it++) {
            int idx = tid + it * T;
            int row = idx >> 3, kq = (idx & 7) << 2;
            cp16(&Bs[buf][row][kq], &B[(size_t)(n0 + row) * K + k0 + kq]);
        }
        cp_commit();
    };

    float acc[4][8][4];
    #pragma unroll
    for (int i = 0; i < 4; i++)
        #pragma unroll
        for (int j = 0; j < 8; j++)
            #pragma unroll
            for (int l = 0; l < 4; l++) acc[i][j][l] = 0.f;

    const int KT = K / BK;
    load_tiles(0, 0);

    for (int kt = 0; kt < KT; kt++) {
        int buf = kt & 1;
        if (kt + 1 < KT) { load_tiles(buf ^ 1, (kt + 1) * BK); cp_wait<1>(); }
        else             { cp_wait<0>(); }
        __syncthreads();

        #pragma unroll
        for (int kc = 0; kc < BK / 8; kc++) {
            int kb = kc * 8;
            uint32_t af[4][4];
            #pragma unroll
            for (int mt = 0; mt < 4; mt++) {
                int r = wm0 + mt * 16 + gid;
                af[mt][0] = ldu(&As[buf][r    ][kb + tig]);
                af[mt][1] = ldu(&As[buf][r + 8][kb + tig]);
                af[mt][2] = ldu(&As[buf][r    ][kb + tig + 4]);
                af[mt][3] = ldu(&As[buf][r + 8][kb + tig + 4]);
            }
            uint32_t bf[8][2];
            #pragma unroll
            for (int nt = 0; nt < 8; nt++) {
                int cn = wn0 + nt * 8 + gid;
                bf[nt][0] = ldu(&Bs[buf][cn][kb + tig]);
                bf[nt][1] = ldu(&Bs[buf][cn][kb + tig + 4]);
            }
            #pragma unroll
            for (int mt = 0; mt < 4; mt++)
                #pragma unroll
                for (int nt = 0; nt < 8; nt++)
                    mma8(acc[mt][nt], af[mt][0], af[mt][1], af[mt][2], af[mt][3],
                         bf[nt][0], bf[nt][1]);
        }
        __syncthreads();
    }

    #pragma unroll
    for (int mt = 0; mt < 4; mt++) {
        #pragma unroll
        for (int nt = 0; nt < 8; nt++) {
            int r0 = m0 + wm0 + mt * 16 + gid;
            int c0 = n0 + wn0 + nt * 8 + 2 * tig;
            if (PROJ3) {   // split heads + tf32-round for downstream mma use
                float2 t0 = make_float2(f2tf_f(acc[mt][nt][0]), f2tf_f(acc[mt][nt][1]));
                float2 t1 = make_float2(f2tf_f(acc[mt][nt][2]), f2tf_f(acc[mt][nt][3]));
                int b = r0 >> 10, s = r0 & 1023, h = c0 >> 6, d = c0 & 63;
                *reinterpret_cast<float2*>(
                    &C[(size_t)((b * NH + h) * SEQ + s) * HD + d]) = t0;
                int b2 = (r0 + 8) >> 10, s2 = (r0 + 8) & 1023;
                *reinterpret_cast<float2*>(
                    &C[(size_t)((b2 * NH + h) * SEQ + s2) * HD + d]) = t1;
            } else {
                float2 t0 = make_float2(acc[mt][nt][0], acc[mt][nt][1]);
                float2 t1 = make_float2(acc[mt][nt][2], acc[mt][nt][3]);
                *reinterpret_cast<float2*>(&C[(size_t)r0 * N + c0]) = t0;
                *reinterpret_cast<float2*>(&C[(size_t)(r0 + 8) * N + c0]) = t1;
            }
        }
    }
}

// =============================================================================
// Fused flash attention. Q/K/V arrive tf32-pre-rounded -> raw-bit fragment
// loads; cvt only on computed P values and Ek.
// =============================================================================
__global__ void __launch_bounds__(128)
flash_kernel(const int* __restrict__ valid_lens,
             const float* __restrict__ Ek, const float* __restrict__ Ev)
{
    constexpr int KS = 68;
    constexpr int TILE = 64 * KS;

    extern __shared__ float sm[];
    float* Ks = sm;
    float* Vs = Ks + 2 * TILE;
    float* Ps = Vs + 2 * TILE;
    float* SQ = Ps + 64 * KS;
    float* SMID = SQ + 64 * NREL;
    float* MR = SMID + 64 * NREL;
    float* IL = MR + 64;

    const int q0 = blockIdx.x * 64;
    const int bh = blockIdx.y;
    const int vl  = valid_lens[bh >> 4];
    const int vlc = (vl + 63) & ~63;

    const int tid = threadIdx.x;
    const int lane = tid & 31, warp = tid >> 5;
    const int gid = lane >> 2, tig = lane & 3;
    const int wq = warp * 16;

    auto loadKV = [&](int buf, int k0) {
        const float* Kg = g_K + ((size_t)bh * SEQ + k0) * HD;
        const float* Vg = g_V + ((size_t)bh * SEQ + k0) * HD;
        #pragma unroll
        for (int it = 0; it < 8; it++) {
            int idx = tid + it * 128;
            int row = idx >> 4, c4 = (idx & 15) << 2;
            cp16(&Ks[buf * TILE + row * KS + c4], Kg + row * HD + c4);
        }
        #pragma unroll
        for (int it = 0; it < 8; it++) {
            int idx = tid + it * 128;
            int row = idx >> 4, c4 = (idx & 15) << 2;
            cp16(&Vs[buf * TILE + row * KS + c4], Vg + row * HD + c4);
        }
        cp_commit();
    };

    loadKV(0, 0);

    for (int i = tid; i < NREL * 16; i += 128) {
        int row = i >> 4, c = i & 15;
        *reinterpret_cast<float4*>(&Ps[row * KS + 4 * c]) =
            reinterpret_cast<const float4*>(Ek)[i];
    }

    uint32_t qa[8][4];
    {
        const float* Qg = g_Q + ((size_t)bh * SEQ + q0 + wq) * HD;
        #pragma unroll
        for (int kc = 0; kc < 8; kc++) {
            qa[kc][0] = ldu(&Qg[(size_t)gid       * HD + kc * 8 + tig]);
            qa[kc][1] = ldu(&Qg[(size_t)(gid + 8) * HD + kc * 8 + tig]);
            qa[kc][2] = ldu(&Qg[(size_t)gid       * HD + kc * 8 + tig + 4]);
            qa[kc][3] = ldu(&Qg[(size_t)(gid + 8) * HD + kc * 8 + tig + 4]);
        }
    }
    __syncthreads();

    {
        float sq[5][4];
        #pragma unroll
        for (int nt = 0; nt < 5; nt++)
            #pragma unroll
            for (int e = 0; e < 4; e++) sq[nt][e] = 0.f;
        #pragma unroll
        for (int kc = 0; kc < 8; kc++) {
            #pragma unroll
            for (int nt = 0; nt < 5; nt++) {
                uint32_t b0 = f2tf(Ps[(nt * 8 + gid) * KS + kc * 8 + tig]);
                uint32_t b1 = f2tf(Ps[(nt * 8 + gid) * KS + kc * 8 + tig + 4]);
                mma8(sq[nt], qa[kc][0], qa[kc][1], qa[kc][2], qa[kc][3], b0, b1);
            }
        }
        #pragma unroll
        for (int nt = 0; nt < 5; nt++) {
            #pragma unroll
            for (int e = 0; e < 4; e++) {
                int col = nt * 8 + 2 * tig + (e & 1);
                int row = wq + gid + ((e < 2) ? 0 : 8);
                if (col < NREL) SQ[row * NREL + col] = sq[nt][e];
            }
        }
    }
    for (int i = tid; i < 64 * NREL; i += 128) SMID[i] = NEGV;
    __syncthreads();

    const int qrow0 = q0 + wq + gid;
    const int qrow1 = qrow0 + 8;

    float oa[8][4];
    #pragma unroll
    for (int nt = 0; nt < 8; nt++)
        #pragma unroll
        for (int j = 0; j < 4; j++) oa[nt][j] = 0.f;

    float m0 = -1e30f, m1 = -1e30f;
    float l0 = 0.f, l1 = 0.f;
    float eL0 = 0.f, eL1 = 0.f, eH0 = 0.f, eH1 = 0.f;

    const int KT = vlc / 64;
    for (int t = 0; t < KT; t++) {
        int buf = t & 1;
        int k0 = t * 64;
        if (t + 1 < KT) { loadKV(buf ^ 1, k0 + 64); cp_wait<1>(); }
        else            { cp_wait<0>(); }
        __syncthreads();

        float sa[8][4];
        #pragma unroll
        for (int nt = 0; nt < 8; nt++)
            #pragma unroll
            for (int j = 0; j < 4; j++) sa[nt][j] = 0.f;

        const float* Kb = Ks + buf * TILE;
        #pragma unroll
        for (int kc = 0; kc < 8; kc++) {
            #pragma unroll
            for (int nt = 0; nt < 8; nt++) {
                uint32_t b0 = ldu(&Kb[(nt * 8 + gid) * KS + kc * 8 + tig]);
                uint32_t b1 = ldu(&Kb[(nt * 8 + gid) * KS + kc * 8 + tig + 4]);
                mma8(sa[nt], qa[kc][0], qa[kc][1], qa[kc][2], qa[kc][3], b0, b1);
            }
        }

        float tm0 = -1e30f, tm1 = -1e30f;
        #pragma unroll
        for (int nt = 0; nt < 8; nt++) {
            int kc0 = k0 + nt * 8 + 2 * tig;
            #pragma unroll
            for (int e = 0; e < 4; e++) {
                int kcol = kc0 + (e & 1);
                int qrow = (e < 2) ? qrow0 : qrow1;
                int rloc = wq + gid + ((e < 2) ? 0 : 8);
                int d = kcol - qrow;
                int bidx = min(16, max(-16, d)) + 16;
                float s = (sa[nt][e] + SQ[rloc * NREL + bidx]) * SCALE;
                if (kcol >= vl) s = NEGV;
                sa[nt][e] = s;
                if (d > -16 && d < 16) SMID[rloc * NREL + bidx] = s;
                if (e < 2) tm0 = fmaxf(tm0, s); else tm1 = fmaxf(tm1, s);
            }
        }
        tm0 = fmaxf(tm0, __shfl_xor_sync(0xffffffffu, tm0, 1));
        tm0 = fmaxf(tm0, __shfl_xor_sync(0xffffffffu, tm0, 2));
        tm1 = fmaxf(tm1, __shfl_xor_sync(0xffffffffu, tm1, 1));
        tm1 = fmaxf(tm1, __shfl_xor_sync(0xffffffffu, tm1, 2));

        float mn0 = fmaxf(m0, tm0), mn1 = fmaxf(m1, tm1);
        float a0 = exp2f(m0 - mn0), a1 = exp2f(m1 - mn1);
        m0 = mn0; m1 = mn1;

        float ps0 = 0.f, ps1 = 0.f, tl0 = 0.f, tl1 = 0.f, th0 = 0.f, th1 = 0.f;
        #pragma unroll
        for (int nt = 0; nt < 8; nt++) {
            int kc0 = k0 + nt * 8 + 2 * tig;
            #pragma unroll
            for (int e = 0; e < 4; e++) {
                int kcol = kc0 + (e & 1);
                float p = exp2f(sa[nt][e] - ((e < 2) ? mn0 : mn1));
                sa[nt][e] = p;
                int d = kcol - ((e < 2) ? qrow0 : qrow1);
                if (e < 2) {
                    ps0 += p;
                    if (d <= -16) tl0 += p; else if (d >= 16) th0 += p;
                } else {
                    ps1 += p;
                    if (d <= -16) tl1 += p; else if (d >= 16) th1 += p;
                }
            }
        }
        ps0 += __shfl_xor_sync(0xffffffffu, ps0, 1); ps0 += __shfl_xor_sync(0xffffffffu, ps0, 2);
        ps1 += __shfl_xor_sync(0xffffffffu, ps1, 1); ps1 += __shfl_xor_sync(0xffffffffu, ps1, 2);
        tl0 += __shfl_xor_sync(0xffffffffu, tl0, 1); tl0 += __shfl_xor_sync(0xffffffffu, tl0, 2);
        tl1 += __shfl_xor_sync(0xffffffffu, tl1, 1); tl1 += __shfl_xor_sync(0xffffffffu, tl1, 2);
        th0 += __shfl_xor_sync(0xffffffffu, th0, 1); th0 += __shfl_xor_sync(0xffffffffu, th0, 2);
        th1 += __shfl_xor_sync(0xffffffffu, th1, 1); th1 += __shfl_xor_sync(0xffffffffu, th1, 2);

        l0 = l0 * a0 + ps0;  l1 = l1 * a1 + ps1;
        eL0 = eL0 * a0 + tl0; eL1 = eL1 * a1 + tl1;
        eH0 = eH0 * a0 + th0; eH1 = eH1 * a1 + th1;

        #pragma unroll
        for (int nt = 0; nt < 8; nt++) {
            oa[nt][0] *= a0; oa[nt][1] *= a0;
            oa[nt][2] *= a1; oa[nt][3] *= a1;
            *reinterpret_cast<float2*>(&Ps[(wq + gid) * KS + nt * 8 + 2 * tig]) =
                make_float2(sa[nt][0], sa[nt][1]);
            *reinterpret_cast<float2*>(&Ps[(wq + gid + 8) * KS + nt * 8 + 2 * tig]) =
                make_float2(sa[nt][2], sa[nt][3]);
        }
        __syncwarp();

        const float* Vb = Vs + buf * TILE;
        #pragma unroll
        for (int kc = 0; kc < 8; kc++) {
            uint32_t p0 = f2tf(Ps[(wq + gid)     * KS + kc * 8 + tig]);
            uint32_t p1 = f2tf(Ps[(wq + gid + 8) * KS + kc * 8 + tig]);
            uint32_t p2 = f2tf(Ps[(wq + gid)     * KS + kc * 8 + tig + 4]);
            uint32_t p3 = f2tf(Ps[(wq + gid + 8) * KS + kc * 8 + tig + 4]);
            #pragma unroll
            for (int nt = 0; nt < 8; nt++) {
                uint32_t b0 = ldu(&Vb[(kc * 8 + tig)     * KS + nt * 8 + gid]);
                uint32_t b1 = ldu(&Vb[(kc * 8 + tig + 4) * KS + nt * 8 + gid]);
                mma8(oa[nt], p0, p1, p2, p3, b0, b1);
            }
        }
        __syncthreads();
    }

    const int b = bh >> 4, h = bh & 15;
    float il0 = 1.f / l0, il1 = 1.f / l1;

    if (tig == 0) {
        MR[wq + gid] = m0;     IL[wq + gid] = il0;
        MR[wq + gid + 8] = m1; IL[wq + gid + 8] = il1;
        SQ[(wq + gid) * NREL + 0]      = eL0 * il0;
        SQ[(wq + gid) * NREL + 32]     = eH0 * il0;
        SQ[(wq + gid + 8) * NREL + 0]  = eL1 * il1;
        SQ[(wq + gid + 8) * NREL + 32] = eH1 * il1;
    }
    for (int i = tid; i < NREL * 16; i += 128) {
        int row = i >> 4, c = i & 15;
        *reinterpret_cast<float4*>(&Ps[row * KS + 4 * c]) =
            reinterpret_cast<const float4*>(Ev)[i];
    }
    __syncthreads();

    for (int i = tid; i < 64 * 31; i += 128) {
        int row = i / 31, r = i % 31 + 1;
        SQ[row * NREL + r] = exp2f(SMID[row * NREL + r] - MR[row]) * IL[row];
    }
    __syncthreads();

    #pragma unroll
    for (int nt = 0; nt < 8; nt++) {
        oa[nt][0] *= il0; oa[nt][1] *= il0;
        oa[nt][2] *= il1; oa[nt][3] *= il1;
    }
    for (int r = 0; r < NREL; r++) {
        float pr0 = SQ[(wq + gid) * NREL + r];
        float pr1 = SQ[(wq + gid + 8) * NREL + r];
        #pragma unroll
        for (int nt = 0; nt < 8; nt++) {
            float2 ev = *reinterpret_cast<const float2*>(&Ps[r * KS + nt * 8 + 2 * tig]);
            oa[nt][0] += pr0 * ev.x; oa[nt][1] += pr0 * ev.y;
            oa[nt][2] += pr1 * ev.x; oa[nt][3] += pr1 * ev.y;
        }
    }
    // store ctx tf32-rounded (it is the A operand of the final GEMM)
    #pragma unroll
    for (int nt = 0; nt < 8; nt++) {
        int col = h * HD + nt * 8 + 2 * tig;
        *reinterpret_cast<float2*>(&g_ctx[(size_t)(b * SEQ + qrow0) * DM + col]) =
            make_float2(f2tf_f(oa[nt][0]), f2tf_f(oa[nt][1]));
        *reinterpret_cast<float2*>(&g_ctx[(size_t)(b * SEQ + qrow1) * DM + col]) =
            make_float2(f2tf_f(oa[nt][2]), f2tf_f(oa[nt][3]));
    }
}

// ---------------- launch ------------------------------------------------------
extern "C" void kernel_launch(void* const* d_in, const int* in_sizes, int n_in,
                              void* d_out, int out_size)
{
    const float* queries = (const float*)d_in[0];
    const float* keys    = (const float*)d_in[1];
    const float* values  = (const float*)d_in[2];
    const int*   valid   = (const int*)  d_in[3];
    const float* Wq      = (const float*)d_in[4];
    const float* Wk      = (const float*)d_in[5];
    const float* Wv      = (const float*)d_in[6];
    const float* Wo      = (const float*)d_in[7];
    const float* Ek      = (const float*)d_in[8];
    const float* Ev      = (const float*)d_in[9];
    float* out = (float*)d_out;

    float *Qp, *Kp, *Vp, *Cp, *rin, *rw;
    cudaGetSymbolAddress((void**)&Qp, g_Q);
    cudaGetSymbolAddress((void**)&Kp, g_K);
    cudaGetSymbolAddress((void**)&Vp, g_V);
    cudaGetSymbolAddress((void**)&Cp, g_ctx);
    cudaGetSymbolAddress((void**)&rin, g_rin);
    cudaGetSymbolAddress((void**)&rw, g_rw);

    const int M = BATCH * SEQ;          // 4096
    const size_t IN = (size_t)M * DM;   // 4M
    const size_t WN = (size_t)DM * DM;  // 1M

    const int smBig   = 2 * (128 * 36 + 128 * 36) * sizeof(float);   // 73728
    const int smFlash = (2 * 64 * 68 + 2 * 64 * 68 + 64 * 68
                         + 64 * NREL + 64 * NREL + 128) * sizeof(float);

    cudaFuncSetAttribute(gemm_big<true>,
        cudaFuncAttributeMaxDynamicSharedMemorySize, smBig);
    cudaFuncSetAttribute(gemm_big<false>,
        cudaFuncAttributeMaxDynamicSharedMemorySize, smBig);
    cudaFuncSetAttribute(flash_kernel,
        cudaFuncAttributeMaxDynamicSharedMemorySize, smFlash);

    // 1) pre-round inputs + weights to tf32 (7 regions, one launch)
    ConvArgs ca;
    ca.src[0] = queries; ca.src[1] = keys; ca.src[2] = values;
    ca.src[3] = Wq; ca.src[4] = Wk; ca.src[5] = Wv; ca.src[6] = Wo;
    for (int i = 0; i < 3; i++) { ca.dst[i] = rin + i * IN; ca.n4[i] = (int)(IN / 4); }
    for (int i = 0; i < 4; i++) { ca.dst[3 + i] = rw + i * WN; ca.n4[3 + i] = (int)(WN / 4); }
    conv_kernel<<<dim3(256, 7), 256>>>(ca);

    // 2) Q/K/V projections (cvt-free hot loop), head-split + tf32-round store
    Proj3Args pa;
    pa.A[0] = rin;          pa.A[1] = rin + IN;     pa.A[2] = rin + 2 * IN;
    pa.B[0] = rw;           pa.B[1] = rw + WN;      pa.B[2] = rw + 2 * WN;
    pa.C[0] = Qp;           pa.C[1] = Kp;           pa.C[2] = Vp;
    gemm_big<true><<<dim3(DM / 128, M / 128, 3), 128, smBig>>>(pa, M, DM, DM);

    // 3) fused attention (cvt-free Q/K/V fragment loads)
    flash_kernel<<<dim3(SEQ / 64, BH), 128, smFlash>>>(valid, Ek, Ev);

    // 4) out = ctx @ Wo^T (both operands pre-rounded)
    Proj3Args po;
    po.A[0] = Cp; po.B[0] = rw + 3 * WN; po.C[0] = out;
    po.A[1] = po.A[2] = Cp; po.B[1] = po.B[2] = rw; po.C[1] = po.C[2] = out;
    gemm_big<false><<<dim3(DM / 128, M / 128, 1), 128, smBig>>>(po, M, DM, DM);
}

// round 9
// speedup vs baseline: 6.1592x; 1.0505x over previous
#include <cuda_runtime.h>
#include <math.h>
#include <stdint.h>

#define BATCH 4
#define SEQ   1024
#define DM    1024
#define NH    16
#define HD    64
#define BH    (BATCH*NH)   // 64
#define NREL  33
#define NEGV  (-1e6f)
#define SCALE 0.1803368801111243f   // (1/sqrt(64)) * log2(e)

// ---------------- scratch (device globals: allocation is forbidden) ----------
__device__ float g_Q[BH*SEQ*HD];                 // [bh][s][d]  (tf32-rounded)
__device__ float g_K[BH*SEQ*HD];
__device__ float g_V[BH*SEQ*HD];
__device__ float g_ctx[BATCH*SEQ*DM];            // merged-head ctx (tf32-rounded)
__device__ float g_rin[3u*4096*1024];            // pre-rounded q,k,v inputs
__device__ float g_rw [4u*1024*1024];            // pre-rounded Wq,Wk,Wv,Wo

// ---------------- helpers ----------------------------------------------------
__device__ __forceinline__ uint32_t f2tf(float f) {
    uint32_t u;
    asm("cvt.rna.tf32.f32 %0, %1;" : "=r"(u) : "f"(f));
    return u;
}
__device__ __forceinline__ float f2tf_f(float f) {
    return __uint_as_float(f2tf(f));
}
__device__ __forceinline__ void mma8(float* c,
    uint32_t a0, uint32_t a1, uint32_t a2, uint32_t a3,
    uint32_t b0, uint32_t b1)
{
    asm volatile(
        "mma.sync.aligned.m16n8k8.row.col.f32.tf32.tf32.f32 "
        "{%0,%1,%2,%3}, {%4,%5,%6,%7}, {%8,%9}, {%0,%1,%2,%3};"
        : "+f"(c[0]), "+f"(c[1]), "+f"(c[2]), "+f"(c[3])
        : "r"(a0), "r"(a1), "r"(a2), "r"(a3), "r"(b0), "r"(b1));
}
__device__ __forceinline__ void cp16(void* smem_dst, const void* gmem_src) {
    uint32_t s = (uint32_t)__cvta_generic_to_shared(smem_dst);
    asm volatile("cp.async.cg.shared.global [%0], [%1], 16;\n"
                 :: "r"(s), "l"(gmem_src));
}
__device__ __forceinline__ void cp_commit() {
    asm volatile("cp.async.commit_group;\n");
}
template<int N>
__device__ __forceinline__ void cp_wait() {
    asm volatile("cp.async.wait_group %0;\n" :: "n"(N));
}
__device__ __forceinline__ uint32_t ldu(const float* p) {   // raw bits
    return __float_as_uint(*p);
}

// =============================================================================
// fp32 -> tf32-rounded fp32 copies (7 regions, one launch)
// =============================================================================
struct ConvArgs {
    const float* src[7];
    float* dst[7];
    int n4[7];
};
__global__ void __launch_bounds__(256) conv_kernel(ConvArgs a)
{
    int rg = blockIdx.y;
    const float4* s = reinterpret_cast<const float4*>(a.src[rg]);
    float4* d = reinterpret_cast<float4*>(a.dst[rg]);
    int n4 = a.n4[rg];
    for (int i = blockIdx.x * 256 + threadIdx.x; i < n4; i += gridDim.x * 256) {
        float4 v = s[i];
        v.x = f2tf_f(v.x); v.y = f2tf_f(v.y);
        v.z = f2tf_f(v.z); v.w = f2tf_f(v.w);
        d[i] = v;
    }
}

struct Proj3Args {
    const float* A[3];
    const float* B[3];
    float*       C[3];
};

// =============================================================================
// Big NT GEMM: C = A * B^T. Operands pre-rounded to tf32 -> NO cvt in hot loop.
// 128x128 tile, 128 threads, warp tile 64x64.
// __launch_bounds__(128, 3): cap regs at 170 so THREE CTAs fit per SM
// (3*128*170 = 65280 <= 64K regs; smem 3*73728 = 221184 <= 228KB carveout).
// PROJ3: z selects triple, split-heads epilogue with tf32-rounded store.
// =============================================================================
template<bool PROJ3>
__global__ void __launch_bounds__(128, 3)
gemm_big(Proj3Args args, int M, int N, int K)
{
    constexpr int BM = 128, BN = 128, BK = 32, T = 128;
    constexpr int ASZ = BM * (BK + 4);

    extern __shared__ float dynsmem[];
    float (*As)[BM][BK + 4] = reinterpret_cast<float(*)[BM][BK + 4]>(dynsmem);
    float (*Bs)[BN][BK + 4] = reinterpret_cast<float(*)[BN][BK + 4]>(dynsmem + 2 * ASZ);

    int z = PROJ3 ? blockIdx.z : 0;
    const float* A = args.A[z];
    const float* B = args.B[z];
    float*       C = args.C[z];

    int m0  = blockIdx.y * BM, n0 = blockIdx.x * BN;
    int tid = threadIdx.x;
    int lane = tid & 31, warp = tid >> 5;
    int gid = lane >> 2, tig = lane & 3;
    int wm0 = (warp >> 1) * 64;
    int wn0 = (warp & 1) * 64;

    auto load_tiles = [&](int buf, int k0) {
        #pragma unroll
        for (int it = 0; it < 8; it++) {
            int idx = tid + it * T;
            int row = idx >> 3, kq = (idx & 7) << 2;
            cp16(&As[buf][row][kq], &A[(size_t)(m0 + row) * K + k0 + kq]);
        }
        #pragma unroll
        for (int it = 0; it < 8; it++) {
            int idx = tid + it * T;
            int row = idx >> 3, kq = (idx & 7) << 2;
            cp16(&Bs[buf][row][kq], &B[(size_t)(n0 + row) * K + k0 + kq]);
        }
        cp_commit();
    };

    float acc[4][8][4];
    #pragma unroll
    for (int i = 0; i < 4; i++)
        #pragma unroll
        for (int j = 0; j < 8; j++)
            #pragma unroll
            for (int l = 0; l < 4; l++) acc[i][j][l] = 0.f;

    const int KT = K / BK;
    load_tiles(0, 0);

    for (int kt = 0; kt < KT; kt++) {
        int buf = kt & 1;
        if (kt + 1 < KT) { load_tiles(buf ^ 1, (kt + 1) * BK); cp_wait<1>(); }
        else             { cp_wait<0>(); }
        __syncthreads();

        #pragma unroll
        for (int kc = 0; kc < BK / 8; kc++) {
            int kb = kc * 8;
            uint32_t af[4][4];
            #pragma unroll
            for (int mt = 0; mt < 4; mt++) {
                int r = wm0 + mt * 16 + gid;
                af[mt][0] = ldu(&As[buf][r    ][kb + tig]);
                af[mt][1] = ldu(&As[buf][r + 8][kb + tig]);
                af[mt][2] = ldu(&As[buf][r    ][kb + tig + 4]);
                af[mt][3] = ldu(&As[buf][r + 8][kb + tig + 4]);
            }
            uint32_t bf[8][2];
            #pragma unroll
            for (int nt = 0; nt < 8; nt++) {
                int cn = wn0 + nt * 8 + gid;
                bf[nt][0] = ldu(&Bs[buf][cn][kb + tig]);
                bf[nt][1] = ldu(&Bs[buf][cn][kb + tig + 4]);
            }
            #pragma unroll
            for (int mt = 0; mt < 4; mt++)
                #pragma unroll
                for (int nt = 0; nt < 8; nt++)
                    mma8(acc[mt][nt], af[mt][0], af[mt][1], af[mt][2], af[mt][3],
                         bf[nt][0], bf[nt][1]);
        }
        __syncthreads();
    }

    #pragma unroll
    for (int mt = 0; mt < 4; mt++) {
        #pragma unroll
        for (int nt = 0; nt < 8; nt++) {
            int r0 = m0 + wm0 + mt * 16 + gid;
            int c0 = n0 + wn0 + nt * 8 + 2 * tig;
            if (PROJ3) {   // split heads + tf32-round for downstream mma use
                float2 t0 = make_float2(f2tf_f(acc[mt][nt][0]), f2tf_f(acc[mt][nt][1]));
                float2 t1 = make_float2(f2tf_f(acc[mt][nt][2]), f2tf_f(acc[mt][nt][3]));
                int b = r0 >> 10, s = r0 & 1023, h = c0 >> 6, d = c0 & 63;
                *reinterpret_cast<float2*>(
                    &C[(size_t)((b * NH + h) * SEQ + s) * HD + d]) = t0;
                int b2 = (r0 + 8) >> 10, s2 = (r0 + 8) & 1023;
                *reinterpret_cast<float2*>(
                    &C[(size_t)((b2 * NH + h) * SEQ + s2) * HD + d]) = t1;
            } else {
                float2 t0 = make_float2(acc[mt][nt][0], acc[mt][nt][1]);
                float2 t1 = make_float2(acc[mt][nt][2], acc[mt][nt][3]);
                *reinterpret_cast<float2*>(&C[(size_t)r0 * N + c0]) = t0;
                *reinterpret_cast<float2*>(&C[(size_t)(r0 + 8) * N + c0]) = t1;
            }
        }
    }
}

// =============================================================================
// Fused flash attention. Q/K/V arrive tf32-pre-rounded -> raw-bit fragment
// loads; cvt only on computed P values and Ek.
// =============================================================================
__global__ void __launch_bounds__(128)
flash_kernel(const int* __restrict__ valid_lens,
             const float* __restrict__ Ek, const float* __restrict__ Ev)
{
    constexpr int KS = 68;
    constexpr int TILE = 64 * KS;

    extern __shared__ float sm[];
    float* Ks = sm;
    float* Vs = Ks + 2 * TILE;
    float* Ps = Vs + 2 * TILE;
    float* SQ = Ps + 64 * KS;
    float* SMID = SQ + 64 * NREL;
    float* MR = SMID + 64 * NREL;
    float* IL = MR + 64;

    const int q0 = blockIdx.x * 64;
    const int bh = blockIdx.y;
    const int vl  = valid_lens[bh >> 4];
    const int vlc = (vl + 63) & ~63;

    const int tid = threadIdx.x;
    const int lane = tid & 31, warp = tid >> 5;
    const int gid = lane >> 2, tig = lane & 3;
    const int wq = warp * 16;

    auto loadKV = [&](int buf, int k0) {
        const float* Kg = g_K + ((size_t)bh * SEQ + k0) * HD;
        const float* Vg = g_V + ((size_t)bh * SEQ + k0) * HD;
        #pragma unroll
        for (int it = 0; it < 8; it++) {
            int idx = tid + it * 128;
            int row = idx >> 4, c4 = (idx & 15) << 2;
            cp16(&Ks[buf * TILE + row * KS + c4], Kg + row * HD + c4);
        }
        #pragma unroll
        for (int it = 0; it < 8; it++) {
            int idx = tid + it * 128;
            int row = idx >> 4, c4 = (idx & 15) << 2;
            cp16(&Vs[buf * TILE + row * KS + c4], Vg + row * HD + c4);
        }
        cp_commit();
    };

    loadKV(0, 0);

    for (int i = tid; i < NREL * 16; i += 128) {
        int row = i >> 4, c = i & 15;
        *reinterpret_cast<float4*>(&Ps[row * KS + 4 * c]) =
            reinterpret_cast<const float4*>(Ek)[i];
    }

    uint32_t qa[8][4];
    {
        const float* Qg = g_Q + ((size_t)bh * SEQ + q0 + wq) * HD;
        #pragma unroll
        for (int kc = 0; kc < 8; kc++) {
            qa[kc][0] = ldu(&Qg[(size_t)gid       * HD + kc * 8 + tig]);
            qa[kc][1] = ldu(&Qg[(size_t)(gid + 8) * HD + kc * 8 + tig]);
            qa[kc][2] = ldu(&Qg[(size_t)gid       * HD + kc * 8 + tig + 4]);
            qa[kc][3] = ldu(&Qg[(size_t)(gid + 8) * HD + kc * 8 + tig + 4]);
        }
    }
    __syncthreads();

    {
        float sq[5][4];
        #pragma unroll
        for (int nt = 0; nt < 5; nt++)
            #pragma unroll
            for (int e = 0; e < 4; e++) sq[nt][e] = 0.f;
        #pragma unroll
        for (int kc = 0; kc < 8; kc++) {
            #pragma unroll
            for (int nt = 0; nt < 5; nt++) {
                uint32_t b0 = f2tf(Ps[(nt * 8 + gid) * KS + kc * 8 + tig]);
                uint32_t b1 = f2tf(Ps[(nt * 8 + gid) * KS + kc * 8 + tig + 4]);
                mma8(sq[nt], qa[kc][0], qa[kc][1], qa[kc][2], qa[kc][3], b0, b1);
            }
        }
        #pragma unroll
        for (int nt = 0; nt < 5; nt++) {
            #pragma unroll
            for (int e = 0; e < 4; e++) {
                int col = nt * 8 + 2 * tig + (e & 1);
                int row = wq + gid + ((e < 2) ? 0 : 8);
                if (col < NREL) SQ[row * NREL + col] = sq[nt][e];
            }
        }
    }
    for (int i = tid; i < 64 * NREL; i += 128) SMID[i] = NEGV;
    __syncthreads();

    const int qrow0 = q0 + wq + gid;
    const int qrow1 = qrow0 + 8;

    float oa[8][4];
    #pragma unroll
    for (int nt = 0; nt < 8; nt++)
        #pragma unroll
        for (int j = 0; j < 4; j++) oa[nt][j] = 0.f;

    float m0 = -1e30f, m1 = -1e30f;
    float l0 = 0.f, l1 = 0.f;
    float eL0 = 0.f, eL1 = 0.f, eH0 = 0.f, eH1 = 0.f;

    const int KT = vlc / 64;
    for (int t = 0; t < KT; t++) {
        int buf = t & 1;
        int k0 = t * 64;
        if (t + 1 < KT) { loadKV(buf ^ 1, k0 + 64); cp_wait<1>(); }
        else            { cp_wait<0>(); }
        __syncthreads();

        float sa[8][4];
        #pragma unroll
        for (int nt = 0; nt < 8; nt++)
            #pragma unroll
            for (int j = 0; j < 4; j++) sa[nt][j] = 0.f;

        const float* Kb = Ks + buf * TILE;
        #pragma unroll
        for (int kc = 0; kc < 8; kc++) {
            #pragma unroll
            for (int nt = 0; nt < 8; nt++) {
                uint32_t b0 = ldu(&Kb[(nt * 8 + gid) * KS + kc * 8 + tig]);
                uint32_t b1 = ldu(&Kb[(nt * 8 + gid) * KS + kc * 8 + tig + 4]);
                mma8(sa[nt], qa[kc][0], qa[kc][1], qa[kc][2], qa[kc][3], b0, b1);
            }
        }

        float tm0 = -1e30f, tm1 = -1e30f;
        #pragma unroll
        for (int nt = 0; nt < 8; nt++) {
            int kc0 = k0 + nt * 8 + 2 * tig;
            #pragma unroll
            for (int e = 0; e < 4; e++) {
                int kcol = kc0 + (e & 1);
                int qrow = (e < 2) ? qrow0 : qrow1;
                int rloc = wq + gid + ((e < 2) ? 0 : 8);
                int d = kcol - qrow;
                int bidx = min(16, max(-16, d)) + 16;
                float s = (sa[nt][e] + SQ[rloc * NREL + bidx]) * SCALE;
                if (kcol >= vl) s = NEGV;
                sa[nt][e] = s;
                if (d > -16 && d < 16) SMID[rloc * NREL + bidx] = s;
                if (e < 2) tm0 = fmaxf(tm0, s); else tm1 = fmaxf(tm1, s);
            }
        }
        tm0 = fmaxf(tm0, __shfl_xor_sync(0xffffffffu, tm0, 1));
        tm0 = fmaxf(tm0, __shfl_xor_sync(0xffffffffu, tm0, 2));
        tm1 = fmaxf(tm1, __shfl_xor_sync(0xffffffffu, tm1, 1));
        tm1 = fmaxf(tm1, __shfl_xor_sync(0xffffffffu, tm1, 2));

        float mn0 = fmaxf(m0, tm0), mn1 = fmaxf(m1, tm1);
        float a0 = exp2f(m0 - mn0), a1 = exp2f(m1 - mn1);
        m0 = mn0; m1 = mn1;

        float ps0 = 0.f, ps1 = 0.f, tl0 = 0.f, tl1 = 0.f, th0 = 0.f, th1 = 0.f;
        #pragma unroll
        for (int nt = 0; nt < 8; nt++) {
            int kc0 = k0 + nt * 8 + 2 * tig;
            #pragma unroll
            for (int e = 0; e < 4; e++) {
                int kcol = kc0 + (e & 1);
                float p = exp2f(sa[nt][e] - ((e < 2) ? mn0 : mn1));
                sa[nt][e] = p;
                int d = kcol - ((e < 2) ? qrow0 : qrow1);
                if (e < 2) {
                    ps0 += p;
                    if (d <= -16) tl0 += p; else if (d >= 16) th0 += p;
                } else {
                    ps1 += p;
                    if (d <= -16) tl1 += p; else if (d >= 16) th1 += p;
                }
            }
        }
        ps0 += __shfl_xor_sync(0xffffffffu, ps0, 1); ps0 += __shfl_xor_sync(0xffffffffu, ps0, 2);
        ps1 += __shfl_xor_sync(0xffffffffu, ps1, 1); ps1 += __shfl_xor_sync(0xffffffffu, ps1, 2);
        tl0 += __shfl_xor_sync(0xffffffffu, tl0, 1); tl0 += __shfl_xor_sync(0xffffffffu, tl0, 2);
        tl1 += __shfl_xor_sync(0xffffffffu, tl1, 1); tl1 += __shfl_xor_sync(0xffffffffu, tl1, 2);
        th0 += __shfl_xor_sync(0xffffffffu, th0, 1); th0 += __shfl_xor_sync(0xffffffffu, th0, 2);
        th1 += __shfl_xor_sync(0xffffffffu, th1, 1); th1 += __shfl_xor_sync(0xffffffffu, th1, 2);

        l0 = l0 * a0 + ps0;  l1 = l1 * a1 + ps1;
        eL0 = eL0 * a0 + tl0; eL1 = eL1 * a1 + tl1;
        eH0 = eH0 * a0 + th0; eH1 = eH1 * a1 + th1;

        #pragma unroll
        for (int nt = 0; nt < 8; nt++) {
            oa[nt][0] *= a0; oa[nt][1] *= a0;
            oa[nt][2] *= a1; oa[nt][3] *= a1;
            *reinterpret_cast<float2*>(&Ps[(wq + gid) * KS + nt * 8 + 2 * tig]) =
                make_float2(sa[nt][0], sa[nt][1]);
            *reinterpret_cast<float2*>(&Ps[(wq + gid + 8) * KS + nt * 8 + 2 * tig]) =
                make_float2(sa[nt][2], sa[nt][3]);
        }
        __syncwarp();

        const float* Vb = Vs + buf * TILE;
        #pragma unroll
        for (int kc = 0; kc < 8; kc++) {
            uint32_t p0 = f2tf(Ps[(wq + gid)     * KS + kc * 8 + tig]);
            uint32_t p1 = f2tf(Ps[(wq + gid + 8) * KS + kc * 8 + tig]);
            uint32_t p2 = f2tf(Ps[(wq + gid)     * KS + kc * 8 + tig + 4]);
            uint32_t p3 = f2tf(Ps[(wq + gid + 8) * KS + kc * 8 + tig + 4]);
            #pragma unroll
            for (int nt = 0; nt < 8; nt++) {
                uint32_t b0 = ldu(&Vb[(kc * 8 + tig)     * KS + nt * 8 + gid]);
                uint32_t b1 = ldu(&Vb[(kc * 8 + tig + 4) * KS + nt * 8 + gid]);
                mma8(oa[nt], p0, p1, p2, p3, b0, b1);
            }
        }
        __syncthreads();
    }

    const int b = bh >> 4, h = bh & 15;
    float il0 = 1.f / l0, il1 = 1.f / l1;

    if (tig == 0) {
        MR[wq + gid] = m0;     IL[wq + gid] = il0;
        MR[wq + gid + 8] = m1; IL[wq + gid + 8] = il1;
        SQ[(wq + gid) * NREL + 0]      = eL0 * il0;
        SQ[(wq + gid) * NREL + 32]     = eH0 * il0;
        SQ[(wq + gid + 8) * NREL + 0]  = eL1 * il1;
        SQ[(wq + gid + 8) * NREL + 32] = eH1 * il1;
    }
    for (int i = tid; i < NREL * 16; i += 128) {
        int row = i >> 4, c = i & 15;
        *reinterpret_cast<float4*>(&Ps[row * KS + 4 * c]) =
            reinterpret_cast<const float4*>(Ev)[i];
    }
    __syncthreads();

    for (int i = tid; i < 64 * 31; i += 128) {
        int row = i / 31, r = i % 31 + 1;
        SQ[row * NREL + r] = exp2f(SMID[row * NREL + r] - MR[row]) * IL[row];
    }
    __syncthreads();

    #pragma unroll
    for (int nt = 0; nt < 8; nt++) {
        oa[nt][0] *= il0; oa[nt][1] *= il0;
        oa[nt][2] *= il1; oa[nt][3] *= il1;
    }
    for (int r = 0; r < NREL; r++) {
        float pr0 = SQ[(wq + gid) * NREL + r];
        float pr1 = SQ[(wq + gid + 8) * NREL + r];
        #pragma unroll
        for (int nt = 0; nt < 8; nt++) {
            float2 ev = *reinterpret_cast<const float2*>(&Ps[r * KS + nt * 8 + 2 * tig]);
            oa[nt][0] += pr0 * ev.x; oa[nt][1] += pr0 * ev.y;
            oa[nt][2] += pr1 * ev.x; oa[nt][3] += pr1 * ev.y;
        }
    }
    // store ctx tf32-rounded (it is the A operand of the final GEMM)
    #pragma unroll
    for (int nt = 0; nt < 8; nt++) {
        int col = h * HD + nt * 8 + 2 * tig;
        *reinterpret_cast<float2*>(&g_ctx[(size_t)(b * SEQ + qrow0) * DM + col]) =
            make_float2(f2tf_f(oa[nt][0]), f2tf_f(oa[nt][1]));
        *reinterpret_cast<float2*>(&g_ctx[(size_t)(b * SEQ + qrow1) * DM + col]) =
            make_float2(f2tf_f(oa[nt][2]), f2tf_f(oa[nt][3]));
    }
}

// ---------------- launch ------------------------------------------------------
extern "C" void kernel_launch(void* const* d_in, const int* in_sizes, int n_in,
                              void* d_out, int out_size)
{
    const float* queries = (const float*)d_in[0];
    const float* keys    = (const float*)d_in[1];
    const float* values  = (const float*)d_in[2];
    const int*   valid   = (const int*)  d_in[3];
    const float* Wq      = (const float*)d_in[4];
    const float* Wk      = (const float*)d_in[5];
    const float* Wv      = (const float*)d_in[6];
    const float* Wo      = (const float*)d_in[7];
    const float* Ek      = (const float*)d_in[8];
    const float* Ev      = (const float*)d_in[9];
    float* out = (float*)d_out;

    float *Qp, *Kp, *Vp, *Cp, *rin, *rw;
    cudaGetSymbolAddress((void**)&Qp, g_Q);
    cudaGetSymbolAddress((void**)&Kp, g_K);
    cudaGetSymbolAddress((void**)&Vp, g_V);
    cudaGetSymbolAddress((void**)&Cp, g_ctx);
    cudaGetSymbolAddress((void**)&rin, g_rin);
    cudaGetSymbolAddress((void**)&rw, g_rw);

    const int M = BATCH * SEQ;          // 4096
    const size_t IN = (size_t)M * DM;   // 4M
    const size_t WN = (size_t)DM * DM;  // 1M

    const int smBig   = 2 * (128 * 36 + 128 * 36) * sizeof(float);   // 73728
    const int smFlash = (2 * 64 * 68 + 2 * 64 * 68 + 64 * 68
                         + 64 * NREL + 64 * NREL + 128) * sizeof(float);

    cudaFuncSetAttribute(gemm_big<true>,
        cudaFuncAttributeMaxDynamicSharedMemorySize, smBig);
    cudaFuncSetAttribute(gemm_big<false>,
        cudaFuncAttributeMaxDynamicSharedMemorySize, smBig);
    cudaFuncSetAttribute(flash_kernel,
        cudaFuncAttributeMaxDynamicSharedMemorySize, smFlash);

    // 1) pre-round inputs + weights to tf32 (7 regions, one launch)
    ConvArgs ca;
    ca.src[0] = queries; ca.src[1] = keys; ca.src[2] = values;
    ca.src[3] = Wq; ca.src[4] = Wk; ca.src[5] = Wv; ca.src[6] = Wo;
    for (int i = 0; i < 3; i++) { ca.dst[i] = rin + i * IN; ca.n4[i] = (int)(IN / 4); }
    for (int i = 0; i < 4; i++) { ca.dst[3 + i] = rw + i * WN; ca.n4[3 + i] = (int)(WN / 4); }
    conv_kernel<<<dim3(256, 7), 256>>>(ca);

    // 2) Q/K/V projections (cvt-free hot loop), head-split + tf32-round store
    Proj3Args pa;
    pa.A[0] = rin;          pa.A[1] = rin + IN;     pa.A[2] = rin + 2 * IN;
    pa.B[0] = rw;           pa.B[1] = rw + WN;      pa.B[2] = rw + 2 * WN;
    pa.C[0] = Qp;           pa.C[1] = Kp;           pa.C[2] = Vp;
    gemm_big<true><<<dim3(DM / 128, M / 128, 3), 128, smBig>>>(pa, M, DM, DM);

    // 3) fused attention (cvt-free Q/K/V fragment loads)
    flash_kernel<<<dim3(SEQ / 64, BH), 128, smFlash>>>(valid, Ek, Ev);

    // 4) out = ctx @ Wo^T (both operands pre-rounded)
    Proj3Args po;
    po.A[0] = Cp; po.B[0] = rw + 3 * WN; po.C[0] = out;
    po.A[1] = po.A[2] = Cp; po.B[1] = po.B[2] = rw; po.C[1] = po.C[2] = out;
    gemm_big<false><<<dim3(DM / 128, M / 128, 1), 128, smBig>>>(po, M, DM, DM);
}

// round 10
// speedup vs baseline: 6.3020x; 1.0232x over previous
#include <cuda_runtime.h>
#include <math.h>
#include <stdint.h>

#define BATCH 4
#define SEQ   1024
#define DM    1024
#define NH    16
#define HD    64
#define BH    (BATCH*NH)   // 64
#define NREL  33
#define NEGV  (-1e6f)
#define SCALE 0.1803368801111243f   // (1/sqrt(64)) * log2(e)

// ---------------- scratch (device globals: allocation is forbidden) ----------
__device__ float g_Q[BH*SEQ*HD];                 // [bh][s][d]  (tf32-rounded)
__device__ float g_K[BH*SEQ*HD];
__device__ float g_V[BH*SEQ*HD];
__device__ float g_ctx[BATCH*SEQ*DM];            // merged-head ctx (tf32-rounded)
__device__ float g_rin[3u*4096*1024];            // pre-rounded q,k,v inputs
__device__ float g_rw [4u*1024*1024];            // pre-rounded Wq,Wk,Wv,Wo

// ---------------- helpers ----------------------------------------------------
__device__ __forceinline__ uint32_t f2tf(float f) {
    uint32_t u;
    asm("cvt.rna.tf32.f32 %0, %1;" : "=r"(u) : "f"(f));
    return u;
}
__device__ __forceinline__ float f2tf_f(float f) {
    return __uint_as_float(f2tf(f));
}
__device__ __forceinline__ void mma8(float* c,
    uint32_t a0, uint32_t a1, uint32_t a2, uint32_t a3,
    uint32_t b0, uint32_t b1)
{
    asm volatile(
        "mma.sync.aligned.m16n8k8.row.col.f32.tf32.tf32.f32 "
        "{%0,%1,%2,%3}, {%4,%5,%6,%7}, {%8,%9}, {%0,%1,%2,%3};"
        : "+f"(c[0]), "+f"(c[1]), "+f"(c[2]), "+f"(c[3])
        : "r"(a0), "r"(a1), "r"(a2), "r"(a3), "r"(b0), "r"(b1));
}
__device__ __forceinline__ void cp16(void* smem_dst, const void* gmem_src) {
    uint32_t s = (uint32_t)__cvta_generic_to_shared(smem_dst);
    asm volatile("cp.async.cg.shared.global [%0], [%1], 16;\n"
                 :: "r"(s), "l"(gmem_src));
}
__device__ __forceinline__ void cp_commit() {
    asm volatile("cp.async.commit_group;\n");
}
template<int N>
__device__ __forceinline__ void cp_wait() {
    asm volatile("cp.async.wait_group %0;\n" :: "n"(N));
}
__device__ __forceinline__ uint32_t ldu(const float* p) {   // raw bits
    return __float_as_uint(*p);
}

// =============================================================================
// fp32 -> tf32-rounded fp32 copies (7 regions, one launch)
// =============================================================================
struct ConvArgs {
    const float* src[7];
    float* dst[7];
    int n4[7];
};
__global__ void __launch_bounds__(256) conv_kernel(ConvArgs a)
{
    int rg = blockIdx.y;
    const float4* s = reinterpret_cast<const float4*>(a.src[rg]);
    float4* d = reinterpret_cast<float4*>(a.dst[rg]);
    int n4 = a.n4[rg];
    for (int i = blockIdx.x * 256 + threadIdx.x; i < n4; i += gridDim.x * 256) {
        float4 v = s[i];
        v.x = f2tf_f(v.x); v.y = f2tf_f(v.y);
        v.z = f2tf_f(v.z); v.w = f2tf_f(v.w);
        d[i] = v;
    }
}

struct Proj3Args {
    const float* A[3];
    const float* B[3];
    float*       C[3];
};

// =============================================================================
// Big NT GEMM: C = A * B^T. Pre-rounded operands -> cvt-free hot loop.
// BM=128, BN template (128 for proj3, 64 for out-proj), 128 threads,
// warp tile 64 x (BN/2). MAXB = min blocks/SM for launch_bounds.
// =============================================================================
template<bool PROJ3, int BN, int MAXB>
__global__ void __launch_bounds__(128, MAXB)
gemm_big(Proj3Args args, int M, int N, int K)
{
    constexpr int BM = 128, BK = 32, T = 128;
    constexpr int NT = BN / 16;               // n-tiles of 8 per warp
    constexpr int ASZ = BM * (BK + 4);

    extern __shared__ float dynsmem[];
    float (*As)[BM][BK + 4] = reinterpret_cast<float(*)[BM][BK + 4]>(dynsmem);
    float (*Bs)[BN][BK + 4] = reinterpret_cast<float(*)[BN][BK + 4]>(dynsmem + 2 * ASZ);

    int z = PROJ3 ? blockIdx.z : 0;
    const float* A = args.A[z];
    const float* B = args.B[z];
    float*       C = args.C[z];

    int m0  = blockIdx.y * BM, n0 = blockIdx.x * BN;
    int tid = threadIdx.x;
    int lane = tid & 31, warp = tid >> 5;
    int gid = lane >> 2, tig = lane & 3;
    int wm0 = (warp >> 1) * 64;
    int wn0 = (warp & 1) * (BN / 2);

    auto load_tiles = [&](int buf, int k0) {
        #pragma unroll
        for (int it = 0; it < 8; it++) {
            int idx = tid + it * T;
            int row = idx >> 3, kq = (idx & 7) << 2;
            cp16(&As[buf][row][kq], &A[(size_t)(m0 + row) * K + k0 + kq]);
        }
        #pragma unroll
        for (int it = 0; it < BN / 16; it++) {
            int idx = tid + it * T;
            int row = idx >> 3, kq = (idx & 7) << 2;
            cp16(&Bs[buf][row][kq], &B[(size_t)(n0 + row) * K + k0 + kq]);
        }
        cp_commit();
    };

    float acc[4][NT][4];
    #pragma unroll
    for (int i = 0; i < 4; i++)
        #pragma unroll
        for (int j = 0; j < NT; j++)
            #pragma unroll
            for (int l = 0; l < 4; l++) acc[i][j][l] = 0.f;

    const int KT = K / BK;
    load_tiles(0, 0);

    for (int kt = 0; kt < KT; kt++) {
        int buf = kt & 1;
        if (kt + 1 < KT) { load_tiles(buf ^ 1, (kt + 1) * BK); cp_wait<1>(); }
        else             { cp_wait<0>(); }
        __syncthreads();

        #pragma unroll
        for (int kc = 0; kc < BK / 8; kc++) {
            int kb = kc * 8;
            uint32_t af[4][4];
            #pragma unroll
            for (int mt = 0; mt < 4; mt++) {
                int r = wm0 + mt * 16 + gid;
                af[mt][0] = ldu(&As[buf][r    ][kb + tig]);
                af[mt][1] = ldu(&As[buf][r + 8][kb + tig]);
                af[mt][2] = ldu(&As[buf][r    ][kb + tig + 4]);
                af[mt][3] = ldu(&As[buf][r + 8][kb + tig + 4]);
            }
            uint32_t bf[NT][2];
            #pragma unroll
            for (int nt = 0; nt < NT; nt++) {
                int cn = wn0 + nt * 8 + gid;
                bf[nt][0] = ldu(&Bs[buf][cn][kb + tig]);
                bf[nt][1] = ldu(&Bs[buf][cn][kb + tig + 4]);
            }
            #pragma unroll
            for (int mt = 0; mt < 4; mt++)
                #pragma unroll
                for (int nt = 0; nt < NT; nt++)
                    mma8(acc[mt][nt], af[mt][0], af[mt][1], af[mt][2], af[mt][3],
                         bf[nt][0], bf[nt][1]);
        }
        __syncthreads();
    }

    #pragma unroll
    for (int mt = 0; mt < 4; mt++) {
        #pragma unroll
        for (int nt = 0; nt < NT; nt++) {
            int r0 = m0 + wm0 + mt * 16 + gid;
            int c0 = n0 + wn0 + nt * 8 + 2 * tig;
            if (PROJ3) {   // split heads + tf32-round for downstream mma use
                float2 t0 = make_float2(f2tf_f(acc[mt][nt][0]), f2tf_f(acc[mt][nt][1]));
                float2 t1 = make_float2(f2tf_f(acc[mt][nt][2]), f2tf_f(acc[mt][nt][3]));
                int b = r0 >> 10, s = r0 & 1023, h = c0 >> 6, d = c0 & 63;
                *reinterpret_cast<float2*>(
                    &C[(size_t)((b * NH + h) * SEQ + s) * HD + d]) = t0;
                int b2 = (r0 + 8) >> 10, s2 = (r0 + 8) & 1023;
                *reinterpret_cast<float2*>(
                    &C[(size_t)((b2 * NH + h) * SEQ + s2) * HD + d]) = t1;
            } else {
                float2 t0 = make_float2(acc[mt][nt][0], acc[mt][nt][1]);
                float2 t1 = make_float2(acc[mt][nt][2], acc[mt][nt][3]);
                *reinterpret_cast<float2*>(&C[(size_t)r0 * N + c0]) = t0;
                *reinterpret_cast<float2*>(&C[(size_t)(r0 + 8) * N + c0]) = t1;
            }
        }
    }
}

// =============================================================================
// Fused flash attention, shuffle-P version (no P staging buffer).
// smem: K double-buffered, V single-buffered (69.6 KB -> 3 CTAs/SM).
// P c-fragment -> a-fragment via warp shuffles (bit-identical values).
// =============================================================================
__global__ void __launch_bounds__(128, 3)
flash_kernel(const int* __restrict__ valid_lens,
             const float* __restrict__ Ek, const float* __restrict__ Ev)
{
    constexpr int KS = 68;
    constexpr int TILE = 64 * KS;   // 4352 floats

    extern __shared__ float sm[];
    float* Ks = sm;                 // [2][64][68]
    float* Vs = Ks + 2 * TILE;      // [64][68]  (also Ek/Ev staging)
    float* SQ = Vs + TILE;          // [64][33]  qek -> pe
    float* SMID = SQ + 64 * NREL;   // [64][33]  raw mid-band scores
    float* MR = SMID + 64 * NREL;   // [64]
    float* IL = MR + 64;            // [64]

    const int q0 = blockIdx.x * 64;
    const int bh = blockIdx.y;
    const int vl  = valid_lens[bh >> 4];
    const int vlc = (vl + 63) & ~63;

    const int tid = threadIdx.x;
    const int lane = tid & 31, warp = tid >> 5;
    const int gid = lane >> 2, tig = lane & 3;
    const int wq = warp * 16;

    auto loadK = [&](int buf, int k0) {
        const float* Kg = g_K + ((size_t)bh * SEQ + k0) * HD;
        #pragma unroll
        for (int it = 0; it < 8; it++) {
            int idx = tid + it * 128;
            int row = idx >> 4, c4 = (idx & 15) << 2;
            cp16(&Ks[buf * TILE + row * KS + c4], Kg + row * HD + c4);
        }
        cp_commit();
    };
    auto loadV = [&](int k0) {
        const float* Vg = g_V + ((size_t)bh * SEQ + k0) * HD;
        #pragma unroll
        for (int it = 0; it < 8; it++) {
            int idx = tid + it * 128;
            int row = idx >> 4, c4 = (idx & 15) << 2;
            cp16(&Vs[row * KS + c4], Vg + row * HD + c4);
        }
        cp_commit();
    };

    loadK(0, 0);                               // outstanding: [K0]

    // Ek -> Vs (free until V(0) load in iter 0)
    for (int i = tid; i < NREL * 16; i += 128) {
        int row = i >> 4, c = i & 15;
        *reinterpret_cast<float4*>(&Vs[row * KS + 4 * c]) =
            reinterpret_cast<const float4*>(Ek)[i];
    }

    // Q fragments resident for the whole kernel (pre-rounded in gmem)
    uint32_t qa[8][4];
    {
        const float* Qg = g_Q + ((size_t)bh * SEQ + q0 + wq) * HD;
        #pragma unroll
        for (int kc = 0; kc < 8; kc++) {
            qa[kc][0] = ldu(&Qg[(size_t)gid       * HD + kc * 8 + tig]);
            qa[kc][1] = ldu(&Qg[(size_t)(gid + 8) * HD + kc * 8 + tig]);
            qa[kc][2] = ldu(&Qg[(size_t)gid       * HD + kc * 8 + tig + 4]);
            qa[kc][3] = ldu(&Qg[(size_t)(gid + 8) * HD + kc * 8 + tig + 4]);
        }
    }
    __syncthreads();    // Ek visible

    // qek: SQ[row][r] = Q[row] . Ek[r]
    {
        float sq[5][4];
        #pragma unroll
        for (int nt = 0; nt < 5; nt++)
            #pragma unroll
            for (int e = 0; e < 4; e++) sq[nt][e] = 0.f;
        #pragma unroll
        for (int kc = 0; kc < 8; kc++) {
            #pragma unroll
            for (int nt = 0; nt < 5; nt++) {
                uint32_t b0 = f2tf(Vs[(nt * 8 + gid) * KS + kc * 8 + tig]);
                uint32_t b1 = f2tf(Vs[(nt * 8 + gid) * KS + kc * 8 + tig + 4]);
                mma8(sq[nt], qa[kc][0], qa[kc][1], qa[kc][2], qa[kc][3], b0, b1);
            }
        }
        #pragma unroll
        for (int nt = 0; nt < 5; nt++) {
            #pragma unroll
            for (int e = 0; e < 4; e++) {
                int col = nt * 8 + 2 * tig + (e & 1);
                int row = wq + gid + ((e < 2) ? 0 : 8);
                if (col < NREL) SQ[row * NREL + col] = sq[nt][e];
            }
        }
    }
    for (int i = tid; i < 64 * NREL; i += 128) SMID[i] = NEGV;
    __syncthreads();    // SQ/SMID ready; Vs free for V tiles

    const int qrow0 = q0 + wq + gid;
    const int qrow1 = qrow0 + 8;

    float oa[8][4];
    #pragma unroll
    for (int nt = 0; nt < 8; nt++)
        #pragma unroll
        for (int j = 0; j < 4; j++) oa[nt][j] = 0.f;

    float m0 = -1e30f, m1 = -1e30f;
    float l0 = 0.f, l1 = 0.f;
    float eL0 = 0.f, eL1 = 0.f, eH0 = 0.f, eH1 = 0.f;

    const int KT = vlc / 64;
    for (int t = 0; t < KT; t++) {
        int buf = t & 1;
        int k0 = t * 64;
        // entering: outstanding = [K(t)]
        loadV(k0);                              // + V(t)
        if (t + 1 < KT) { loadK(buf ^ 1, k0 + 64); cp_wait<2>(); }   // + K(t+1); K(t) done
        else            { cp_wait<1>(); }
        __syncthreads();                        // K(t) visible to all

        // ---- S = Q K^T
        float sa[8][4];
        #pragma unroll
        for (int nt = 0; nt < 8; nt++)
            #pragma unroll
            for (int j = 0; j < 4; j++) sa[nt][j] = 0.f;

        const float* Kb = Ks + buf * TILE;
        #pragma unroll
        for (int kc = 0; kc < 8; kc++) {
            #pragma unroll
            for (int nt = 0; nt < 8; nt++) {
                uint32_t b0 = ldu(&Kb[(nt * 8 + gid) * KS + kc * 8 + tig]);
                uint32_t b1 = ldu(&Kb[(nt * 8 + gid) * KS + kc * 8 + tig + 4]);
                mma8(sa[nt], qa[kc][0], qa[kc][1], qa[kc][2], qa[kc][3], b0, b1);
            }
        }

        // ---- rel-pos add, scale (log2 domain), mask; stash mid-band
        float tm0 = -1e30f, tm1 = -1e30f;
        #pragma unroll
        for (int nt = 0; nt < 8; nt++) {
            int kc0 = k0 + nt * 8 + 2 * tig;
            #pragma unroll
            for (int e = 0; e < 4; e++) {
                int kcol = kc0 + (e & 1);
                int qrow = (e < 2) ? qrow0 : qrow1;
                int rloc = wq + gid + ((e < 2) ? 0 : 8);
                int d = kcol - qrow;
                int bidx = min(16, max(-16, d)) + 16;
                float s = (sa[nt][e] + SQ[rloc * NREL + bidx]) * SCALE;
                if (kcol >= vl) s = NEGV;
                sa[nt][e] = s;
                if (d > -16 && d < 16) SMID[rloc * NREL + bidx] = s;
                if (e < 2) tm0 = fmaxf(tm0, s); else tm1 = fmaxf(tm1, s);
            }
        }
        tm0 = fmaxf(tm0, __shfl_xor_sync(0xffffffffu, tm0, 1));
        tm0 = fmaxf(tm0, __shfl_xor_sync(0xffffffffu, tm0, 2));
        tm1 = fmaxf(tm1, __shfl_xor_sync(0xffffffffu, tm1, 1));
        tm1 = fmaxf(tm1, __shfl_xor_sync(0xffffffffu, tm1, 2));

        float mn0 = fmaxf(m0, tm0), mn1 = fmaxf(m1, tm1);
        float a0 = exp2f(m0 - mn0), a1 = exp2f(m1 - mn1);
        m0 = mn0; m1 = mn1;

        // ---- p = exp2(s - m), partial sums + end buckets
        float ps0 = 0.f, ps1 = 0.f, tl0 = 0.f, tl1 = 0.f, th0 = 0.f, th1 = 0.f;
        #pragma unroll
        for (int nt = 0; nt < 8; nt++) {
            int kc0 = k0 + nt * 8 + 2 * tig;
            #pragma unroll
            for (int e = 0; e < 4; e++) {
                int kcol = kc0 + (e & 1);
                float p = exp2f(sa[nt][e] - ((e < 2) ? mn0 : mn1));
                sa[nt][e] = p;
                int d = kcol - ((e < 2) ? qrow0 : qrow1);
                if (e < 2) {
                    ps0 += p;
                    if (d <= -16) tl0 += p; else if (d >= 16) th0 += p;
                } else {
                    ps1 += p;
                    if (d <= -16) tl1 += p; else if (d >= 16) th1 += p;
                }
            }
        }
        ps0 += __shfl_xor_sync(0xffffffffu, ps0, 1); ps0 += __shfl_xor_sync(0xffffffffu, ps0, 2);
        ps1 += __shfl_xor_sync(0xffffffffu, ps1, 1); ps1 += __shfl_xor_sync(0xffffffffu, ps1, 2);
        tl0 += __shfl_xor_sync(0xffffffffu, tl0, 1); tl0 += __shfl_xor_sync(0xffffffffu, tl0, 2);
        tl1 += __shfl_xor_sync(0xffffffffu, tl1, 1); tl1 += __shfl_xor_sync(0xffffffffu, tl1, 2);
        th0 += __shfl_xor_sync(0xffffffffu, th0, 1); th0 += __shfl_xor_sync(0xffffffffu, th0, 2);
        th1 += __shfl_xor_sync(0xffffffffu, th1, 1); th1 += __shfl_xor_sync(0xffffffffu, th1, 2);

        l0 = l0 * a0 + ps0;  l1 = l1 * a1 + ps1;
        eL0 = eL0 * a0 + tl0; eL1 = eL1 * a1 + tl1;
        eH0 = eH0 * a0 + th0; eH1 = eH1 * a1 + th1;

        // ---- rescale O
        #pragma unroll
        for (int nt = 0; nt < 8; nt++) {
            oa[nt][0] *= a0; oa[nt][1] *= a0;
            oa[nt][2] *= a1; oa[nt][3] *= a1;
        }

        // ---- wait V(t), then PV with shuffle-transposed P fragments
        if (t + 1 < KT) cp_wait<1>(); else cp_wait<0>();
        __syncthreads();    // V(t) visible

        const int L0 = (gid << 2) + (tig >> 1);
        const int L1 = L0 + 2;
        const bool odd = (tig & 1) != 0;
        #pragma unroll
        for (int kc = 0; kc < 8; kc++) {
            float a0e = __shfl_sync(0xffffffffu, sa[kc][0], L0);
            float a0o = __shfl_sync(0xffffffffu, sa[kc][1], L0);
            float a1e = __shfl_sync(0xffffffffu, sa[kc][2], L0);
            float a1o = __shfl_sync(0xffffffffu, sa[kc][3], L0);
            float a2e = __shfl_sync(0xffffffffu, sa[kc][0], L1);
            float a2o = __shfl_sync(0xffffffffu, sa[kc][1], L1);
            float a3e = __shfl_sync(0xffffffffu, sa[kc][2], L1);
            float a3o = __shfl_sync(0xffffffffu, sa[kc][3], L1);
            uint32_t p0 = f2tf(odd ? a0o : a0e);
            uint32_t p1 = f2tf(odd ? a1o : a1e);
            uint32_t p2 = f2tf(odd ? a2o : a2e);
            uint32_t p3 = f2tf(odd ? a3o : a3e);
            #pragma unroll
            for (int nt = 0; nt < 8; nt++) {
                uint32_t b0 = ldu(&Vs[(kc * 8 + tig)     * KS + nt * 8 + gid]);
                uint32_t b1 = ldu(&Vs[(kc * 8 + tig + 4) * KS + nt * 8 + gid]);
                mma8(oa[nt], p0, p1, p2, p3, b0, b1);
            }
        }
        __syncthreads();    // all done reading Vs / Ks[buf] before next iter
    }

    // ---- epilogue ----
    const int b = bh >> 4, h = bh & 15;
    float il0 = 1.f / l0, il1 = 1.f / l1;

    if (tig == 0) {
        MR[wq + gid] = m0;     IL[wq + gid] = il0;
        MR[wq + gid + 8] = m1; IL[wq + gid + 8] = il1;
        SQ[(wq + gid) * NREL + 0]      = eL0 * il0;
        SQ[(wq + gid) * NREL + 32]     = eH0 * il0;
        SQ[(wq + gid + 8) * NREL + 0]  = eL1 * il1;
        SQ[(wq + gid + 8) * NREL + 32] = eH1 * il1;
    }
    // Ev -> Vs (main loop's final sync freed it)
    for (int i = tid; i < NREL * 16; i += 128) {
        int row = i >> 4, c = i & 15;
        *reinterpret_cast<float4*>(&Vs[row * KS + 4 * c]) =
            reinterpret_cast<const float4*>(Ev)[i];
    }
    __syncthreads();

    // mid buckets -> normalized pe in SQ
    for (int i = tid; i < 64 * 31; i += 128) {
        int row = i / 31, r = i % 31 + 1;
        SQ[row * NREL + r] = exp2f(SMID[row * NREL + r] - MR[row]) * IL[row];
    }
    __syncthreads();

    // normalize O, add pe @ Ev, store merged-head ctx (tf32-rounded)
    #pragma unroll
    for (int nt = 0; nt < 8; nt++) {
        oa[nt][0] *= il0; oa[nt][1] *= il0;
        oa[nt][2] *= il1; oa[nt][3] *= il1;
    }
    for (int r = 0; r < NREL; r++) {
        float pr0 = SQ[(wq + gid) * NREL + r];
        float pr1 = SQ[(wq + gid + 8) * NREL + r];
        #pragma unroll
        for (int nt = 0; nt < 8; nt++) {
            float2 ev = *reinterpret_cast<const float2*>(&Vs[r * KS + nt * 8 + 2 * tig]);
            oa[nt][0] += pr0 * ev.x; oa[nt][1] += pr0 * ev.y;
            oa[nt][2] += pr1 * ev.x; oa[nt][3] += pr1 * ev.y;
        }
    }
    #pragma unroll
    for (int nt = 0; nt < 8; nt++) {
        int col = h * HD + nt * 8 + 2 * tig;
        *reinterpret_cast<float2*>(&g_ctx[(size_t)(b * SEQ + qrow0) * DM + col]) =
            make_float2(f2tf_f(oa[nt][0]), f2tf_f(oa[nt][1]));
        *reinterpret_cast<float2*>(&g_ctx[(size_t)(b * SEQ + qrow1) * DM + col]) =
            make_float2(f2tf_f(oa[nt][2]), f2tf_f(oa[nt][3]));
    }
}

// ---------------- launch ------------------------------------------------------
extern "C" void kernel_launch(void* const* d_in, const int* in_sizes, int n_in,
                              void* d_out, int out_size)
{
    const float* queries = (const float*)d_in[0];
    const float* keys    = (const float*)d_in[1];
    const float* values  = (const float*)d_in[2];
    const int*   valid   = (const int*)  d_in[3];
    const float* Wq      = (const float*)d_in[4];
    const float* Wk      = (const float*)d_in[5];
    const float* Wv      = (const float*)d_in[6];
    const float* Wo      = (const float*)d_in[7];
    const float* Ek      = (const float*)d_in[8];
    const float* Ev      = (const float*)d_in[9];
    float* out = (float*)d_out;

    float *Qp, *Kp, *Vp, *Cp, *rin, *rw;
    cudaGetSymbolAddress((void**)&Qp, g_Q);
    cudaGetSymbolAddress((void**)&Kp, g_K);
    cudaGetSymbolAddress((void**)&Vp, g_V);
    cudaGetSymbolAddress((void**)&Cp, g_ctx);
    cudaGetSymbolAddress((void**)&rin, g_rin);
    cudaGetSymbolAddress((void**)&rw, g_rw);

    const int M = BATCH * SEQ;          // 4096
    const size_t IN = (size_t)M * DM;   // 4M
    const size_t WN = (size_t)DM * DM;  // 1M

    const int smProj  = 2 * (128 * 36 + 128 * 36) * sizeof(float);   // 73728
    const int smOut   = 2 * (128 * 36 +  64 * 36) * sizeof(float);   // 55296
    const int smFlash = (2 * 64 * 68 + 64 * 68
                         + 64 * NREL + 64 * NREL + 128) * sizeof(float); // 69632

    cudaFuncSetAttribute(gemm_big<true, 128, 3>,
        cudaFuncAttributeMaxDynamicSharedMemorySize, smProj);
    cudaFuncSetAttribute(gemm_big<false, 64, 4>,
        cudaFuncAttributeMaxDynamicSharedMemorySize, smOut);
    cudaFuncSetAttribute(flash_kernel,
        cudaFuncAttributeMaxDynamicSharedMemorySize, smFlash);

    // 1) pre-round inputs + weights to tf32 (7 regions, one launch)
    ConvArgs ca;
    ca.src[0] = queries; ca.src[1] = keys; ca.src[2] = values;
    ca.src[3] = Wq; ca.src[4] = Wk; ca.src[5] = Wv; ca.src[6] = Wo;
    for (int i = 0; i < 3; i++) { ca.dst[i] = rin + i * IN; ca.n4[i] = (int)(IN / 4); }
    for (int i = 0; i < 4; i++) { ca.dst[3 + i] = rw + i * WN; ca.n4[3 + i] = (int)(WN / 4); }
    conv_kernel<<<dim3(256, 7), 256>>>(ca);

    // 2) Q/K/V projections, head-split + tf32-round store
    Proj3Args pa;
    pa.A[0] = rin;          pa.A[1] = rin + IN;     pa.A[2] = rin + 2 * IN;
    pa.B[0] = rw;           pa.B[1] = rw + WN;      pa.B[2] = rw + 2 * WN;
    pa.C[0] = Qp;           pa.C[1] = Kp;           pa.C[2] = Vp;
    gemm_big<true, 128, 3><<<dim3(DM / 128, M / 128, 3), 128, smProj>>>(pa, M, DM, DM);

    // 3) fused attention (shuffle-P, 3 CTAs/SM)
    flash_kernel<<<dim3(SEQ / 64, BH), 128, smFlash>>>(valid, Ek, Ev);

    // 4) out = ctx @ Wo^T  (BN=64 tiles -> 512 blocks, 4 CTAs/SM)
    Proj3Args po;
    po.A[0] = Cp; po.B[0] = rw + 3 * WN; po.C[0] = out;
    po.A[1] = po.A[2] = Cp; po.B[1] = po.B[2] = rw; po.C[1] = po.C[2] = out;
    gemm_big<false, 64, 4><<<dim3(DM / 64, M / 128, 1), 128, smOut>>>(po, M, DM, DM);
}

// round 11
// speedup vs baseline: 6.7816x; 1.0761x over previous
#include <cuda_runtime.h>
#include <math.h>
#include <stdint.h>

#define BATCH 4
#define SEQ   1024
#define DM    1024
#define NH    16
#define HD    64
#define BH    (BATCH*NH)   // 64
#define NREL  33
#define NEGV  (-1e6f)
#define SCALE 0.1803368801111243f   // (1/sqrt(64)) * log2(e)

// ---------------- scratch (device globals: allocation is forbidden) ----------
__device__ float g_Q[BH*SEQ*HD];                 // [bh][s][d]  (tf32-rounded)
__device__ float g_K[BH*SEQ*HD];
__device__ float g_V[BH*SEQ*HD];
__device__ float g_ctx[BATCH*SEQ*DM];            // merged-head ctx (tf32-rounded)
__device__ float g_rin[3u*4096*1024];            // pre-rounded q,k,v inputs
__device__ float g_rw [4u*1024*1024];            // pre-rounded Wq,Wk,Wv,Wo

// ---------------- helpers ----------------------------------------------------
__device__ __forceinline__ uint32_t f2tf(float f) {
    uint32_t u;
    asm("cvt.rna.tf32.f32 %0, %1;" : "=r"(u) : "f"(f));
    return u;
}
__device__ __forceinline__ float f2tf_f(float f) {
    return __uint_as_float(f2tf(f));
}
__device__ __forceinline__ void mma8(float* c,
    uint32_t a0, uint32_t a1, uint32_t a2, uint32_t a3,
    uint32_t b0, uint32_t b1)
{
    asm volatile(
        "mma.sync.aligned.m16n8k8.row.col.f32.tf32.tf32.f32 "
        "{%0,%1,%2,%3}, {%4,%5,%6,%7}, {%8,%9}, {%0,%1,%2,%3};"
        : "+f"(c[0]), "+f"(c[1]), "+f"(c[2]), "+f"(c[3])
        : "r"(a0), "r"(a1), "r"(a2), "r"(a3), "r"(b0), "r"(b1));
}
// ldmatrix x4: one instruction loads 4 fragment regs warp-wide.
// For 32-bit data viewed as b16 pairs, thread t receives f32 element
// (t/4, t%4) of the 8x8-f32 matrix addressed by lanes 8m..8m+7.
__device__ __forceinline__ void ldsm4(uint32_t& r0, uint32_t& r1,
                                      uint32_t& r2, uint32_t& r3, uint32_t addr)
{
    asm volatile("ldmatrix.sync.aligned.m8n8.x4.shared.b16 {%0,%1,%2,%3}, [%4];"
        : "=r"(r0), "=r"(r1), "=r"(r2), "=r"(r3) : "r"(addr));
}
__device__ __forceinline__ void cp16(void* smem_dst, const void* gmem_src) {
    uint32_t s = (uint32_t)__cvta_generic_to_shared(smem_dst);
    asm volatile("cp.async.cg.shared.global [%0], [%1], 16;\n"
                 :: "r"(s), "l"(gmem_src));
}
__device__ __forceinline__ void cp_commit() {
    asm volatile("cp.async.commit_group;\n");
}
template<int N>
__device__ __forceinline__ void cp_wait() {
    asm volatile("cp.async.wait_group %0;\n" :: "n"(N));
}
__device__ __forceinline__ uint32_t ldu(const float* p) {   // raw bits
    return __float_as_uint(*p);
}
__device__ __forceinline__ uint32_t smem_u32(const void* p) {
    return (uint32_t)__cvta_generic_to_shared(p);
}

// =============================================================================
// fp32 -> tf32-rounded fp32 copies (7 regions, one launch)
// =============================================================================
struct ConvArgs {
    const float* src[7];
    float* dst[7];
    int n4[7];
};
__global__ void __launch_bounds__(256) conv_kernel(ConvArgs a)
{
    int rg = blockIdx.y;
    const float4* s = reinterpret_cast<const float4*>(a.src[rg]);
    float4* d = reinterpret_cast<float4*>(a.dst[rg]);
    int n4 = a.n4[rg];
    for (int i = blockIdx.x * 256 + threadIdx.x; i < n4; i += gridDim.x * 256) {
        float4 v = s[i];
        v.x = f2tf_f(v.x); v.y = f2tf_f(v.y);
        v.z = f2tf_f(v.z); v.w = f2tf_f(v.w);
        d[i] = v;
    }
}

struct Proj3Args {
    const float* A[3];
    const float* B[3];
    float*       C[3];
};

// =============================================================================
// Big NT GEMM: C = A * B^T. Pre-rounded operands; ldmatrix fragment loads.
// 128x128 tile, 128 threads, warp tile 64x64. 3 CTAs/SM.
// =============================================================================
template<bool PROJ3>
__global__ void __launch_bounds__(128, 3)
gemm_big(Proj3Args args, int M, int N, int K)
{
    constexpr int BM = 128, BN = 128, BK = 32, T = 128;
    constexpr int ASZ = BM * (BK + 4);          // floats per A buffer
    constexpr int BSZ = BN * (BK + 4);
    constexpr int ABYTES = ASZ * 4;
    constexpr int BBYTES = BSZ * 4;

    extern __shared__ float dynsmem[];
    float (*As)[BM][BK + 4] = reinterpret_cast<float(*)[BM][BK + 4]>(dynsmem);
    float (*Bs)[BN][BK + 4] = reinterpret_cast<float(*)[BN][BK + 4]>(dynsmem + 2 * ASZ);

    int z = PROJ3 ? blockIdx.z : 0;
    const float* A = args.A[z];
    const float* B = args.B[z];
    float*       C = args.C[z];

    int m0  = blockIdx.y * BM, n0 = blockIdx.x * BN;
    int tid = threadIdx.x;
    int lane = tid & 31, warp = tid >> 5;
    int gid = lane >> 2, tig = lane & 3;
    int wm0 = (warp >> 1) * 64;
    int wn0 = (warp & 1) * 64;

    // ldmatrix lane-address decomposition
    int Lm = lane >> 3, Lr = lane & 7;
    int a_row = ((Lm & 1) ? 8 : 0) + Lr;        // q0/q2: rows 0-7; q1/q3: rows 8-15
    int a_col = (Lm & 2) ? 4 : 0;               // q2/q3: cols +4
    int b_row = ((Lm & 2) ? 8 : 0) + Lr;        // q2/q3: second nt tile (+8 rows)
    int b_col = (Lm & 1) ? 4 : 0;               // q1/q3: cols +4

    uint32_t sA = smem_u32(&As[0][0][0]);
    uint32_t sB = smem_u32(&Bs[0][0][0]);
    uint32_t aBase[4], bBase[4];
    #pragma unroll
    for (int mt = 0; mt < 4; mt++)
        aBase[mt] = sA + ((wm0 + mt * 16 + a_row) * (BK + 4) + a_col) * 4;
    #pragma unroll
    for (int np = 0; np < 4; np++)
        bBase[np] = sB + ((wn0 + np * 16 + b_row) * (BK + 4) + b_col) * 4;

    auto load_tiles = [&](int buf, int k0) {
        #pragma unroll
        for (int it = 0; it < 8; it++) {
            int idx = tid + it * T;
            int row = idx >> 3, kq = (idx & 7) << 2;
            cp16(&As[buf][row][kq], &A[(size_t)(m0 + row) * K + k0 + kq]);
        }
        #pragma unroll
        for (int it = 0; it < 8; it++) {
            int idx = tid + it * T;
            int row = idx >> 3, kq = (idx & 7) << 2;
            cp16(&Bs[buf][row][kq], &B[(size_t)(n0 + row) * K + k0 + kq]);
        }
        cp_commit();
    };

    float acc[4][8][4];
    #pragma unroll
    for (int i = 0; i < 4; i++)
        #pragma unroll
        for (int j = 0; j < 8; j++)
            #pragma unroll
            for (int l = 0; l < 4; l++) acc[i][j][l] = 0.f;

    const int KT = K / BK;
    load_tiles(0, 0);

    for (int kt = 0; kt < KT; kt++) {
        int buf = kt & 1;
        if (kt + 1 < KT) { load_tiles(buf ^ 1, (kt + 1) * BK); cp_wait<1>(); }
        else             { cp_wait<0>(); }
        __syncthreads();

        uint32_t aOff = buf * ABYTES;
        uint32_t bOff = buf * BBYTES;
        #pragma unroll
        for (int kc = 0; kc < BK / 8; kc++) {
            uint32_t kb4 = kc * 32;             // kb * 4 bytes
            uint32_t af[4][4];
            #pragma unroll
            for (int mt = 0; mt < 4; mt++)
                ldsm4(af[mt][0], af[mt][1], af[mt][2], af[mt][3],
                      aBase[mt] + aOff + kb4);
            uint32_t bf[8][2];
            #pragma unroll
            for (int np = 0; np < 4; np++)
                ldsm4(bf[2*np][0], bf[2*np][1], bf[2*np+1][0], bf[2*np+1][1],
                      bBase[np] + bOff + kb4);
            #pragma unroll
            for (int mt = 0; mt < 4; mt++)
                #pragma unroll
                for (int nt = 0; nt < 8; nt++)
                    mma8(acc[mt][nt], af[mt][0], af[mt][1], af[mt][2], af[mt][3],
                         bf[nt][0], bf[nt][1]);
        }
        __syncthreads();
    }

    #pragma unroll
    for (int mt = 0; mt < 4; mt++) {
        #pragma unroll
        for (int nt = 0; nt < 8; nt++) {
            int r0 = m0 + wm0 + mt * 16 + gid;
            int c0 = n0 + wn0 + nt * 8 + 2 * tig;
            if (PROJ3) {
                float2 t0 = make_float2(f2tf_f(acc[mt][nt][0]), f2tf_f(acc[mt][nt][1]));
                float2 t1 = make_float2(f2tf_f(acc[mt][nt][2]), f2tf_f(acc[mt][nt][3]));
                int b = r0 >> 10, s = r0 & 1023, h = c0 >> 6, d = c0 & 63;
                *reinterpret_cast<float2*>(
                    &C[(size_t)((b * NH + h) * SEQ + s) * HD + d]) = t0;
                int b2 = (r0 + 8) >> 10, s2 = (r0 + 8) & 1023;
                *reinterpret_cast<float2*>(
                    &C[(size_t)((b2 * NH + h) * SEQ + s2) * HD + d]) = t1;
            } else {
                float2 t0 = make_float2(acc[mt][nt][0], acc[mt][nt][1]);
                float2 t1 = make_float2(acc[mt][nt][2], acc[mt][nt][3]);
                *reinterpret_cast<float2*>(&C[(size_t)r0 * N + c0]) = t0;
                *reinterpret_cast<float2*>(&C[(size_t)(r0 + 8) * N + c0]) = t1;
            }
        }
    }
}

// =============================================================================
// Fused flash attention (shuffle-P, single-buffered V, ldmatrix K fragments).
// =============================================================================
__global__ void __launch_bounds__(128, 3)
flash_kernel(const int* __restrict__ valid_lens,
             const float* __restrict__ Ek, const float* __restrict__ Ev)
{
    constexpr int KS = 68;
    constexpr int TILE = 64 * KS;
    constexpr int TILEB = TILE * 4;

    extern __shared__ float sm[];
    float* Ks = sm;                 // [2][64][68]
    float* Vs = Ks + 2 * TILE;      // [64][68]  (also Ek/Ev staging)
    float* SQ = Vs + TILE;          // [64][33]
    float* SMID = SQ + 64 * NREL;   // [64][33]
    float* MR = SMID + 64 * NREL;   // [64]
    float* IL = MR + 64;            // [64]

    const int q0 = blockIdx.x * 64;
    const int bh = blockIdx.y;
    const int vl  = valid_lens[bh >> 4];
    const int vlc = (vl + 63) & ~63;

    const int tid = threadIdx.x;
    const int lane = tid & 31, warp = tid >> 5;
    const int gid = lane >> 2, tig = lane & 3;
    const int wq = warp * 16;

    // ldmatrix lane addresses for K fragments (B-NT pattern)
    int Lm = lane >> 3, Lr = lane & 7;
    int b_row = ((Lm & 2) ? 8 : 0) + Lr;
    int b_col = (Lm & 1) ? 4 : 0;
    uint32_t sK = smem_u32(Ks);
    uint32_t kBase[4];
    #pragma unroll
    for (int np = 0; np < 4; np++)
        kBase[np] = sK + ((np * 16 + b_row) * KS + b_col) * 4;

    auto loadK = [&](int buf, int k0) {
        const float* Kg = g_K + ((size_t)bh * SEQ + k0) * HD;
        #pragma unroll
        for (int it = 0; it < 8; it++) {
            int idx = tid + it * 128;
            int row = idx >> 4, c4 = (idx & 15) << 2;
            cp16(&Ks[buf * TILE + row * KS + c4], Kg + row * HD + c4);
        }
        cp_commit();
    };
    auto loadV = [&](int k0) {
        const float* Vg = g_V + ((size_t)bh * SEQ + k0) * HD;
        #pragma unroll
        for (int it = 0; it < 8; it++) {
            int idx = tid + it * 128;
            int row = idx >> 4, c4 = (idx & 15) << 2;
            cp16(&Vs[row * KS + c4], Vg + row * HD + c4);
        }
        cp_commit();
    };

    loadK(0, 0);                               // outstanding: [K0]

    // Ek -> Vs (free until iter 0's V load)
    for (int i = tid; i < NREL * 16; i += 128) {
        int row = i >> 4, c = i & 15;
        *reinterpret_cast<float4*>(&Vs[row * KS + 4 * c]) =
            reinterpret_cast<const float4*>(Ek)[i];
    }

    uint32_t qa[8][4];
    {
        const float* Qg = g_Q + ((size_t)bh * SEQ + q0 + wq) * HD;
        #pragma unroll
        for (int kc = 0; kc < 8; kc++) {
            qa[kc][0] = ldu(&Qg[(size_t)gid       * HD + kc * 8 + tig]);
            qa[kc][1] = ldu(&Qg[(size_t)(gid + 8) * HD + kc * 8 + tig]);
            qa[kc][2] = ldu(&Qg[(size_t)gid       * HD + kc * 8 + tig + 4]);
            qa[kc][3] = ldu(&Qg[(size_t)(gid + 8) * HD + kc * 8 + tig + 4]);
        }
    }
    __syncthreads();    // Ek visible

    {
        float sq[5][4];
        #pragma unroll
        for (int nt = 0; nt < 5; nt++)
            #pragma unroll
            for (int e = 0; e < 4; e++) sq[nt][e] = 0.f;
        #pragma unroll
        for (int kc = 0; kc < 8; kc++) {
            #pragma unroll
            for (int nt = 0; nt < 5; nt++) {
                uint32_t b0 = f2tf(Vs[(nt * 8 + gid) * KS + kc * 8 + tig]);
                uint32_t b1 = f2tf(Vs[(nt * 8 + gid) * KS + kc * 8 + tig + 4]);
                mma8(sq[nt], qa[kc][0], qa[kc][1], qa[kc][2], qa[kc][3], b0, b1);
            }
        }
        #pragma unroll
        for (int nt = 0; nt < 5; nt++) {
            #pragma unroll
            for (int e = 0; e < 4; e++) {
                int col = nt * 8 + 2 * tig + (e & 1);
                int row = wq + gid + ((e < 2) ? 0 : 8);
                if (col < NREL) SQ[row * NREL + col] = sq[nt][e];
            }
        }
    }
    for (int i = tid; i < 64 * NREL; i += 128) SMID[i] = NEGV;
    __syncthreads();

    const int qrow0 = q0 + wq + gid;
    const int qrow1 = qrow0 + 8;

    float oa[8][4];
    #pragma unroll
    for (int nt = 0; nt < 8; nt++)
        #pragma unroll
        for (int j = 0; j < 4; j++) oa[nt][j] = 0.f;

    float m0 = -1e30f, m1 = -1e30f;
    float l0 = 0.f, l1 = 0.f;
    float eL0 = 0.f, eL1 = 0.f, eH0 = 0.f, eH1 = 0.f;

    const int KT = vlc / 64;
    for (int t = 0; t < KT; t++) {
        int buf = t & 1;
        int k0 = t * 64;
        loadV(k0);
        if (t + 1 < KT) { loadK(buf ^ 1, k0 + 64); cp_wait<2>(); }
        else            { cp_wait<1>(); }
        __syncthreads();                        // K(t) visible

        // ---- S = Q K^T with ldmatrix K fragments
        float sa[8][4];
        #pragma unroll
        for (int nt = 0; nt < 8; nt++)
            #pragma unroll
            for (int j = 0; j < 4; j++) sa[nt][j] = 0.f;

        uint32_t kOff = buf * TILEB;
        #pragma unroll
        for (int kc = 0; kc < 8; kc++) {
            uint32_t bf[8][2];
            #pragma unroll
            for (int np = 0; np < 4; np++)
                ldsm4(bf[2*np][0], bf[2*np][1], bf[2*np+1][0], bf[2*np+1][1],
                      kBase[np] + kOff + kc * 32);
            #pragma unroll
            for (int nt = 0; nt < 8; nt++)
                mma8(sa[nt], qa[kc][0], qa[kc][1], qa[kc][2], qa[kc][3],
                     bf[nt][0], bf[nt][1]);
        }

        // ---- rel-pos add, scale (log2 domain), mask; stash mid-band
        float tm0 = -1e30f, tm1 = -1e30f;
        #pragma unroll
        for (int nt = 0; nt < 8; nt++) {
            int kc0 = k0 + nt * 8 + 2 * tig;
            #pragma unroll
            for (int e = 0; e < 4; e++) {
                int kcol = kc0 + (e & 1);
                int qrow = (e < 2) ? qrow0 : qrow1;
                int rloc = wq + gid + ((e < 2) ? 0 : 8);
                int d = kcol - qrow;
                int bidx = min(16, max(-16, d)) + 16;
                float s = (sa[nt][e] + SQ[rloc * NREL + bidx]) * SCALE;
                if (kcol >= vl) s = NEGV;
                sa[nt][e] = s;
                if (d > -16 && d < 16) SMID[rloc * NREL + bidx] = s;
                if (e < 2) tm0 = fmaxf(tm0, s); else tm1 = fmaxf(tm1, s);
            }
        }
        tm0 = fmaxf(tm0, __shfl_xor_sync(0xffffffffu, tm0, 1));
        tm0 = fmaxf(tm0, __shfl_xor_sync(0xffffffffu, tm0, 2));
        tm1 = fmaxf(tm1, __shfl_xor_sync(0xffffffffu, tm1, 1));
        tm1 = fmaxf(tm1, __shfl_xor_sync(0xffffffffu, tm1, 2));

        float mn0 = fmaxf(m0, tm0), mn1 = fmaxf(m1, tm1);
        float a0 = exp2f(m0 - mn0), a1 = exp2f(m1 - mn1);
        m0 = mn0; m1 = mn1;

        float ps0 = 0.f, ps1 = 0.f, tl0 = 0.f, tl1 = 0.f, th0 = 0.f, th1 = 0.f;
        #pragma unroll
        for (int nt = 0; nt < 8; nt++) {
            int kc0 = k0 + nt * 8 + 2 * tig;
            #pragma unroll
            for (int e = 0; e < 4; e++) {
                int kcol = kc0 + (e & 1);
                float p = exp2f(sa[nt][e] - ((e < 2) ? mn0 : mn1));
                sa[nt][e] = p;
                int d = kcol - ((e < 2) ? qrow0 : qrow1);
                if (e < 2) {
                    ps0 += p;
                    if (d <= -16) tl0 += p; else if (d >= 16) th0 += p;
                } else {
                    ps1 += p;
                    if (d <= -16) tl1 += p; else if (d >= 16) th1 += p;
                }
            }
        }
        ps0 += __shfl_xor_sync(0xffffffffu, ps0, 1); ps0 += __shfl_xor_sync(0xffffffffu, ps0, 2);
        ps1 += __shfl_xor_sync(0xffffffffu, ps1, 1); ps1 += __shfl_xor_sync(0xffffffffu, ps1, 2);
        tl0 += __shfl_xor_sync(0xffffffffu, tl0, 1); tl0 += __shfl_xor_sync(0xffffffffu, tl0, 2);
        tl1 += __shfl_xor_sync(0xffffffffu, tl1, 1); tl1 += __shfl_xor_sync(0xffffffffu, tl1, 2);
        th0 += __shfl_xor_sync(0xffffffffu, th0, 1); th0 += __shfl_xor_sync(0xffffffffu, th0, 2);
        th1 += __shfl_xor_sync(0xffffffffu, th1, 1); th1 += __shfl_xor_sync(0xffffffffu, th1, 2);

        l0 = l0 * a0 + ps0;  l1 = l1 * a1 + ps1;
        eL0 = eL0 * a0 + tl0; eL1 = eL1 * a1 + tl1;
        eH0 = eH0 * a0 + th0; eH1 = eH1 * a1 + th1;

        #pragma unroll
        for (int nt = 0; nt < 8; nt++) {
            oa[nt][0] *= a0; oa[nt][1] *= a0;
            oa[nt][2] *= a1; oa[nt][3] *= a1;
        }

        // ---- wait V(t), then PV with shuffle-transposed P fragments
        if (t + 1 < KT) cp_wait<1>(); else cp_wait<0>();
        __syncthreads();    // V(t) visible

        const int L0 = (gid << 2) + (tig >> 1);
        const int L1 = L0 + 2;
        const bool odd = (tig & 1) != 0;
        #pragma unroll
        for (int kc = 0; kc < 8; kc++) {
            float a0e = __shfl_sync(0xffffffffu, sa[kc][0], L0);
            float a0o = __shfl_sync(0xffffffffu, sa[kc][1], L0);
            float a1e = __shfl_sync(0xffffffffu, sa[kc][2], L0);
            float a1o = __shfl_sync(0xffffffffu, sa[kc][3], L0);
            float a2e = __shfl_sync(0xffffffffu, sa[kc][0], L1);
            float a2o = __shfl_sync(0xffffffffu, sa[kc][1], L1);
            float a3e = __shfl_sync(0xffffffffu, sa[kc][2], L1);
            float a3o = __shfl_sync(0xffffffffu, sa[kc][3], L1);
            uint32_t p0 = f2tf(odd ? a0o : a0e);
            uint32_t p1 = f2tf(odd ? a1o : a1e);
            uint32_t p2 = f2tf(odd ? a2o : a2e);
            uint32_t p3 = f2tf(odd ? a3o : a3e);
            #pragma unroll
            for (int nt = 0; nt < 8; nt++) {
                uint32_t b0 = ldu(&Vs[(kc * 8 + tig)     * KS + nt * 8 + gid]);
                uint32_t b1 = ldu(&Vs[(kc * 8 + tig + 4) * KS + nt * 8 + gid]);
                mma8(oa[nt], p0, p1, p2, p3, b0, b1);
            }
        }
        __syncthreads();
    }

    // ---- epilogue ----
    const int b = bh >> 4, h = bh & 15;
    float il0 = 1.f / l0, il1 = 1.f / l1;

    if (tig == 0) {
        MR[wq + gid] = m0;     IL[wq + gid] = il0;
        MR[wq + gid + 8] = m1; IL[wq + gid + 8] = il1;
        SQ[(wq + gid) * NREL + 0]      = eL0 * il0;
        SQ[(wq + gid) * NREL + 32]     = eH0 * il0;
        SQ[(wq + gid + 8) * NREL + 0]  = eL1 * il1;
        SQ[(wq + gid + 8) * NREL + 32] = eH1 * il1;
    }
    for (int i = tid; i < NREL * 16; i += 128) {
        int row = i >> 4, c = i & 15;
        *reinterpret_cast<float4*>(&Vs[row * KS + 4 * c]) =
            reinterpret_cast<const float4*>(Ev)[i];
    }
    __syncthreads();

    for (int i = tid; i < 64 * 31; i += 128) {
        int row = i / 31, r = i % 31 + 1;
        SQ[row * NREL + r] = exp2f(SMID[row * NREL + r] - MR[row]) * IL[row];
    }
    __syncthreads();

    #pragma unroll
    for (int nt = 0; nt < 8; nt++) {
        oa[nt][0] *= il0; oa[nt][1] *= il0;
        oa[nt][2] *= il1; oa[nt][3] *= il1;
    }
    for (int r = 0; r < NREL; r++) {
        float pr0 = SQ[(wq + gid) * NREL + r];
        float pr1 = SQ[(wq + gid + 8) * NREL + r];
        #pragma unroll
        for (int nt = 0; nt < 8; nt++) {
            float2 ev = *reinterpret_cast<const float2*>(&Vs[r * KS + nt * 8 + 2 * tig]);
            oa[nt][0] += pr0 * ev.x; oa[nt][1] += pr0 * ev.y;
            oa[nt][2] += pr1 * ev.x; oa[nt][3] += pr1 * ev.y;
        }
    }
    #pragma unroll
    for (int nt = 0; nt < 8; nt++) {
        int col = h * HD + nt * 8 + 2 * tig;
        *reinterpret_cast<float2*>(&g_ctx[(size_t)(b * SEQ + qrow0) * DM + col]) =
            make_float2(f2tf_f(oa[nt][0]), f2tf_f(oa[nt][1]));
        *reinterpret_cast<float2*>(&g_ctx[(size_t)(b * SEQ + qrow1) * DM + col]) =
            make_float2(f2tf_f(oa[nt][2]), f2tf_f(oa[nt][3]));
    }
}

// ---------------- launch ------------------------------------------------------
extern "C" void kernel_launch(void* const* d_in, const int* in_sizes, int n_in,
                              void* d_out, int out_size)
{
    const float* queries = (const float*)d_in[0];
    const float* keys    = (const float*)d_in[1];
    const float* values  = (const float*)d_in[2];
    const int*   valid   = (const int*)  d_in[3];
    const float* Wq      = (const float*)d_in[4];
    const float* Wk      = (const float*)d_in[5];
    const float* Wv      = (const float*)d_in[6];
    const float* Wo      = (const float*)d_in[7];
    const float* Ek      = (const float*)d_in[8];
    const float* Ev      = (const float*)d_in[9];
    float* out = (float*)d_out;

    float *Qp, *Kp, *Vp, *Cp, *rin, *rw;
    cudaGetSymbolAddress((void**)&Qp, g_Q);
    cudaGetSymbolAddress((void**)&Kp, g_K);
    cudaGetSymbolAddress((void**)&Vp, g_V);
    cudaGetSymbolAddress((void**)&Cp, g_ctx);
    cudaGetSymbolAddress((void**)&rin, g_rin);
    cudaGetSymbolAddress((void**)&rw, g_rw);

    const int M = BATCH * SEQ;          // 4096
    const size_t IN = (size_t)M * DM;   // 4M
    const size_t WN = (size_t)DM * DM;  // 1M

    const int smBig   = 2 * (128 * 36 + 128 * 36) * sizeof(float);   // 73728
    const int smFlash = (2 * 64 * 68 + 64 * 68
                         + 64 * NREL + 64 * NREL + 128) * sizeof(float); // 69632

    cudaFuncSetAttribute(gemm_big<true>,
        cudaFuncAttributeMaxDynamicSharedMemorySize, smBig);
    cudaFuncSetAttribute(gemm_big<false>,
        cudaFuncAttributeMaxDynamicSharedMemorySize, smBig);
    cudaFuncSetAttribute(flash_kernel,
        cudaFuncAttributeMaxDynamicSharedMemorySize, smFlash);

    // 1) pre-round inputs + weights to tf32
    ConvArgs ca;
    ca.src[0] = queries; ca.src[1] = keys; ca.src[2] = values;
    ca.src[3] = Wq; ca.src[4] = Wk; ca.src[5] = Wv; ca.src[6] = Wo;
    for (int i = 0; i < 3; i++) { ca.dst[i] = rin + i * IN; ca.n4[i] = (int)(IN / 4); }
    for (int i = 0; i < 4; i++) { ca.dst[3 + i] = rw + i * WN; ca.n4[3 + i] = (int)(WN / 4); }
    conv_kernel<<<dim3(256, 7), 256>>>(ca);

    // 2) Q/K/V projections, head-split + tf32-round store
    Proj3Args pa;
    pa.A[0] = rin;          pa.A[1] = rin + IN;     pa.A[2] = rin + 2 * IN;
    pa.B[0] = rw;           pa.B[1] = rw + WN;      pa.B[2] = rw + 2 * WN;
    pa.C[0] = Qp;           pa.C[1] = Kp;           pa.C[2] = Vp;
    gemm_big<true><<<dim3(DM / 128, M / 128, 3), 128, smBig>>>(pa, M, DM, DM);

    // 3) fused attention
    flash_kernel<<<dim3(SEQ / 64, BH), 128, smFlash>>>(valid, Ek, Ev);

    // 4) out = ctx @ Wo^T  (BN=128 tile: better issue economy, measured)
    Proj3Args po;
    po.A[0] = Cp; po.B[0] = rw + 3 * WN; po.C[0] = out;
    po.A[1] = po.A[2] = Cp; po.B[1] = po.B[2] = rw; po.C[1] = po.C[2] = out;
    gemm_big<false><<<dim3(DM / 128, M / 128, 1), 128, smBig>>>(po, M, DM, DM);
}